// round 2
// baseline (speedup 1.0000x reference)
#include <cuda_runtime.h>
#include <math.h>

// Problem constants
#define BB 4
#define NN 4096
#define EE 131072
#define II 128
#define HH 128
#define FF 140

#define TE 32   // edges per block in edge kernel
#define NT 16   // rows per block in node kernel

// Scratch (allocation-free rule: __device__ globals)
__device__ float g_hm_sum[(size_t)BB * NN * HH];   // 8 MB
__device__ float g_pm_sum[(size_t)BB * NN * HH];   // 8 MB
__device__ int   g_cnt[NN];

__device__ __forceinline__ float sigmoidf_(float x) {
    return 1.0f / (1.0f + expf(-x));
}

// acc[e] += sum_k in_s[e*PITCH + k] * W[k*128 + t]
template<int TILE, int K, int PITCH>
__device__ __forceinline__ void gemm_tile(const float* in_s,
                                          const float* __restrict__ W,
                                          int t, float* acc) {
    for (int k = 0; k < K; k += 4) {
        float w0 = W[(k + 0) * 128 + t];
        float w1 = W[(k + 1) * 128 + t];
        float w2 = W[(k + 2) * 128 + t];
        float w3 = W[(k + 3) * 128 + t];
        #pragma unroll
        for (int e = 0; e < TILE; e++) {
            float4 f = *reinterpret_cast<const float4*>(in_s + e * PITCH + k);
            acc[e] = fmaf(f.x, w0, acc[e]);
            acc[e] = fmaf(f.y, w1, acc[e]);
            acc[e] = fmaf(f.z, w2, acc[e]);
            acc[e] = fmaf(f.w, w3, acc[e]);
        }
    }
}

__global__ void zero_kernel() {
    const size_t M = (size_t)BB * NN * HH;
    size_t stride = (size_t)gridDim.x * blockDim.x;
    size_t i = (size_t)blockIdx.x * blockDim.x + threadIdx.x;
    for (size_t j = i; j < M; j += stride) {
        g_hm_sum[j] = 0.0f;
        g_pm_sum[j] = 0.0f;
    }
    if (i < NN) g_cnt[i] = 0;
}

__global__ void count_kernel(const int* __restrict__ recv_e) {
    int e = blockIdx.x * blockDim.x + threadIdx.x;
    if (e < EE) atomicAdd(&g_cnt[recv_e[e]], 1);
}

__global__ void __launch_bounds__(128) edge_kernel(
    const float* __restrict__ hidden,
    const float* __restrict__ edge_attr,
    const int*   __restrict__ send_e,
    const int*   __restrict__ recv_e,
    const float* __restrict__ mw1, const float* __restrict__ mb1,
    const float* __restrict__ mw2, const float* __restrict__ mb2,
    const float* __restrict__ pw1, const float* __restrict__ pb1,
    const float* __restrict__ pw2, const float* __restrict__ pb2)
{
    extern __shared__ float sm[];
    float* feat = sm;                       // TE * 256
    float* mid  = sm + TE * 256;            // TE * 128
    int*   s_recv = (int*)(mid + TE * 128); // TE
    int*   s_send = s_recv + TE;            // TE

    const int t  = threadIdx.x;     // 0..127 : output feature
    const int b  = blockIdx.y;
    const int e0 = blockIdx.x * TE;

    if (t < TE)            s_recv[t]      = recv_e[e0 + t];
    else if (t < 2 * TE)   s_send[t - TE] = send_e[e0 + t - TE];
    __syncthreads();

    // ---- stage concat(hidden[recv], hidden[send]) ----
    const float* hb = hidden + (size_t)b * NN * HH;
    #pragma unroll
    for (int e = 0; e < TE; e++) {
        feat[e * 256 + t]       = hb[(size_t)s_recv[e] * HH + t];
        feat[e * 256 + 128 + t] = hb[(size_t)s_send[e] * HH + t];
    }
    __syncthreads();

    float acc[TE];

    // ---- hm layer 1: tanh([r,s] @ msg_w1 + b1) ----
    {
        const float bv = mb1[t];
        #pragma unroll
        for (int e = 0; e < TE; e++) acc[e] = bv;
        gemm_tile<TE, 256, 256>(feat, mw1, t, acc);
        #pragma unroll
        for (int e = 0; e < TE; e++) mid[e * 128 + t] = tanhf(acc[e]);
    }
    __syncthreads();

    // ---- hm layer 2 + scatter ----
    {
        const float bv = mb2[t];
        #pragma unroll
        for (int e = 0; e < TE; e++) acc[e] = bv;
        gemm_tile<TE, 128, 128>(mid, mw2, t, acc);
        float* hs = g_hm_sum + (size_t)b * NN * HH;
        #pragma unroll
        for (int e = 0; e < TE; e++)
            atomicAdd(hs + (size_t)s_recv[e] * HH + t, tanhf(acc[e]));
    }
    __syncthreads();   // all feat/mid reads done before reuse

    // ---- stage edge_attr ----
    const float* ea = edge_attr + ((size_t)b * EE + e0) * FF;
    #pragma unroll
    for (int e = 0; e < TE; e++) {
        feat[e * 256 + t] = ea[(size_t)e * FF + t];
        if (t < FF - 128) feat[e * 256 + 128 + t] = ea[(size_t)e * FF + 128 + t];
    }
    __syncthreads();

    // ---- pm layer 1: relu(edge_attr @ pm_w1 + b1) ----
    {
        const float bv = pb1[t];
        #pragma unroll
        for (int e = 0; e < TE; e++) acc[e] = bv;
        gemm_tile<TE, 140, 256>(feat, pw1, t, acc);
        #pragma unroll
        for (int e = 0; e < TE; e++) mid[e * 128 + t] = fmaxf(acc[e], 0.0f);
    }
    __syncthreads();

    // ---- pm layer 2 + scatter ----
    {
        const float bv = pb2[t];
        #pragma unroll
        for (int e = 0; e < TE; e++) acc[e] = bv;
        gemm_tile<TE, 128, 128>(mid, pw2, t, acc);
        float* ps = g_pm_sum + (size_t)b * NN * HH;
        #pragma unroll
        for (int e = 0; e < TE; e++)
            atomicAdd(ps + (size_t)s_recv[e] * HH + t, fmaxf(acc[e], 0.0f));
    }
}

__global__ void __launch_bounds__(128) node_kernel(
    const float* __restrict__ inputs,
    const float* __restrict__ hidden,
    const float* __restrict__ res_w1, const float* __restrict__ res_b1,
    const float* __restrict__ res_w2, const float* __restrict__ res_b2,
    const float* __restrict__ ir_w,   const float* __restrict__ ir_b,
    const float* __restrict__ ii_w,   const float* __restrict__ ii_b,
    const float* __restrict__ in_w,   const float* __restrict__ in_b,
    const float* __restrict__ hr_w,
    const float* __restrict__ hi_w,
    const float* __restrict__ hh_w,
    const float* __restrict__ out_w1, const float* __restrict__ out_b1,
    const float* __restrict__ out_w2, const float* __restrict__ out_b2,
    const float* __restrict__ out_w3, const float* __restrict__ out_b3,
    float* __restrict__ out_pred,
    float* __restrict__ out_hidden)
{
    extern __shared__ float sm[];
    float* s_pres = sm;                 // NT*128
    float* s_hemb = s_pres + NT * 128;  // NT*128
    float* s_a    = s_hemb + NT * 128;  // NT*128
    float* s_b    = s_a    + NT * 128;  // NT*128

    const int t    = threadIdx.x;           // 0..127
    const int row0 = blockIdx.x * NT;       // row in [0, B*N)

    float inv[NT];
    #pragma unroll
    for (int e = 0; e < NT; e++) {
        int n = (row0 + e) & (NN - 1);
        inv[e] = 1.0f / fmaxf((float)g_cnt[n], 1.0f);
    }

    // hemb = mean(hm), s_pres <- mean(pm) (temp), s_a <- inputs row
    #pragma unroll
    for (int e = 0; e < NT; e++) {
        size_t off = (size_t)(row0 + e) * HH + t;
        s_hemb[e * 128 + t] = g_hm_sum[off] * inv[e];
        s_pres[e * 128 + t] = g_pm_sum[off] * inv[e];
        s_a[e * 128 + t]    = inputs[off];   // I == H == 128
    }
    __syncthreads();

    float acc[NT];

    // res layer 1
    {
        const float bv = res_b1[t];
        #pragma unroll
        for (int e = 0; e < NT; e++) acc[e] = bv;
        gemm_tile<NT, 128, 128>(s_a, res_w1, t, acc);
        #pragma unroll
        for (int e = 0; e < NT; e++) s_b[e * 128 + t] = fmaxf(acc[e], 0.0f);
    }
    __syncthreads();

    // res layer 2 + add pm-mean -> present
    {
        const float bv = res_b2[t];
        #pragma unroll
        for (int e = 0; e < NT; e++) acc[e] = bv;
        gemm_tile<NT, 128, 128>(s_b, res_w2, t, acc);
        #pragma unroll
        for (int e = 0; e < NT; e++)
            acc[e] = fmaxf(acc[e], 0.0f) + s_pres[e * 128 + t];
        #pragma unroll
        for (int e = 0; e < NT; e++) s_pres[e * 128 + t] = acc[e];
    }
    __syncthreads();

    // r gate -> s_a
    {
        const float bv = ir_b[t];
        #pragma unroll
        for (int e = 0; e < NT; e++) acc[e] = bv;
        gemm_tile<NT, 128, 128>(s_pres, ir_w, t, acc);
        gemm_tile<NT, 128, 128>(s_hemb, hr_w, t, acc);
        #pragma unroll
        for (int e = 0; e < NT; e++) s_a[e * 128 + t] = sigmoidf_(acc[e]);
    }
    // i gate -> s_b
    {
        const float bv = ii_b[t];
        #pragma unroll
        for (int e = 0; e < NT; e++) acc[e] = bv;
        gemm_tile<NT, 128, 128>(s_pres, ii_w, t, acc);
        gemm_tile<NT, 128, 128>(s_hemb, hi_w, t, acc);
        #pragma unroll
        for (int e = 0; e < NT; e++) s_b[e * 128 + t] = sigmoidf_(acc[e]);
    }
    // n gate + blend
    {
        float acc2[NT];
        #pragma unroll
        for (int e = 0; e < NT; e++) acc2[e] = 0.0f;
        gemm_tile<NT, 128, 128>(s_hemb, hh_w, t, acc2);

        const float bv = in_b[t];
        #pragma unroll
        for (int e = 0; e < NT; e++) acc[e] = bv;
        gemm_tile<NT, 128, 128>(s_pres, in_w, t, acc);

        #pragma unroll
        for (int e = 0; e < NT; e++) {
            float ng = tanhf(acc[e] + s_a[e * 128 + t] * acc2[e]);
            float ig = s_b[e * 128 + t];
            float ih = hidden[(size_t)(row0 + e) * HH + t];
            float nh = (1.0f - ig) * ng + ig * ih;
            out_hidden[(size_t)(row0 + e) * HH + t] = nh;
            acc[e] = nh;
        }
        #pragma unroll
        for (int e = 0; e < NT; e++) s_a[e * 128 + t] = acc[e];
    }
    __syncthreads();

    // out layer 1
    {
        const float bv = out_b1[t];
        #pragma unroll
        for (int e = 0; e < NT; e++) acc[e] = bv;
        gemm_tile<NT, 128, 128>(s_a, out_w1, t, acc);
        #pragma unroll
        for (int e = 0; e < NT; e++) s_b[e * 128 + t] = fmaxf(acc[e], 0.0f);
    }
    __syncthreads();

    // out layer 2
    {
        const float bv = out_b2[t];
        #pragma unroll
        for (int e = 0; e < NT; e++) acc[e] = bv;
        gemm_tile<NT, 128, 128>(s_b, out_w2, t, acc);
        #pragma unroll
        for (int e = 0; e < NT; e++) s_pres[e * 128 + t] = fmaxf(acc[e], 0.0f);
    }
    __syncthreads();

    // out layer 3 -> pred
    {
        const float bv = out_b3[t];
        #pragma unroll
        for (int e = 0; e < NT; e++) acc[e] = bv;
        gemm_tile<NT, 128, 128>(s_pres, out_w3, t, acc);
        #pragma unroll
        for (int e = 0; e < NT; e++)
            out_pred[(size_t)(row0 + e) * II + t] = acc[e];
    }
}

extern "C" void kernel_launch(void* const* d_in, const int* in_sizes, int n_in,
                              void* d_out, int out_size) {
    const float* inputs    = (const float*)d_in[0];
    const float* edge_attr = (const float*)d_in[1];
    const int*   send_e    = (const int*)  d_in[2];
    const int*   recv_e    = (const int*)  d_in[3];
    const float* hidden    = (const float*)d_in[4];
    const float* msg_w1 = (const float*)d_in[5];
    const float* msg_b1 = (const float*)d_in[6];
    const float* msg_w2 = (const float*)d_in[7];
    const float* msg_b2 = (const float*)d_in[8];
    const float* pm_w1  = (const float*)d_in[9];
    const float* pm_b1  = (const float*)d_in[10];
    const float* pm_w2  = (const float*)d_in[11];
    const float* pm_b2  = (const float*)d_in[12];
    const float* res_w1 = (const float*)d_in[13];
    const float* res_b1 = (const float*)d_in[14];
    const float* res_w2 = (const float*)d_in[15];
    const float* res_b2 = (const float*)d_in[16];
    const float* ir_w   = (const float*)d_in[17];
    const float* ir_b   = (const float*)d_in[18];
    const float* ii_w   = (const float*)d_in[19];
    const float* ii_b   = (const float*)d_in[20];
    const float* in_w   = (const float*)d_in[21];
    const float* in_b   = (const float*)d_in[22];
    const float* hr_w   = (const float*)d_in[23];
    const float* hi_w   = (const float*)d_in[24];
    const float* hh_w   = (const float*)d_in[25];
    const float* out_w1 = (const float*)d_in[26];
    const float* out_b1 = (const float*)d_in[27];
    const float* out_w2 = (const float*)d_in[28];
    const float* out_b2 = (const float*)d_in[29];
    const float* out_w3 = (const float*)d_in[30];
    const float* out_b3 = (const float*)d_in[31];

    float* out_pred   = (float*)d_out;
    float* out_hidden = (float*)d_out + (size_t)BB * NN * II;

    const int EDGE_SMEM = (TE * 256 + TE * 128) * 4 + 2 * TE * 4;    // 49,408 B
    const int NODE_SMEM = 4 * NT * 128 * 4;                          // 32,768 B
    cudaFuncSetAttribute(edge_kernel, cudaFuncAttributeMaxDynamicSharedMemorySize, EDGE_SMEM);

    zero_kernel<<<1024, 256>>>();
    count_kernel<<<EE / 256, 256>>>(recv_e);
    edge_kernel<<<dim3(EE / TE, BB), 128, EDGE_SMEM>>>(
        hidden, edge_attr, send_e, recv_e,
        msg_w1, msg_b1, msg_w2, msg_b2,
        pm_w1, pm_b1, pm_w2, pm_b2);
    node_kernel<<<(BB * NN) / NT, 128, NODE_SMEM>>>(
        inputs, hidden,
        res_w1, res_b1, res_w2, res_b2,
        ir_w, ir_b, ii_w, ii_b, in_w, in_b,
        hr_w, hi_w, hh_w,
        out_w1, out_b1, out_w2, out_b2, out_w3, out_b3,
        out_pred, out_hidden);
}

// round 5
// speedup vs baseline: 2.6738x; 2.6738x over previous
#include <cuda_runtime.h>
#include <math.h>
#include <stdint.h>

// Problem constants
#define BB 4
#define NN 4096
#define EE 131072
#define II 128
#define HH 128
#define FF 140

#define NT 16   // rows per block in node kernel

// ---------------- scratch (__device__ globals; no allocs allowed) ----------
__device__ float g_hm_sum[(size_t)BB * NN * HH];   // 8 MB
__device__ float g_pm_sum[(size_t)BB * NN * HH];   // 8 MB
__device__ int   g_cnt[NN];

// permuted tf32-rounded weights: w[k][ (n%8)*16 + n/8 ]
__device__ float g_w1p[256 * 128];
__device__ float g_w2p[128 * 128];
__device__ float g_pw1p[144 * 128];   // K padded 140 -> 144 with zeros
__device__ float g_pw2p[128 * 128];

__device__ __forceinline__ float sigmoidf_(float x) {
    return 1.0f / (1.0f + expf(-x));
}

__device__ __forceinline__ unsigned rna(float x) {
    unsigned r;
    asm("cvt.rna.tf32.f32 %0, %1;" : "=r"(r) : "f"(x));
    return r;
}

__device__ __forceinline__ void mma8(float* c,
                                     unsigned a0, unsigned a1, unsigned a2, unsigned a3,
                                     unsigned b0, unsigned b1) {
    asm volatile(
        "mma.sync.aligned.m16n8k8.row.col.f32.tf32.tf32.f32 "
        "{%0,%1,%2,%3}, {%4,%5,%6,%7}, {%8,%9}, {%0,%1,%2,%3};"
        : "+f"(c[0]), "+f"(c[1]), "+f"(c[2]), "+f"(c[3])
        : "r"(a0), "r"(a1), "r"(a2), "r"(a3), "r"(b0), "r"(b1));
}

// ---------------- helper kernels ----------------

__global__ void zero_kernel() {
    const size_t M = (size_t)BB * NN * HH;
    size_t stride = (size_t)gridDim.x * blockDim.x;
    size_t i = (size_t)blockIdx.x * blockDim.x + threadIdx.x;
    for (size_t j = i; j < M; j += stride) {
        g_hm_sum[j] = 0.0f;
        g_pm_sum[j] = 0.0f;
    }
    if (i < NN) g_cnt[i] = 0;
}

__global__ void count_kernel(const int* __restrict__ recv_e) {
    int e = blockIdx.x * blockDim.x + threadIdx.x;
    if (e < EE) atomicAdd(&g_cnt[recv_e[e]], 1);
}

__global__ void prep_kernel(const float* __restrict__ mw1,
                            const float* __restrict__ mw2,
                            const float* __restrict__ pw1,
                            const float* __restrict__ pw2) {
    int i = blockIdx.x * blockDim.x + threadIdx.x;   // up to 32768
    if (i < 256 * 128) {
        int k = i >> 7, n = i & 127;
        g_w1p[k * 128 + ((n & 7) * 16 + (n >> 3))] = __uint_as_float(rna(mw1[i]));
    }
    if (i < 128 * 128) {
        int k = i >> 7, n = i & 127;
        int s = k * 128 + ((n & 7) * 16 + (n >> 3));
        g_w2p[s]  = __uint_as_float(rna(mw2[i]));
        g_pw2p[s] = __uint_as_float(rna(pw2[i]));
    }
    if (i < 144 * 128) {
        int k = i >> 7, n = i & 127;
        float v = (k < 140) ? pw1[i] : 0.0f;
        g_pw1p[k * 128 + ((n & 7) * 16 + (n >> 3))] = __uint_as_float(rna(v));
    }
}

// ---------------- hm edge kernel (tf32 tensor cores) ----------------
// tile: 128 edges x 128 out-features, K=256 (concat recv||send), then K=128.
// smem floats: Ac[128][36] | Bc[32][132] | mid[128][132] | idx[256]
#define HM_A_OFF 0
#define HM_B_OFF (128 * 36)
#define HM_M_OFF (HM_B_OFF + 32 * 132)
#define HM_SMEMF (HM_M_OFF + 128 * 132 + 256)

__global__ void __launch_bounds__(256) hm_kernel(
    const float* __restrict__ hidden,
    const int* __restrict__ send_e, const int* __restrict__ recv_e,
    const float* __restrict__ mb1, const float* __restrict__ mb2)
{
    extern __shared__ __align__(16) float sm[];
    int* s_recv = (int*)(sm + HM_M_OFF + 128 * 132);
    int* s_send = s_recv + 128;

    const int tid = threadIdx.x;
    const int b   = blockIdx.y;
    const int e0  = blockIdx.x * 128;

    if (tid < 128) s_recv[tid] = recv_e[e0 + tid];
    else           s_send[tid - 128] = send_e[e0 + tid - 128];

    const int warp = tid >> 5, lane = tid & 31;
    const int wm = warp >> 1, wn = warp & 1;      // 4 M-warps x 2 N-warps
    const int m0 = wm * 32, n0 = wn * 64;
    const int g = lane >> 2, q = lane & 3;

    float acc[2][8][4];
    #pragma unroll
    for (int j = 0; j < 8; j++) {
        int c0 = n0 + 8 * j + 2 * q;
        float b0v = __ldg(mb1 + c0), b1v = __ldg(mb1 + c0 + 1);
        #pragma unroll
        for (int t = 0; t < 2; t++) {
            acc[t][j][0] = b0v; acc[t][j][1] = b1v;
            acc[t][j][2] = b0v; acc[t][j][3] = b1v;
        }
    }
    __syncthreads();

    const float* hb = hidden + (size_t)b * NN * HH;

    // ---------------- layer 1: K = 256 in 8 chunks of 32 ----------------
    #pragma unroll 1
    for (int kc = 0; kc < 8; kc++) {
        if (kc) __syncthreads();
        const int* nidx = (kc < 4) ? s_recv : s_send;
        const int kk0 = (kc < 4) ? kc * 32 : kc * 32 - 128;
        #pragma unroll
        for (int i = 0; i < 4; i++) {
            int it = tid + i * 256;              // 0..1023
            int e = it >> 3, v = it & 7;
            float4 f = *(const float4*)(hb + (size_t)nidx[e] * HH + kk0 + v * 4);
            uint4 r;
            r.x = rna(f.x); r.y = rna(f.y); r.z = rna(f.z); r.w = rna(f.w);
            *(uint4*)(sm + HM_A_OFF + e * 36 + v * 4) = r;
        }
        const float4* wsrc = (const float4*)g_w1p + kc * 32 * 32;
        #pragma unroll
        for (int i = 0; i < 4; i++) {
            int it = tid + i * 256;
            int r = it >> 5, c = it & 31;
            *(float4*)(sm + HM_B_OFF + r * 132 + c * 4) = wsrc[r * 32 + c];
        }
        __syncthreads();

        const unsigned* Au = (const unsigned*)(sm + HM_A_OFF);
        const float4*   B4 = (const float4*)(sm + HM_B_OFF);
        #pragma unroll
        for (int ks = 0; ks < 4; ks++) {
            int kr = ks * 8;
            int bb0 = (kr + q) * 33 + g * 4 + wn * 2;
            int bb1 = (kr + q + 4) * 33 + g * 4 + wn * 2;
            float4 u0 = B4[bb0], u1 = B4[bb0 + 1];
            float4 v0 = B4[bb1], v1 = B4[bb1 + 1];
            unsigned bu[8] = {__float_as_uint(u0.x), __float_as_uint(u0.y),
                              __float_as_uint(u0.z), __float_as_uint(u0.w),
                              __float_as_uint(u1.x), __float_as_uint(u1.y),
                              __float_as_uint(u1.z), __float_as_uint(u1.w)};
            unsigned bv[8] = {__float_as_uint(v0.x), __float_as_uint(v0.y),
                              __float_as_uint(v0.z), __float_as_uint(v0.w),
                              __float_as_uint(v1.x), __float_as_uint(v1.y),
                              __float_as_uint(v1.z), __float_as_uint(v1.w)};
            #pragma unroll
            for (int t = 0; t < 2; t++) {
                int r0 = (m0 + t * 16 + g) * 36 + kr + q;
                unsigned a0 = Au[r0], a1 = Au[r0 + 8 * 36];
                unsigned a2 = Au[r0 + 4], a3 = Au[r0 + 8 * 36 + 4];
                #pragma unroll
                for (int j = 0; j < 8; j++) mma8(acc[t][j], a0, a1, a2, a3, bu[j], bv[j]);
            }
        }
    }

    // activation -> mid (tf32-rounded bits for layer-2 A)
    #pragma unroll
    for (int t = 0; t < 2; t++) {
        int r = m0 + t * 16 + g;
        #pragma unroll
        for (int j = 0; j < 8; j++) {
            int c0 = n0 + 8 * j + 2 * q;
            sm[HM_M_OFF + r * 132 + c0]           = __uint_as_float(rna(tanhf(acc[t][j][0])));
            sm[HM_M_OFF + r * 132 + c0 + 1]       = __uint_as_float(rna(tanhf(acc[t][j][1])));
            sm[HM_M_OFF + (r + 8) * 132 + c0]     = __uint_as_float(rna(tanhf(acc[t][j][2])));
            sm[HM_M_OFF + (r + 8) * 132 + c0 + 1] = __uint_as_float(rna(tanhf(acc[t][j][3])));
        }
    }

    // ---------------- layer 2: K = 128 in 4 chunks of 32 ----------------
    float acc2[2][8][4];
    #pragma unroll
    for (int j = 0; j < 8; j++) {
        int c0 = n0 + 8 * j + 2 * q;
        float b0v = __ldg(mb2 + c0), b1v = __ldg(mb2 + c0 + 1);
        #pragma unroll
        for (int t = 0; t < 2; t++) {
            acc2[t][j][0] = b0v; acc2[t][j][1] = b1v;
            acc2[t][j][2] = b0v; acc2[t][j][3] = b1v;
        }
    }

    #pragma unroll 1
    for (int c2 = 0; c2 < 4; c2++) {
        __syncthreads();
        const float4* wsrc = (const float4*)g_w2p + c2 * 32 * 32;
        #pragma unroll
        for (int i = 0; i < 4; i++) {
            int it = tid + i * 256;
            int r = it >> 5, c = it & 31;
            *(float4*)(sm + HM_B_OFF + r * 132 + c * 4) = wsrc[r * 32 + c];
        }
        __syncthreads();

        const unsigned* Mu = (const unsigned*)(sm + HM_M_OFF);
        const float4*   B4 = (const float4*)(sm + HM_B_OFF);
        #pragma unroll
        for (int ks = 0; ks < 4; ks++) {
            int kr = ks * 8;
            int bb0 = (kr + q) * 33 + g * 4 + wn * 2;
            int bb1 = (kr + q + 4) * 33 + g * 4 + wn * 2;
            float4 u0 = B4[bb0], u1 = B4[bb0 + 1];
            float4 v0 = B4[bb1], v1 = B4[bb1 + 1];
            unsigned bu[8] = {__float_as_uint(u0.x), __float_as_uint(u0.y),
                              __float_as_uint(u0.z), __float_as_uint(u0.w),
                              __float_as_uint(u1.x), __float_as_uint(u1.y),
                              __float_as_uint(u1.z), __float_as_uint(u1.w)};
            unsigned bv[8] = {__float_as_uint(v0.x), __float_as_uint(v0.y),
                              __float_as_uint(v0.z), __float_as_uint(v0.w),
                              __float_as_uint(v1.x), __float_as_uint(v1.y),
                              __float_as_uint(v1.z), __float_as_uint(v1.w)};
            #pragma unroll
            for (int t = 0; t < 2; t++) {
                int r0 = (m0 + t * 16 + g) * 132 + c2 * 32 + kr + q;
                unsigned a0 = Mu[r0], a1 = Mu[r0 + 8 * 132];
                unsigned a2 = Mu[r0 + 4], a3 = Mu[r0 + 8 * 132 + 4];
                #pragma unroll
                for (int j = 0; j < 8; j++) mma8(acc2[t][j], a0, a1, a2, a3, bu[j], bv[j]);
            }
        }
    }

    __syncthreads();   // all layer-2 mid reads complete before overwrite
    #pragma unroll
    for (int t = 0; t < 2; t++) {
        int r = m0 + t * 16 + g;
        #pragma unroll
        for (int j = 0; j < 8; j++) {
            int c0 = n0 + 8 * j + 2 * q;
            sm[HM_M_OFF + r * 132 + c0]           = tanhf(acc2[t][j][0]);
            sm[HM_M_OFF + r * 132 + c0 + 1]       = tanhf(acc2[t][j][1]);
            sm[HM_M_OFF + (r + 8) * 132 + c0]     = tanhf(acc2[t][j][2]);
            sm[HM_M_OFF + (r + 8) * 132 + c0 + 1] = tanhf(acc2[t][j][3]);
        }
    }
    __syncthreads();

    // coalesced scatter
    float* dst = g_hm_sum + (size_t)b * NN * HH;
    const int colt = tid & 127, eh = tid >> 7;
    #pragma unroll 1
    for (int e = eh; e < 128; e += 2)
        atomicAdd(dst + (size_t)s_recv[e] * HH + colt, sm[HM_M_OFF + e * 132 + colt]);
}

// ---------------- pm edge kernel (tf32) ----------------
// K1 = 144 (140 zero-padded) in 3 chunks of 48; K2 = 128 in 4 chunks of 32.
// smem floats: Ac[128][52] | Bc[48][132] | mid[128][132] | idx[128]
#define PM_A_OFF 0
#define PM_B_OFF (128 * 52)
#define PM_M_OFF (PM_B_OFF + 48 * 132)
#define PM_SMEMF (PM_M_OFF + 128 * 132 + 128)

__global__ void __launch_bounds__(256) pm_kernel(
    const float* __restrict__ edge_attr,
    const int* __restrict__ recv_e,
    const float* __restrict__ pb1, const float* __restrict__ pb2)
{
    extern __shared__ __align__(16) float sm[];
    int* s_recv = (int*)(sm + PM_M_OFF + 128 * 132);

    const int tid = threadIdx.x;
    const int b   = blockIdx.y;
    const int e0  = blockIdx.x * 128;

    if (tid < 128) s_recv[tid] = recv_e[e0 + tid];

    const int warp = tid >> 5, lane = tid & 31;
    const int wm = warp >> 1, wn = warp & 1;
    const int m0 = wm * 32, n0 = wn * 64;
    const int g = lane >> 2, q = lane & 3;

    float acc[2][8][4];
    #pragma unroll
    for (int j = 0; j < 8; j++) {
        int c0 = n0 + 8 * j + 2 * q;
        float b0v = __ldg(pb1 + c0), b1v = __ldg(pb1 + c0 + 1);
        #pragma unroll
        for (int t = 0; t < 2; t++) {
            acc[t][j][0] = b0v; acc[t][j][1] = b1v;
            acc[t][j][2] = b0v; acc[t][j][3] = b1v;
        }
    }
    __syncthreads();

    const float* ea = edge_attr + ((size_t)b * EE + e0) * FF;

    // ---------------- layer 1: 3 chunks of 48 ----------------
    #pragma unroll 1
    for (int kc = 0; kc < 3; kc++) {
        if (kc) __syncthreads();
        const int k0 = kc * 48;
        #pragma unroll
        for (int i = 0; i < 12; i++) {
            int it = tid + i * 256;           // 0..3071
            int e = it / 24, c = it % 24;
            int f = k0 + c * 2;
            float2 v;
            if (f < FF) v = *(const float2*)(ea + (size_t)e * FF + f);
            else { v.x = 0.0f; v.y = 0.0f; }
            uint2 r; r.x = rna(v.x); r.y = rna(v.y);
            *(uint2*)(sm + PM_A_OFF + e * 52 + c * 2) = r;
        }
        const float4* wsrc = (const float4*)g_pw1p + k0 * 32;
        #pragma unroll
        for (int i = 0; i < 6; i++) {
            int it = tid + i * 256;           // 0..1535
            int r = it >> 5, c = it & 31;
            *(float4*)(sm + PM_B_OFF + r * 132 + c * 4) = wsrc[r * 32 + c];
        }
        __syncthreads();

        const unsigned* Au = (const unsigned*)(sm + PM_A_OFF);
        const float4*   B4 = (const float4*)(sm + PM_B_OFF);
        #pragma unroll
        for (int ks = 0; ks < 6; ks++) {
            int kr = ks * 8;
            int bb0 = (kr + q) * 33 + g * 4 + wn * 2;
            int bb1 = (kr + q + 4) * 33 + g * 4 + wn * 2;
            float4 u0 = B4[bb0], u1 = B4[bb0 + 1];
            float4 v0 = B4[bb1], v1 = B4[bb1 + 1];
            unsigned bu[8] = {__float_as_uint(u0.x), __float_as_uint(u0.y),
                              __float_as_uint(u0.z), __float_as_uint(u0.w),
                              __float_as_uint(u1.x), __float_as_uint(u1.y),
                              __float_as_uint(u1.z), __float_as_uint(u1.w)};
            unsigned bv[8] = {__float_as_uint(v0.x), __float_as_uint(v0.y),
                              __float_as_uint(v0.z), __float_as_uint(v0.w),
                              __float_as_uint(v1.x), __float_as_uint(v1.y),
                              __float_as_uint(v1.z), __float_as_uint(v1.w)};
            #pragma unroll
            for (int t = 0; t < 2; t++) {
                int r0 = (m0 + t * 16 + g) * 52 + kr + q;
                unsigned a0 = Au[r0], a1 = Au[r0 + 8 * 52];
                unsigned a2 = Au[r0 + 4], a3 = Au[r0 + 8 * 52 + 4];
                #pragma unroll
                for (int j = 0; j < 8; j++) mma8(acc[t][j], a0, a1, a2, a3, bu[j], bv[j]);
            }
        }
    }

    // relu -> mid
    #pragma unroll
    for (int t = 0; t < 2; t++) {
        int r = m0 + t * 16 + g;
        #pragma unroll
        for (int j = 0; j < 8; j++) {
            int c0 = n0 + 8 * j + 2 * q;
            sm[PM_M_OFF + r * 132 + c0]           = __uint_as_float(rna(fmaxf(acc[t][j][0], 0.0f)));
            sm[PM_M_OFF + r * 132 + c0 + 1]       = __uint_as_float(rna(fmaxf(acc[t][j][1], 0.0f)));
            sm[PM_M_OFF + (r + 8) * 132 + c0]     = __uint_as_float(rna(fmaxf(acc[t][j][2], 0.0f)));
            sm[PM_M_OFF + (r + 8) * 132 + c0 + 1] = __uint_as_float(rna(fmaxf(acc[t][j][3], 0.0f)));
        }
    }

    // ---------------- layer 2 ----------------
    float acc2[2][8][4];
    #pragma unroll
    for (int j = 0; j < 8; j++) {
        int c0 = n0 + 8 * j + 2 * q;
        float b0v = __ldg(pb2 + c0), b1v = __ldg(pb2 + c0 + 1);
        #pragma unroll
        for (int t = 0; t < 2; t++) {
            acc2[t][j][0] = b0v; acc2[t][j][1] = b1v;
            acc2[t][j][2] = b0v; acc2[t][j][3] = b1v;
        }
    }

    #pragma unroll 1
    for (int c2 = 0; c2 < 4; c2++) {
        __syncthreads();
        const float4* wsrc = (const float4*)g_pw2p + c2 * 32 * 32;
        #pragma unroll
        for (int i = 0; i < 4; i++) {
            int it = tid + i * 256;
            int r = it >> 5, c = it & 31;
            *(float4*)(sm + PM_B_OFF + r * 132 + c * 4) = wsrc[r * 32 + c];
        }
        __syncthreads();

        const unsigned* Mu = (const unsigned*)(sm + PM_M_OFF);
        const float4*   B4 = (const float4*)(sm + PM_B_OFF);
        #pragma unroll
        for (int ks = 0; ks < 4; ks++) {
            int kr = ks * 8;
            int bb0 = (kr + q) * 33 + g * 4 + wn * 2;
            int bb1 = (kr + q + 4) * 33 + g * 4 + wn * 2;
            float4 u0 = B4[bb0], u1 = B4[bb0 + 1];
            float4 v0 = B4[bb1], v1 = B4[bb1 + 1];
            unsigned bu[8] = {__float_as_uint(u0.x), __float_as_uint(u0.y),
                              __float_as_uint(u0.z), __float_as_uint(u0.w),
                              __float_as_uint(u1.x), __float_as_uint(u1.y),
                              __float_as_uint(u1.z), __float_as_uint(u1.w)};
            unsigned bv[8] = {__float_as_uint(v0.x), __float_as_uint(v0.y),
                              __float_as_uint(v0.z), __float_as_uint(v0.w),
                              __float_as_uint(v1.x), __float_as_uint(v1.y),
                              __float_as_uint(v1.z), __float_as_uint(v1.w)};
            #pragma unroll
            for (int t = 0; t < 2; t++) {
                int r0 = (m0 + t * 16 + g) * 132 + c2 * 32 + kr + q;
                unsigned a0 = Mu[r0], a1 = Mu[r0 + 8 * 132];
                unsigned a2 = Mu[r0 + 4], a3 = Mu[r0 + 8 * 132 + 4];
                #pragma unroll
                for (int j = 0; j < 8; j++) mma8(acc2[t][j], a0, a1, a2, a3, bu[j], bv[j]);
            }
        }
    }

    __syncthreads();
    #pragma unroll
    for (int t = 0; t < 2; t++) {
        int r = m0 + t * 16 + g;
        #pragma unroll
        for (int j = 0; j < 8; j++) {
            int c0 = n0 + 8 * j + 2 * q;
            sm[PM_M_OFF + r * 132 + c0]           = fmaxf(acc2[t][j][0], 0.0f);
            sm[PM_M_OFF + r * 132 + c0 + 1]       = fmaxf(acc2[t][j][1], 0.0f);
            sm[PM_M_OFF + (r + 8) * 132 + c0]     = fmaxf(acc2[t][j][2], 0.0f);
            sm[PM_M_OFF + (r + 8) * 132 + c0 + 1] = fmaxf(acc2[t][j][3], 0.0f);
        }
    }
    __syncthreads();

    float* dst = g_pm_sum + (size_t)b * NN * HH;
    const int colt = tid & 127, eh = tid >> 7;
    #pragma unroll 1
    for (int e = eh; e < 128; e += 2)
        atomicAdd(dst + (size_t)s_recv[e] * HH + colt, sm[PM_M_OFF + e * 132 + colt]);
}

// ---------------- node kernel (unchanged fp32, round-2 proven) ----------------
template<int TILE, int K, int PITCH>
__device__ __forceinline__ void gemm_tile(const float* in_s,
                                          const float* __restrict__ W,
                                          int t, float* acc) {
    for (int k = 0; k < K; k += 4) {
        float w0 = W[(k + 0) * 128 + t];
        float w1 = W[(k + 1) * 128 + t];
        float w2 = W[(k + 2) * 128 + t];
        float w3 = W[(k + 3) * 128 + t];
        #pragma unroll
        for (int e = 0; e < TILE; e++) {
            float4 f = *reinterpret_cast<const float4*>(in_s + e * PITCH + k);
            acc[e] = fmaf(f.x, w0, acc[e]);
            acc[e] = fmaf(f.y, w1, acc[e]);
            acc[e] = fmaf(f.z, w2, acc[e]);
            acc[e] = fmaf(f.w, w3, acc[e]);
        }
    }
}

__global__ void __launch_bounds__(128) node_kernel(
    const float* __restrict__ inputs,
    const float* __restrict__ hidden,
    const float* __restrict__ res_w1, const float* __restrict__ res_b1,
    const float* __restrict__ res_w2, const float* __restrict__ res_b2,
    const float* __restrict__ ir_w,   const float* __restrict__ ir_b,
    const float* __restrict__ ii_w,   const float* __restrict__ ii_b,
    const float* __restrict__ in_w,   const float* __restrict__ in_b,
    const float* __restrict__ hr_w,
    const float* __restrict__ hi_w,
    const float* __restrict__ hh_w,
    const float* __restrict__ out_w1, const float* __restrict__ out_b1,
    const float* __restrict__ out_w2, const float* __restrict__ out_b2,
    const float* __restrict__ out_w3, const float* __restrict__ out_b3,
    float* __restrict__ out_pred,
    float* __restrict__ out_hidden)
{
    extern __shared__ float smn[];
    float* s_pres = smn;
    float* s_hemb = s_pres + NT * 128;
    float* s_a    = s_hemb + NT * 128;
    float* s_b    = s_a    + NT * 128;

    const int t    = threadIdx.x;
    const int row0 = blockIdx.x * NT;

    float inv[NT];
    #pragma unroll
    for (int e = 0; e < NT; e++) {
        int n = (row0 + e) & (NN - 1);
        inv[e] = 1.0f / fmaxf((float)g_cnt[n], 1.0f);
    }

    #pragma unroll
    for (int e = 0; e < NT; e++) {
        size_t off = (size_t)(row0 + e) * HH + t;
        s_hemb[e * 128 + t] = g_hm_sum[off] * inv[e];
        s_pres[e * 128 + t] = g_pm_sum[off] * inv[e];
        s_a[e * 128 + t]    = inputs[off];
    }
    __syncthreads();

    float acc[NT];

    {
        const float bv = res_b1[t];
        #pragma unroll
        for (int e = 0; e < NT; e++) acc[e] = bv;
        gemm_tile<NT, 128, 128>(s_a, res_w1, t, acc);
        #pragma unroll
        for (int e = 0; e < NT; e++) s_b[e * 128 + t] = fmaxf(acc[e], 0.0f);
    }
    __syncthreads();

    {
        const float bv = res_b2[t];
        #pragma unroll
        for (int e = 0; e < NT; e++) acc[e] = bv;
        gemm_tile<NT, 128, 128>(s_b, res_w2, t, acc);
        #pragma unroll
        for (int e = 0; e < NT; e++)
            acc[e] = fmaxf(acc[e], 0.0f) + s_pres[e * 128 + t];
        #pragma unroll
        for (int e = 0; e < NT; e++) s_pres[e * 128 + t] = acc[e];
    }
    __syncthreads();

    {
        const float bv = ir_b[t];
        #pragma unroll
        for (int e = 0; e < NT; e++) acc[e] = bv;
        gemm_tile<NT, 128, 128>(s_pres, ir_w, t, acc);
        gemm_tile<NT, 128, 128>(s_hemb, hr_w, t, acc);
        #pragma unroll
        for (int e = 0; e < NT; e++) s_a[e * 128 + t] = sigmoidf_(acc[e]);
    }
    {
        const float bv = ii_b[t];
        #pragma unroll
        for (int e = 0; e < NT; e++) acc[e] = bv;
        gemm_tile<NT, 128, 128>(s_pres, ii_w, t, acc);
        gemm_tile<NT, 128, 128>(s_hemb, hi_w, t, acc);
        #pragma unroll
        for (int e = 0; e < NT; e++) s_b[e * 128 + t] = sigmoidf_(acc[e]);
    }
    {
        float acc2[NT];
        #pragma unroll
        for (int e = 0; e < NT; e++) acc2[e] = 0.0f;
        gemm_tile<NT, 128, 128>(s_hemb, hh_w, t, acc2);

        const float bv = in_b[t];
        #pragma unroll
        for (int e = 0; e < NT; e++) acc[e] = bv;
        gemm_tile<NT, 128, 128>(s_pres, in_w, t, acc);

        #pragma unroll
        for (int e = 0; e < NT; e++) {
            float ng = tanhf(acc[e] + s_a[e * 128 + t] * acc2[e]);
            float ig = s_b[e * 128 + t];
            float ih = hidden[(size_t)(row0 + e) * HH + t];
            float nh = (1.0f - ig) * ng + ig * ih;
            out_hidden[(size_t)(row0 + e) * HH + t] = nh;
            acc[e] = nh;
        }
        #pragma unroll
        for (int e = 0; e < NT; e++) s_a[e * 128 + t] = acc[e];
    }
    __syncthreads();

    {
        const float bv = out_b1[t];
        #pragma unroll
        for (int e = 0; e < NT; e++) acc[e] = bv;
        gemm_tile<NT, 128, 128>(s_a, out_w1, t, acc);
        #pragma unroll
        for (int e = 0; e < NT; e++) s_b[e * 128 + t] = fmaxf(acc[e], 0.0f);
    }
    __syncthreads();

    {
        const float bv = out_b2[t];
        #pragma unroll
        for (int e = 0; e < NT; e++) acc[e] = bv;
        gemm_tile<NT, 128, 128>(s_b, out_w2, t, acc);
        #pragma unroll
        for (int e = 0; e < NT; e++) s_pres[e * 128 + t] = fmaxf(acc[e], 0.0f);
    }
    __syncthreads();

    {
        const float bv = out_b3[t];
        #pragma unroll
        for (int e = 0; e < NT; e++) acc[e] = bv;
        gemm_tile<NT, 128, 128>(s_pres, out_w3, t, acc);
        #pragma unroll
        for (int e = 0; e < NT; e++)
            out_pred[(size_t)(row0 + e) * II + t] = acc[e];
    }
}

// ---------------- launch ----------------
extern "C" void kernel_launch(void* const* d_in, const int* in_sizes, int n_in,
                              void* d_out, int out_size) {
    const float* inputs    = (const float*)d_in[0];
    const float* edge_attr = (const float*)d_in[1];
    const int*   send_e    = (const int*)  d_in[2];
    const int*   recv_e    = (const int*)  d_in[3];
    const float* hidden    = (const float*)d_in[4];
    const float* msg_w1 = (const float*)d_in[5];
    const float* msg_b1 = (const float*)d_in[6];
    const float* msg_w2 = (const float*)d_in[7];
    const float* msg_b2 = (const float*)d_in[8];
    const float* pm_w1  = (const float*)d_in[9];
    const float* pm_b1  = (const float*)d_in[10];
    const float* pm_w2  = (const float*)d_in[11];
    const float* pm_b2  = (const float*)d_in[12];
    const float* res_w1 = (const float*)d_in[13];
    const float* res_b1 = (const float*)d_in[14];
    const float* res_w2 = (const float*)d_in[15];
    const float* res_b2 = (const float*)d_in[16];
    const float* ir_w   = (const float*)d_in[17];
    const float* ir_b   = (const float*)d_in[18];
    const float* ii_w   = (const float*)d_in[19];
    const float* ii_b   = (const float*)d_in[20];
    const float* in_w   = (const float*)d_in[21];
    const float* in_b   = (const float*)d_in[22];
    const float* hr_w   = (const float*)d_in[23];
    const float* hi_w   = (const float*)d_in[24];
    const float* hh_w   = (const float*)d_in[25];
    const float* out_w1 = (const float*)d_in[26];
    const float* out_b1 = (const float*)d_in[27];
    const float* out_w2 = (const float*)d_in[28];
    const float* out_b2 = (const float*)d_in[29];
    const float* out_w3 = (const float*)d_in[30];
    const float* out_b3 = (const float*)d_in[31];

    float* out_pred   = (float*)d_out;
    float* out_hidden = (float*)d_out + (size_t)BB * NN * II;

    const int HM_SMEM = HM_SMEMF * 4;   // ~103.9 KB
    const int PM_SMEM = PM_SMEMF * 4;   // ~120.1 KB
    const int NODE_SMEM = 4 * NT * 128 * 4;
    cudaFuncSetAttribute(hm_kernel, cudaFuncAttributeMaxDynamicSharedMemorySize, HM_SMEM);
    cudaFuncSetAttribute(pm_kernel, cudaFuncAttributeMaxDynamicSharedMemorySize, PM_SMEM);

    zero_kernel<<<1024, 256>>>();
    count_kernel<<<EE / 256, 256>>>(recv_e);
    prep_kernel<<<128, 256>>>(msg_w1, msg_w2, pm_w1, pm_w2);

    hm_kernel<<<dim3(EE / 128, BB), 256, HM_SMEM>>>(hidden, send_e, recv_e, msg_b1, msg_b2);
    pm_kernel<<<dim3(EE / 128, BB), 256, PM_SMEM>>>(edge_attr, recv_e, pm_b1, pm_b2);

    node_kernel<<<(BB * NN) / NT, 128, NODE_SMEM>>>(
        inputs, hidden,
        res_w1, res_b1, res_w2, res_b2,
        ir_w, ir_b, ii_w, ii_b, in_w, in_b,
        hr_w, hi_w, hh_w,
        out_w1, out_b1, out_w2, out_b2, out_w3, out_b3,
        out_pred, out_hidden);
}

// round 8
// speedup vs baseline: 2.7181x; 1.0165x over previous
#include <cuda_runtime.h>
#include <math.h>
#include <stdint.h>

// Problem constants
#define BB 4
#define NN 4096
#define EE 131072
#define II 128
#define HH 128
#define FF 140

// ---------------- scratch (__device__ globals; no allocs allowed) ----------
__device__ float g_hm_sum[(size_t)BB * NN * HH];   // 8 MB
__device__ float g_pm_sum[(size_t)BB * NN * HH];   // 8 MB
__device__ int   g_cnt[NN];

// permuted tf32-rounded weights: w[k][ (n%8)*16 + n/8 ]
__device__ float g_w1p[256 * 128];
__device__ float g_w2p[128 * 128];
__device__ float g_pw1p[144 * 128];   // K padded 140 -> 144 with zeros
__device__ float g_pw2p[128 * 128];
// node weights, same permutation: order
// 0:res_w1 1:res_w2 2:ir_w 3:hr_w 4:ii_w 5:hi_w 6:in_w 7:hh_w 8:out_w1 9:out_w2 10:out_w3
__device__ float g_nw[11][128 * 128];

__device__ __forceinline__ float sigmoidf_(float x) {
    return 1.0f / (1.0f + expf(-x));
}

__device__ __forceinline__ unsigned rna(float x) {
    unsigned r;
    asm("cvt.rna.tf32.f32 %0, %1;" : "=r"(r) : "f"(x));
    return r;
}
__device__ __forceinline__ float uif(unsigned x) { return __uint_as_float(x); }

__device__ __forceinline__ void mma8(float* c,
                                     unsigned a0, unsigned a1, unsigned a2, unsigned a3,
                                     unsigned b0, unsigned b1) {
    asm volatile(
        "mma.sync.aligned.m16n8k8.row.col.f32.tf32.tf32.f32 "
        "{%0,%1,%2,%3}, {%4,%5,%6,%7}, {%8,%9}, {%0,%1,%2,%3};"
        : "+f"(c[0]), "+f"(c[1]), "+f"(c[2]), "+f"(c[3])
        : "r"(a0), "r"(a1), "r"(a2), "r"(a3), "r"(b0), "r"(b1));
}

__device__ __forceinline__ void red4(float* p, float4 v) {
    asm volatile("red.global.add.v4.f32 [%0], {%1,%2,%3,%4};"
                 :: "l"(p), "f"(v.x), "f"(v.y), "f"(v.z), "f"(v.w) : "memory");
}

// ---------------- helper kernels ----------------

__global__ void zero_kernel() {
    const size_t M = (size_t)BB * NN * HH;
    size_t stride = (size_t)gridDim.x * blockDim.x;
    size_t i = (size_t)blockIdx.x * blockDim.x + threadIdx.x;
    for (size_t j = i; j < M; j += stride) {
        g_hm_sum[j] = 0.0f;
        g_pm_sum[j] = 0.0f;
    }
    if (i < NN) g_cnt[i] = 0;
}

__global__ void count_kernel(const int* __restrict__ recv_e) {
    int e = blockIdx.x * blockDim.x + threadIdx.x;
    if (e < EE) atomicAdd(&g_cnt[recv_e[e]], 1);
}

__global__ void prep_kernel(const float* __restrict__ mw1,
                            const float* __restrict__ mw2,
                            const float* __restrict__ pw1,
                            const float* __restrict__ pw2,
                            const float* __restrict__ res_w1,
                            const float* __restrict__ res_w2,
                            const float* __restrict__ ir_w,
                            const float* __restrict__ hr_w,
                            const float* __restrict__ ii_w,
                            const float* __restrict__ hi_w,
                            const float* __restrict__ in_w,
                            const float* __restrict__ hh_w,
                            const float* __restrict__ out_w1,
                            const float* __restrict__ out_w2,
                            const float* __restrict__ out_w3) {
    int i = blockIdx.x * blockDim.x + threadIdx.x;   // up to 32768
    if (i < 256 * 128) {
        int k = i >> 7, n = i & 127;
        g_w1p[k * 128 + ((n & 7) * 16 + (n >> 3))] = uif(rna(mw1[i]));
    }
    if (i < 128 * 128) {
        int k = i >> 7, n = i & 127;
        int s = k * 128 + ((n & 7) * 16 + (n >> 3));
        g_w2p[s]  = uif(rna(mw2[i]));
        g_pw2p[s] = uif(rna(pw2[i]));
        g_nw[0][s]  = uif(rna(res_w1[i]));
        g_nw[1][s]  = uif(rna(res_w2[i]));
        g_nw[2][s]  = uif(rna(ir_w[i]));
        g_nw[3][s]  = uif(rna(hr_w[i]));
        g_nw[4][s]  = uif(rna(ii_w[i]));
        g_nw[5][s]  = uif(rna(hi_w[i]));
        g_nw[6][s]  = uif(rna(in_w[i]));
        g_nw[7][s]  = uif(rna(hh_w[i]));
        g_nw[8][s]  = uif(rna(out_w1[i]));
        g_nw[9][s]  = uif(rna(out_w2[i]));
        g_nw[10][s] = uif(rna(out_w3[i]));
    }
    if (i < 144 * 128) {
        int k = i >> 7, n = i & 127;
        float v = (k < 140) ? pw1[i] : 0.0f;
        g_pw1p[k * 128 + ((n & 7) * 16 + (n >> 3))] = uif(rna(v));
    }
}

// ---------------- hm edge kernel (tf32 tensor cores) ----------------
#define HM_A_OFF 0
#define HM_B_OFF (128 * 36)
#define HM_M_OFF (HM_B_OFF + 32 * 132)
#define HM_SMEMF (HM_M_OFF + 128 * 132 + 256)

__global__ void __launch_bounds__(256) hm_kernel(
    const float* __restrict__ hidden,
    const int* __restrict__ send_e, const int* __restrict__ recv_e,
    const float* __restrict__ mb1, const float* __restrict__ mb2)
{
    extern __shared__ __align__(16) float sm[];
    int* s_recv = (int*)(sm + HM_M_OFF + 128 * 132);
    int* s_send = s_recv + 128;

    const int tid = threadIdx.x;
    const int b   = blockIdx.y;
    const int e0  = blockIdx.x * 128;

    if (tid < 128) s_recv[tid] = recv_e[e0 + tid];
    else           s_send[tid - 128] = send_e[e0 + tid - 128];

    const int warp = tid >> 5, lane = tid & 31;
    const int wm = warp >> 1, wn = warp & 1;
    const int m0 = wm * 32, n0 = wn * 64;
    const int g = lane >> 2, q = lane & 3;

    float acc[2][8][4];
    #pragma unroll
    for (int j = 0; j < 8; j++) {
        int c0 = n0 + 8 * j + 2 * q;
        float b0v = __ldg(mb1 + c0), b1v = __ldg(mb1 + c0 + 1);
        #pragma unroll
        for (int t = 0; t < 2; t++) {
            acc[t][j][0] = b0v; acc[t][j][1] = b1v;
            acc[t][j][2] = b0v; acc[t][j][3] = b1v;
        }
    }
    __syncthreads();

    const float* hb = hidden + (size_t)b * NN * HH;

    #pragma unroll 1
    for (int kc = 0; kc < 8; kc++) {
        if (kc) __syncthreads();
        const int* nidx = (kc < 4) ? s_recv : s_send;
        const int kk0 = (kc < 4) ? kc * 32 : kc * 32 - 128;
        #pragma unroll
        for (int i = 0; i < 4; i++) {
            int it = tid + i * 256;
            int e = it >> 3, v = it & 7;
            float4 f = *(const float4*)(hb + (size_t)nidx[e] * HH + kk0 + v * 4);
            uint4 r;
            r.x = rna(f.x); r.y = rna(f.y); r.z = rna(f.z); r.w = rna(f.w);
            *(uint4*)(sm + HM_A_OFF + e * 36 + v * 4) = r;
        }
        const float4* wsrc = (const float4*)g_w1p + kc * 32 * 32;
        #pragma unroll
        for (int i = 0; i < 4; i++) {
            int it = tid + i * 256;
            int r = it >> 5, c = it & 31;
            *(float4*)(sm + HM_B_OFF + r * 132 + c * 4) = wsrc[r * 32 + c];
        }
        __syncthreads();

        const unsigned* Au = (const unsigned*)(sm + HM_A_OFF);
        const float4*   B4 = (const float4*)(sm + HM_B_OFF);
        #pragma unroll
        for (int ks = 0; ks < 4; ks++) {
            int kr = ks * 8;
            int bb0 = (kr + q) * 33 + g * 4 + wn * 2;
            int bb1 = (kr + q + 4) * 33 + g * 4 + wn * 2;
            float4 u0 = B4[bb0], u1 = B4[bb0 + 1];
            float4 v0 = B4[bb1], v1 = B4[bb1 + 1];
            unsigned bu[8] = {__float_as_uint(u0.x), __float_as_uint(u0.y),
                              __float_as_uint(u0.z), __float_as_uint(u0.w),
                              __float_as_uint(u1.x), __float_as_uint(u1.y),
                              __float_as_uint(u1.z), __float_as_uint(u1.w)};
            unsigned bv[8] = {__float_as_uint(v0.x), __float_as_uint(v0.y),
                              __float_as_uint(v0.z), __float_as_uint(v0.w),
                              __float_as_uint(v1.x), __float_as_uint(v1.y),
                              __float_as_uint(v1.z), __float_as_uint(v1.w)};
            #pragma unroll
            for (int t = 0; t < 2; t++) {
                int r0 = (m0 + t * 16 + g) * 36 + kr + q;
                unsigned a0 = Au[r0], a1 = Au[r0 + 8 * 36];
                unsigned a2 = Au[r0 + 4], a3 = Au[r0 + 8 * 36 + 4];
                #pragma unroll
                for (int j = 0; j < 8; j++) mma8(acc[t][j], a0, a1, a2, a3, bu[j], bv[j]);
            }
        }
    }

    #pragma unroll
    for (int t = 0; t < 2; t++) {
        int r = m0 + t * 16 + g;
        #pragma unroll
        for (int j = 0; j < 8; j++) {
            int c0 = n0 + 8 * j + 2 * q;
            sm[HM_M_OFF + r * 132 + c0]           = uif(rna(tanhf(acc[t][j][0])));
            sm[HM_M_OFF + r * 132 + c0 + 1]       = uif(rna(tanhf(acc[t][j][1])));
            sm[HM_M_OFF + (r + 8) * 132 + c0]     = uif(rna(tanhf(acc[t][j][2])));
            sm[HM_M_OFF + (r + 8) * 132 + c0 + 1] = uif(rna(tanhf(acc[t][j][3])));
        }
    }

    float acc2[2][8][4];
    #pragma unroll
    for (int j = 0; j < 8; j++) {
        int c0 = n0 + 8 * j + 2 * q;
        float b0v = __ldg(mb2 + c0), b1v = __ldg(mb2 + c0 + 1);
        #pragma unroll
        for (int t = 0; t < 2; t++) {
            acc2[t][j][0] = b0v; acc2[t][j][1] = b1v;
            acc2[t][j][2] = b0v; acc2[t][j][3] = b1v;
        }
    }

    #pragma unroll 1
    for (int c2 = 0; c2 < 4; c2++) {
        __syncthreads();
        const float4* wsrc = (const float4*)g_w2p + c2 * 32 * 32;
        #pragma unroll
        for (int i = 0; i < 4; i++) {
            int it = tid + i * 256;
            int r = it >> 5, c = it & 31;
            *(float4*)(sm + HM_B_OFF + r * 132 + c * 4) = wsrc[r * 32 + c];
        }
        __syncthreads();

        const unsigned* Mu = (const unsigned*)(sm + HM_M_OFF);
        const float4*   B4 = (const float4*)(sm + HM_B_OFF);
        #pragma unroll
        for (int ks = 0; ks < 4; ks++) {
            int kr = ks * 8;
            int bb0 = (kr + q) * 33 + g * 4 + wn * 2;
            int bb1 = (kr + q + 4) * 33 + g * 4 + wn * 2;
            float4 u0 = B4[bb0], u1 = B4[bb0 + 1];
            float4 v0 = B4[bb1], v1 = B4[bb1 + 1];
            unsigned bu[8] = {__float_as_uint(u0.x), __float_as_uint(u0.y),
                              __float_as_uint(u0.z), __float_as_uint(u0.w),
                              __float_as_uint(u1.x), __float_as_uint(u1.y),
                              __float_as_uint(u1.z), __float_as_uint(u1.w)};
            unsigned bv[8] = {__float_as_uint(v0.x), __float_as_uint(v0.y),
                              __float_as_uint(v0.z), __float_as_uint(v0.w),
                              __float_as_uint(v1.x), __float_as_uint(v1.y),
                              __float_as_uint(v1.z), __float_as_uint(v1.w)};
            #pragma unroll
            for (int t = 0; t < 2; t++) {
                int r0 = (m0 + t * 16 + g) * 132 + c2 * 32 + kr + q;
                unsigned a0 = Mu[r0], a1 = Mu[r0 + 8 * 132];
                unsigned a2 = Mu[r0 + 4], a3 = Mu[r0 + 8 * 132 + 4];
                #pragma unroll
                for (int j = 0; j < 8; j++) mma8(acc2[t][j], a0, a1, a2, a3, bu[j], bv[j]);
            }
        }
    }

    __syncthreads();
    #pragma unroll
    for (int t = 0; t < 2; t++) {
        int r = m0 + t * 16 + g;
        #pragma unroll
        for (int j = 0; j < 8; j++) {
            int c0 = n0 + 8 * j + 2 * q;
            sm[HM_M_OFF + r * 132 + c0]           = tanhf(acc2[t][j][0]);
            sm[HM_M_OFF + r * 132 + c0 + 1]       = tanhf(acc2[t][j][1]);
            sm[HM_M_OFF + (r + 8) * 132 + c0]     = tanhf(acc2[t][j][2]);
            sm[HM_M_OFF + (r + 8) * 132 + c0 + 1] = tanhf(acc2[t][j][3]);
        }
    }
    __syncthreads();

    // vectorized coalesced scatter: red.global.add.v4.f32
    float* dst = g_hm_sum + (size_t)b * NN * HH;
    const int c4 = tid & 31;
    #pragma unroll 1
    for (int e = tid >> 5; e < 128; e += 8) {
        float4 v = *(const float4*)(sm + HM_M_OFF + e * 132 + c4 * 4);
        red4(dst + (size_t)s_recv[e] * HH + c4 * 4, v);
    }
}

// ---------------- pm edge kernel (tf32) ----------------
#define PM_A_OFF 0
#define PM_B_OFF (128 * 52)
#define PM_M_OFF (PM_B_OFF + 48 * 132)
#define PM_SMEMF (PM_M_OFF + 128 * 132 + 128)

__global__ void __launch_bounds__(256) pm_kernel(
    const float* __restrict__ edge_attr,
    const int* __restrict__ recv_e,
    const float* __restrict__ pb1, const float* __restrict__ pb2)
{
    extern __shared__ __align__(16) float sm[];
    int* s_recv = (int*)(sm + PM_M_OFF + 128 * 132);

    const int tid = threadIdx.x;
    const int b   = blockIdx.y;
    const int e0  = blockIdx.x * 128;

    if (tid < 128) s_recv[tid] = recv_e[e0 + tid];

    const int warp = tid >> 5, lane = tid & 31;
    const int wm = warp >> 1, wn = warp & 1;
    const int m0 = wm * 32, n0 = wn * 64;
    const int g = lane >> 2, q = lane & 3;

    float acc[2][8][4];
    #pragma unroll
    for (int j = 0; j < 8; j++) {
        int c0 = n0 + 8 * j + 2 * q;
        float b0v = __ldg(pb1 + c0), b1v = __ldg(pb1 + c0 + 1);
        #pragma unroll
        for (int t = 0; t < 2; t++) {
            acc[t][j][0] = b0v; acc[t][j][1] = b1v;
            acc[t][j][2] = b0v; acc[t][j][3] = b1v;
        }
    }
    __syncthreads();

    const float* ea = edge_attr + ((size_t)b * EE + e0) * FF;

    #pragma unroll 1
    for (int kc = 0; kc < 3; kc++) {
        if (kc) __syncthreads();
        const int k0 = kc * 48;
        #pragma unroll
        for (int i = 0; i < 12; i++) {
            int it = tid + i * 256;
            int e = it / 24, c = it % 24;
            int f = k0 + c * 2;
            float2 v;
            if (f < FF) v = *(const float2*)(ea + (size_t)e * FF + f);
            else { v.x = 0.0f; v.y = 0.0f; }
            uint2 r; r.x = rna(v.x); r.y = rna(v.y);
            *(uint2*)(sm + PM_A_OFF + e * 52 + c * 2) = r;
        }
        const float4* wsrc = (const float4*)g_pw1p + k0 * 32;
        #pragma unroll
        for (int i = 0; i < 6; i++) {
            int it = tid + i * 256;
            int r = it >> 5, c = it & 31;
            *(float4*)(sm + PM_B_OFF + r * 132 + c * 4) = wsrc[r * 32 + c];
        }
        __syncthreads();

        const unsigned* Au = (const unsigned*)(sm + PM_A_OFF);
        const float4*   B4 = (const float4*)(sm + PM_B_OFF);
        #pragma unroll
        for (int ks = 0; ks < 6; ks++) {
            int kr = ks * 8;
            int bb0 = (kr + q) * 33 + g * 4 + wn * 2;
            int bb1 = (kr + q + 4) * 33 + g * 4 + wn * 2;
            float4 u0 = B4[bb0], u1 = B4[bb0 + 1];
            float4 v0 = B4[bb1], v1 = B4[bb1 + 1];
            unsigned bu[8] = {__float_as_uint(u0.x), __float_as_uint(u0.y),
                              __float_as_uint(u0.z), __float_as_uint(u0.w),
                              __float_as_uint(u1.x), __float_as_uint(u1.y),
                              __float_as_uint(u1.z), __float_as_uint(u1.w)};
            unsigned bv[8] = {__float_as_uint(v0.x), __float_as_uint(v0.y),
                              __float_as_uint(v0.z), __float_as_uint(v0.w),
                              __float_as_uint(v1.x), __float_as_uint(v1.y),
                              __float_as_uint(v1.z), __float_as_uint(v1.w)};
            #pragma unroll
            for (int t = 0; t < 2; t++) {
                int r0 = (m0 + t * 16 + g) * 52 + kr + q;
                unsigned a0 = Au[r0], a1 = Au[r0 + 8 * 52];
                unsigned a2 = Au[r0 + 4], a3 = Au[r0 + 8 * 52 + 4];
                #pragma unroll
                for (int j = 0; j < 8; j++) mma8(acc[t][j], a0, a1, a2, a3, bu[j], bv[j]);
            }
        }
    }

    #pragma unroll
    for (int t = 0; t < 2; t++) {
        int r = m0 + t * 16 + g;
        #pragma unroll
        for (int j = 0; j < 8; j++) {
            int c0 = n0 + 8 * j + 2 * q;
            sm[PM_M_OFF + r * 132 + c0]           = uif(rna(fmaxf(acc[t][j][0], 0.0f)));
            sm[PM_M_OFF + r * 132 + c0 + 1]       = uif(rna(fmaxf(acc[t][j][1], 0.0f)));
            sm[PM_M_OFF + (r + 8) * 132 + c0]     = uif(rna(fmaxf(acc[t][j][2], 0.0f)));
            sm[PM_M_OFF + (r + 8) * 132 + c0 + 1] = uif(rna(fmaxf(acc[t][j][3], 0.0f)));
        }
    }

    float acc2[2][8][4];
    #pragma unroll
    for (int j = 0; j < 8; j++) {
        int c0 = n0 + 8 * j + 2 * q;
        float b0v = __ldg(pb2 + c0), b1v = __ldg(pb2 + c0 + 1);
        #pragma unroll
        for (int t = 0; t < 2; t++) {
            acc2[t][j][0] = b0v; acc2[t][j][1] = b1v;
            acc2[t][j][2] = b0v; acc2[t][j][3] = b1v;
        }
    }

    #pragma unroll 1
    for (int c2 = 0; c2 < 4; c2++) {
        __syncthreads();
        const float4* wsrc = (const float4*)g_pw2p + c2 * 32 * 32;
        #pragma unroll
        for (int i = 0; i < 4; i++) {
            int it = tid + i * 256;
            int r = it >> 5, c = it & 31;
            *(float4*)(sm + PM_B_OFF + r * 132 + c * 4) = wsrc[r * 32 + c];
        }
        __syncthreads();

        const unsigned* Mu = (const unsigned*)(sm + PM_M_OFF);
        const float4*   B4 = (const float4*)(sm + PM_B_OFF);
        #pragma unroll
        for (int ks = 0; ks < 4; ks++) {
            int kr = ks * 8;
            int bb0 = (kr + q) * 33 + g * 4 + wn * 2;
            int bb1 = (kr + q + 4) * 33 + g * 4 + wn * 2;
            float4 u0 = B4[bb0], u1 = B4[bb0 + 1];
            float4 v0 = B4[bb1], v1 = B4[bb1 + 1];
            unsigned bu[8] = {__float_as_uint(u0.x), __float_as_uint(u0.y),
                              __float_as_uint(u0.z), __float_as_uint(u0.w),
                              __float_as_uint(u1.x), __float_as_uint(u1.y),
                              __float_as_uint(u1.z), __float_as_uint(u1.w)};
            unsigned bv[8] = {__float_as_uint(v0.x), __float_as_uint(v0.y),
                              __float_as_uint(v0.z), __float_as_uint(v0.w),
                              __float_as_uint(v1.x), __float_as_uint(v1.y),
                              __float_as_uint(v1.z), __float_as_uint(v1.w)};
            #pragma unroll
            for (int t = 0; t < 2; t++) {
                int r0 = (m0 + t * 16 + g) * 132 + c2 * 32 + kr + q;
                unsigned a0 = Mu[r0], a1 = Mu[r0 + 8 * 132];
                unsigned a2 = Mu[r0 + 4], a3 = Mu[r0 + 8 * 132 + 4];
                #pragma unroll
                for (int j = 0; j < 8; j++) mma8(acc2[t][j], a0, a1, a2, a3, bu[j], bv[j]);
            }
        }
    }

    __syncthreads();
    #pragma unroll
    for (int t = 0; t < 2; t++) {
        int r = m0 + t * 16 + g;
        #pragma unroll
        for (int j = 0; j < 8; j++) {
            int c0 = n0 + 8 * j + 2 * q;
            sm[PM_M_OFF + r * 132 + c0]           = fmaxf(acc2[t][j][0], 0.0f);
            sm[PM_M_OFF + r * 132 + c0 + 1]       = fmaxf(acc2[t][j][1], 0.0f);
            sm[PM_M_OFF + (r + 8) * 132 + c0]     = fmaxf(acc2[t][j][2], 0.0f);
            sm[PM_M_OFF + (r + 8) * 132 + c0 + 1] = fmaxf(acc2[t][j][3], 0.0f);
        }
    }
    __syncthreads();

    float* dst = g_pm_sum + (size_t)b * NN * HH;
    const int c4 = tid & 31;
    #pragma unroll 1
    for (int e = tid >> 5; e < 128; e += 8) {
        float4 v = *(const float4*)(sm + PM_M_OFF + e * 132 + c4 * 4);
        red4(dst + (size_t)s_recv[e] * HH + c4 * 4, v);
    }
}

// ---------------- node kernel (tf32 tensor cores) ----------------
// 128 rows per CTA. smem: s_pres[128*132] | s_hemb[128*132] | s_x[128*132] | s_B[32*132]
#define ND_PRES 0
#define ND_HEMB (128 * 132)
#define ND_X    (2 * 128 * 132)
#define ND_B    (3 * 128 * 132)
#define ND_SMEMF (ND_B + 32 * 132)

__device__ __forceinline__ void acc_init_n(float acc[2][8][4], const float* bias,
                                           int n0, int q) {
    #pragma unroll
    for (int j = 0; j < 8; j++) {
        float b0v = 0.0f, b1v = 0.0f;
        if (bias) {
            int c0 = n0 + 8 * j + 2 * q;
            b0v = __ldg(bias + c0); b1v = __ldg(bias + c0 + 1);
        }
        #pragma unroll
        for (int t = 0; t < 2; t++) {
            acc[t][j][0] = b0v; acc[t][j][1] = b1v;
            acc[t][j][2] = b0v; acc[t][j][3] = b1v;
        }
    }
}

// one K=128 GEMM pass: acc += A(smem, pitch 132, tf32 bits) @ Wg(permuted global)
__device__ __forceinline__ void gemm128(const float* As, const float* Wg, float* sB,
                                        float acc[2][8][4], int tid) {
    const int warp = tid >> 5, lane = tid & 31;
    const int wm = warp >> 1, wn = warp & 1;
    const int m0 = wm * 32;
    const int g = lane >> 2, q = lane & 3;

    #pragma unroll 1
    for (int c2 = 0; c2 < 4; c2++) {
        __syncthreads();
        const float4* wsrc = (const float4*)Wg + c2 * 32 * 32;
        #pragma unroll
        for (int i = 0; i < 4; i++) {
            int it = tid + i * 256;
            int r = it >> 5, c = it & 31;
            *(float4*)(sB + r * 132 + c * 4) = wsrc[r * 32 + c];
        }
        __syncthreads();

        const unsigned* Mu = (const unsigned*)As;
        const float4*   B4 = (const float4*)sB;
        #pragma unroll
        for (int ks = 0; ks < 4; ks++) {
            int kr = ks * 8;
            int bb0 = (kr + q) * 33 + g * 4 + wn * 2;
            int bb1 = (kr + q + 4) * 33 + g * 4 + wn * 2;
            float4 u0 = B4[bb0], u1 = B4[bb0 + 1];
            float4 v0 = B4[bb1], v1 = B4[bb1 + 1];
            unsigned bu[8] = {__float_as_uint(u0.x), __float_as_uint(u0.y),
                              __float_as_uint(u0.z), __float_as_uint(u0.w),
                              __float_as_uint(u1.x), __float_as_uint(u1.y),
                              __float_as_uint(u1.z), __float_as_uint(u1.w)};
            unsigned bv[8] = {__float_as_uint(v0.x), __float_as_uint(v0.y),
                              __float_as_uint(v0.z), __float_as_uint(v0.w),
                              __float_as_uint(v1.x), __float_as_uint(v1.y),
                              __float_as_uint(v1.z), __float_as_uint(v1.w)};
            #pragma unroll
            for (int t = 0; t < 2; t++) {
                int r0 = (m0 + t * 16 + g) * 132 + c2 * 32 + kr + q;
                unsigned a0 = Mu[r0], a1 = Mu[r0 + 8 * 132];
                unsigned a2 = Mu[r0 + 4], a3 = Mu[r0 + 8 * 132 + 4];
                #pragma unroll
                for (int j = 0; j < 8; j++) mma8(acc[t][j], a0, a1, a2, a3, bu[j], bv[j]);
            }
        }
    }
    __syncthreads();   // all reads of As/sB done before caller writes
}

__global__ void __launch_bounds__(256) node_kernel(
    const float* __restrict__ inputs,
    const float* __restrict__ hidden,
    const float* __restrict__ res_b1, const float* __restrict__ res_b2,
    const float* __restrict__ ir_b,   const float* __restrict__ ii_b,
    const float* __restrict__ in_b,
    const float* __restrict__ out_b1, const float* __restrict__ out_b2,
    const float* __restrict__ out_b3,
    float* __restrict__ out_pred,
    float* __restrict__ out_hidden)
{
    extern __shared__ __align__(16) float sm[];
    float* s_pres = sm + ND_PRES;
    float* s_hemb = sm + ND_HEMB;
    float* s_x    = sm + ND_X;
    float* s_B    = sm + ND_B;

    const int tid  = threadIdx.x;
    const int row0 = blockIdx.x * 128;

    // stage: hemb=rna(hm_mean), pres=pm_mean (raw), x=rna(inputs)
    #pragma unroll
    for (int i = 0; i < 16; i++) {
        int it = tid + i * 256;            // 0..4095
        int r = it >> 5, c4v = it & 31;
        size_t off = (size_t)(row0 + r) * HH + c4v * 4;
        float invc = 1.0f / fmaxf((float)__ldg(&g_cnt[(row0 + r) & (NN - 1)]), 1.0f);
        float4 hm4 = *(const float4*)(g_hm_sum + off);
        float4 pm4 = *(const float4*)(g_pm_sum + off);
        float4 in4 = *(const float4*)(inputs + off);
        uint4 a;
        a.x = rna(hm4.x * invc); a.y = rna(hm4.y * invc);
        a.z = rna(hm4.z * invc); a.w = rna(hm4.w * invc);
        *(uint4*)(s_hemb + r * 132 + c4v * 4) = a;
        float4 p;
        p.x = pm4.x * invc; p.y = pm4.y * invc; p.z = pm4.z * invc; p.w = pm4.w * invc;
        *(float4*)(s_pres + r * 132 + c4v * 4) = p;
        uint4 x;
        x.x = rna(in4.x); x.y = rna(in4.y); x.z = rna(in4.z); x.w = rna(in4.w);
        *(uint4*)(s_x + r * 132 + c4v * 4) = x;
    }
    // gemm128 begins with __syncthreads(): staging visible.

    const int warp = tid >> 5, lane = tid & 31;
    const int wm = warp >> 1, wn = warp & 1;
    const int m0 = wm * 32, n0 = wn * 64;
    const int g = lane >> 2, q = lane & 3;

    float acc[2][8][4];

    // fragment coordinate helpers (variadic: bodies may contain commas)
    #define FRAG_LOOP(...)                                               \
        _Pragma("unroll")                                                \
        for (int t = 0; t < 2; t++) {                                    \
            int r_ = m0 + t * 16 + g;                                    \
            _Pragma("unroll")                                            \
            for (int j = 0; j < 8; j++) {                                \
                int c0 = n0 + 8 * j + 2 * q;                             \
                int i0 = r_ * 132 + c0;                                  \
                int i2 = (r_ + 8) * 132 + c0;                            \
                (void)i0; (void)i2;                                      \
                __VA_ARGS__                                              \
            }                                                            \
        }

    // 1) res1 = relu(x @ res_w1 + b) -> s_x (in place; gemm's trailing sync protects)
    acc_init_n(acc, res_b1, n0, q);
    gemm128(s_x, g_nw[0], s_B, acc, tid);
    FRAG_LOOP({
        s_x[i0]     = uif(rna(fmaxf(acc[t][j][0], 0.0f)));
        s_x[i0 + 1] = uif(rna(fmaxf(acc[t][j][1], 0.0f)));
        s_x[i2]     = uif(rna(fmaxf(acc[t][j][2], 0.0f)));
        s_x[i2 + 1] = uif(rna(fmaxf(acc[t][j][3], 0.0f)));
    })

    // 2) pres = relu(res1 @ res_w2 + b) + pm_mean -> s_pres
    acc_init_n(acc, res_b2, n0, q);
    gemm128(s_x, g_nw[1], s_B, acc, tid);
    FRAG_LOOP({
        s_pres[i0]     = uif(rna(fmaxf(acc[t][j][0], 0.0f) + s_pres[i0]));
        s_pres[i0 + 1] = uif(rna(fmaxf(acc[t][j][1], 0.0f) + s_pres[i0 + 1]));
        s_pres[i2]     = uif(rna(fmaxf(acc[t][j][2], 0.0f) + s_pres[i2]));
        s_pres[i2 + 1] = uif(rna(fmaxf(acc[t][j][3], 0.0f) + s_pres[i2 + 1]));
    })

    // 3) hh = hemb @ hh_w -> s_x (raw)
    acc_init_n(acc, nullptr, n0, q);
    gemm128(s_hemb, g_nw[7], s_B, acc, tid);
    FRAG_LOOP({
        s_x[i0]     = acc[t][j][0];
        s_x[i0 + 1] = acc[t][j][1];
        s_x[i2]     = acc[t][j][2];
        s_x[i2 + 1] = acc[t][j][3];
    })

    // 4) r = sigmoid(pres@ir_w + ir_b + hemb@hr_w); s_x <- r * hh
    acc_init_n(acc, ir_b, n0, q);
    gemm128(s_pres, g_nw[2], s_B, acc, tid);
    gemm128(s_hemb, g_nw[3], s_B, acc, tid);
    FRAG_LOOP({
        s_x[i0]     = sigmoidf_(acc[t][j][0]) * s_x[i0];
        s_x[i0 + 1] = sigmoidf_(acc[t][j][1]) * s_x[i0 + 1];
        s_x[i2]     = sigmoidf_(acc[t][j][2]) * s_x[i2];
        s_x[i2 + 1] = sigmoidf_(acc[t][j][3]) * s_x[i2 + 1];
    })

    // 5) i = sigmoid(pres@ii_w + ii_b + hemb@hi_w) -> s_hemb (hemb dead after this)
    acc_init_n(acc, ii_b, n0, q);
    gemm128(s_pres, g_nw[4], s_B, acc, tid);
    gemm128(s_hemb, g_nw[5], s_B, acc, tid);
    FRAG_LOOP({
        s_hemb[i0]     = sigmoidf_(acc[t][j][0]);
        s_hemb[i0 + 1] = sigmoidf_(acc[t][j][1]);
        s_hemb[i2]     = sigmoidf_(acc[t][j][2]);
        s_hemb[i2 + 1] = sigmoidf_(acc[t][j][3]);
    })

    // 6) n = tanh(pres@in_w + in_b + r*hh); new_h = (1-i)*n + i*hidden
    acc_init_n(acc, in_b, n0, q);
    gemm128(s_pres, g_nw[6], s_B, acc, tid);
    FRAG_LOOP({
        float n_0 = tanhf(acc[t][j][0] + s_x[i0]);
        float n_1 = tanhf(acc[t][j][1] + s_x[i0 + 1]);
        float n_2 = tanhf(acc[t][j][2] + s_x[i2]);
        float n_3 = tanhf(acc[t][j][3] + s_x[i2 + 1]);
        float i_0 = s_hemb[i0];
        float i_1 = s_hemb[i0 + 1];
        float i_2 = s_hemb[i2];
        float i_3 = s_hemb[i2 + 1];
        size_t go0 = (size_t)(row0 + r_) * HH + c0;
        size_t go2 = (size_t)(row0 + r_ + 8) * HH + c0;
        float2 h0 = *(const float2*)(hidden + go0);
        float2 h2 = *(const float2*)(hidden + go2);
        float2 nh0;
        float2 nh2;
        nh0.x = (1.0f - i_0) * n_0 + i_0 * h0.x;
        nh0.y = (1.0f - i_1) * n_1 + i_1 * h0.y;
        nh2.x = (1.0f - i_2) * n_2 + i_2 * h2.x;
        nh2.y = (1.0f - i_3) * n_3 + i_3 * h2.y;
        *(float2*)(out_hidden + go0) = nh0;
        *(float2*)(out_hidden + go2) = nh2;
        s_x[i0]     = uif(rna(nh0.x));
        s_x[i0 + 1] = uif(rna(nh0.y));
        s_x[i2]     = uif(rna(nh2.x));
        s_x[i2 + 1] = uif(rna(nh2.y));
    })

    // 7) o1 = relu(new_h @ out_w1 + b) -> s_hemb
    acc_init_n(acc, out_b1, n0, q);
    gemm128(s_x, g_nw[8], s_B, acc, tid);
    FRAG_LOOP({
        s_hemb[i0]     = uif(rna(fmaxf(acc[t][j][0], 0.0f)));
        s_hemb[i0 + 1] = uif(rna(fmaxf(acc[t][j][1], 0.0f)));
        s_hemb[i2]     = uif(rna(fmaxf(acc[t][j][2], 0.0f)));
        s_hemb[i2 + 1] = uif(rna(fmaxf(acc[t][j][3], 0.0f)));
    })

    // 8) o2 = relu(o1 @ out_w2 + b) -> s_x
    acc_init_n(acc, out_b2, n0, q);
    gemm128(s_hemb, g_nw[9], s_B, acc, tid);
    FRAG_LOOP({
        s_x[i0]     = uif(rna(fmaxf(acc[t][j][0], 0.0f)));
        s_x[i0 + 1] = uif(rna(fmaxf(acc[t][j][1], 0.0f)));
        s_x[i2]     = uif(rna(fmaxf(acc[t][j][2], 0.0f)));
        s_x[i2 + 1] = uif(rna(fmaxf(acc[t][j][3], 0.0f)));
    })

    // 9) pred = o2 @ out_w3 + b -> global
    acc_init_n(acc, out_b3, n0, q);
    gemm128(s_x, g_nw[10], s_B, acc, tid);
    FRAG_LOOP({
        size_t go0 = (size_t)(row0 + r_) * II + c0;
        size_t go2 = (size_t)(row0 + r_ + 8) * II + c0;
        float2 p0;
        float2 p2;
        p0.x = acc[t][j][0]; p0.y = acc[t][j][1];
        p2.x = acc[t][j][2]; p2.y = acc[t][j][3];
        *(float2*)(out_pred + go0) = p0;
        *(float2*)(out_pred + go2) = p2;
    })
    #undef FRAG_LOOP
}

// ---------------- launch ----------------
extern "C" void kernel_launch(void* const* d_in, const int* in_sizes, int n_in,
                              void* d_out, int out_size) {
    const float* inputs    = (const float*)d_in[0];
    const float* edge_attr = (const float*)d_in[1];
    const int*   send_e    = (const int*)  d_in[2];
    const int*   recv_e    = (const int*)  d_in[3];
    const float* hidden    = (const float*)d_in[4];
    const float* msg_w1 = (const float*)d_in[5];
    const float* msg_b1 = (const float*)d_in[6];
    const float* msg_w2 = (const float*)d_in[7];
    const float* msg_b2 = (const float*)d_in[8];
    const float* pm_w1  = (const float*)d_in[9];
    const float* pm_b1  = (const float*)d_in[10];
    const float* pm_w2  = (const float*)d_in[11];
    const float* pm_b2  = (const float*)d_in[12];
    const float* res_w1 = (const float*)d_in[13];
    const float* res_b1 = (const float*)d_in[14];
    const float* res_w2 = (const float*)d_in[15];
    const float* res_b2 = (const float*)d_in[16];
    const float* ir_w   = (const float*)d_in[17];
    const float* ir_b   = (const float*)d_in[18];
    const float* ii_w   = (const float*)d_in[19];
    const float* ii_b   = (const float*)d_in[20];
    const float* in_w   = (const float*)d_in[21];
    const float* in_b   = (const float*)d_in[22];
    const float* hr_w   = (const float*)d_in[23];
    const float* hi_w   = (const float*)d_in[24];
    const float* hh_w   = (const float*)d_in[25];
    const float* out_w1 = (const float*)d_in[26];
    const float* out_b1 = (const float*)d_in[27];
    const float* out_w2 = (const float*)d_in[28];
    const float* out_b2 = (const float*)d_in[29];
    const float* out_w3 = (const float*)d_in[30];
    const float* out_b3 = (const float*)d_in[31];

    float* out_pred   = (float*)d_out;
    float* out_hidden = (float*)d_out + (size_t)BB * NN * II;

    const int HM_SMEM = HM_SMEMF * 4;
    const int PM_SMEM = PM_SMEMF * 4;
    const int ND_SMEM = ND_SMEMF * 4;     // 219,648 B
    cudaFuncSetAttribute(hm_kernel, cudaFuncAttributeMaxDynamicSharedMemorySize, HM_SMEM);
    cudaFuncSetAttribute(pm_kernel, cudaFuncAttributeMaxDynamicSharedMemorySize, PM_SMEM);
    cudaFuncSetAttribute(node_kernel, cudaFuncAttributeMaxDynamicSharedMemorySize, ND_SMEM);

    zero_kernel<<<1024, 256>>>();
    count_kernel<<<EE / 256, 256>>>(recv_e);
    prep_kernel<<<128, 256>>>(msg_w1, msg_w2, pm_w1, pm_w2,
                              res_w1, res_w2, ir_w, hr_w, ii_w, hi_w,
                              in_w, hh_w, out_w1, out_w2, out_w3);

    hm_kernel<<<dim3(EE / 128, BB), 256, HM_SMEM>>>(hidden, send_e, recv_e, msg_b1, msg_b2);
    pm_kernel<<<dim3(EE / 128, BB), 256, PM_SMEM>>>(edge_attr, recv_e, pm_b1, pm_b2);

    node_kernel<<<(BB * NN) / 128, 256, ND_SMEM>>>(
        inputs, hidden,
        res_b1, res_b2, ir_b, ii_b, in_b,
        out_b1, out_b2, out_b3,
        out_pred, out_hidden);
}

// round 11
// speedup vs baseline: 3.6806x; 1.3541x over previous
#include <cuda_runtime.h>
#include <math.h>
#include <stdint.h>

// Problem constants
#define BB 4
#define NN 4096
#define EE 131072
#define II 128
#define HH 128
#define FF 140

// ---------------- scratch (__device__ globals; no allocs allowed) ----------
__device__ float g_hm_sum[(size_t)BB * NN * HH];   // 8 MB
__device__ float g_pm_sum[(size_t)BB * NN * HH];   // 8 MB
__device__ int   g_cnt[NN];

// permuted tf32-rounded weights: w[k][ (n%8)*16 + n/8 ]
__device__ float g_w1p[256 * 128];
__device__ float g_w2p[128 * 128];
__device__ float g_pw1p[160 * 128];   // K padded 140 -> 160 with zeros
__device__ float g_pw2p[128 * 128];
// node weights, same permutation: order
// 0:res_w1 1:res_w2 2:ir_w 3:hr_w 4:ii_w 5:hi_w 6:in_w 7:hh_w 8:out_w1 9:out_w2 10:out_w3
__device__ float g_nw[11][128 * 128];

__device__ __forceinline__ float sigmoidf_(float x) {
    return 1.0f / (1.0f + expf(-x));
}

__device__ __forceinline__ unsigned rna(float x) {
    unsigned r;
    asm("cvt.rna.tf32.f32 %0, %1;" : "=r"(r) : "f"(x));
    return r;
}
__device__ __forceinline__ float uif(unsigned x) { return __uint_as_float(x); }

__device__ __forceinline__ void mma8(float* c,
                                     unsigned a0, unsigned a1, unsigned a2, unsigned a3,
                                     unsigned b0, unsigned b1) {
    asm volatile(
        "mma.sync.aligned.m16n8k8.row.col.f32.tf32.tf32.f32 "
        "{%0,%1,%2,%3}, {%4,%5,%6,%7}, {%8,%9}, {%0,%1,%2,%3};"
        : "+f"(c[0]), "+f"(c[1]), "+f"(c[2]), "+f"(c[3])
        : "r"(a0), "r"(a1), "r"(a2), "r"(a3), "r"(b0), "r"(b1));
}

__device__ __forceinline__ void red4(float* p, float4 v) {
    asm volatile("red.global.add.v4.f32 [%0], {%1,%2,%3,%4};"
                 :: "l"(p), "f"(v.x), "f"(v.y), "f"(v.z), "f"(v.w) : "memory");
}

// ---------------- helper kernels ----------------

__global__ void zero_kernel() {
    const size_t M = (size_t)BB * NN * HH;
    size_t stride = (size_t)gridDim.x * blockDim.x;
    size_t i = (size_t)blockIdx.x * blockDim.x + threadIdx.x;
    for (size_t j = i; j < M; j += stride) {
        g_hm_sum[j] = 0.0f;
        g_pm_sum[j] = 0.0f;
    }
    if (i < NN) g_cnt[i] = 0;
}

__global__ void count_kernel(const int* __restrict__ recv_e) {
    int e = blockIdx.x * blockDim.x + threadIdx.x;
    if (e < EE) atomicAdd(&g_cnt[recv_e[e]], 1);
}

__global__ void prep_kernel(const float* __restrict__ mw1,
                            const float* __restrict__ mw2,
                            const float* __restrict__ pw1,
                            const float* __restrict__ pw2,
                            const float* __restrict__ res_w1,
                            const float* __restrict__ res_w2,
                            const float* __restrict__ ir_w,
                            const float* __restrict__ hr_w,
                            const float* __restrict__ ii_w,
                            const float* __restrict__ hi_w,
                            const float* __restrict__ in_w,
                            const float* __restrict__ hh_w,
                            const float* __restrict__ out_w1,
                            const float* __restrict__ out_w2,
                            const float* __restrict__ out_w3) {
    int i = blockIdx.x * blockDim.x + threadIdx.x;   // up to 32768
    if (i < 256 * 128) {
        int k = i >> 7, n = i & 127;
        g_w1p[k * 128 + ((n & 7) * 16 + (n >> 3))] = uif(rna(mw1[i]));
    }
    if (i < 128 * 128) {
        int k = i >> 7, n = i & 127;
        int s = k * 128 + ((n & 7) * 16 + (n >> 3));
        g_w2p[s]  = uif(rna(mw2[i]));
        g_pw2p[s] = uif(rna(pw2[i]));
        g_nw[0][s]  = uif(rna(res_w1[i]));
        g_nw[1][s]  = uif(rna(res_w2[i]));
        g_nw[2][s]  = uif(rna(ir_w[i]));
        g_nw[3][s]  = uif(rna(hr_w[i]));
        g_nw[4][s]  = uif(rna(ii_w[i]));
        g_nw[5][s]  = uif(rna(hi_w[i]));
        g_nw[6][s]  = uif(rna(in_w[i]));
        g_nw[7][s]  = uif(rna(hh_w[i]));
        g_nw[8][s]  = uif(rna(out_w1[i]));
        g_nw[9][s]  = uif(rna(out_w2[i]));
        g_nw[10][s] = uif(rna(out_w3[i]));
    }
    if (i < 160 * 128) {
        int k = i >> 7, n = i & 127;
        float v = (k < 140) ? pw1[i] : 0.0f;
        g_pw1p[k * 128 + ((n & 7) * 16 + (n >> 3))] = uif(rna(v));
    }
}

// ---------------- hm edge kernel (tf32 tensor cores) ----------------
// smem floats: Ac[128][36] | Bc[32][132] | mid[128][132] | idx[256]  = 103,936 B
#define HM_A_OFF 0
#define HM_B_OFF (128 * 36)
#define HM_M_OFF (HM_B_OFF + 32 * 132)
#define HM_SMEMF (HM_M_OFF + 128 * 132 + 256)

__global__ void __launch_bounds__(256, 2) hm_kernel(
    const float* __restrict__ hidden,
    const int* __restrict__ send_e, const int* __restrict__ recv_e,
    const float* __restrict__ mb1, const float* __restrict__ mb2)
{
    extern __shared__ __align__(16) float sm[];
    int* s_recv = (int*)(sm + HM_M_OFF + 128 * 132);
    int* s_send = s_recv + 128;

    const int tid = threadIdx.x;
    const int b   = blockIdx.y;
    const int e0  = blockIdx.x * 128;

    if (tid < 128) s_recv[tid] = recv_e[e0 + tid];
    else           s_send[tid - 128] = send_e[e0 + tid - 128];

    const int warp = tid >> 5, lane = tid & 31;
    const int wm = warp >> 1, wn = warp & 1;
    const int m0 = wm * 32, n0 = wn * 64;
    const int g = lane >> 2, q = lane & 3;

    float acc[2][8][4];
    #pragma unroll
    for (int j = 0; j < 8; j++) {
        int c0 = n0 + 8 * j + 2 * q;
        float b0v = __ldg(mb1 + c0), b1v = __ldg(mb1 + c0 + 1);
        #pragma unroll
        for (int t = 0; t < 2; t++) {
            acc[t][j][0] = b0v; acc[t][j][1] = b1v;
            acc[t][j][2] = b0v; acc[t][j][3] = b1v;
        }
    }
    __syncthreads();

    const float* hb = hidden + (size_t)b * NN * HH;

    #pragma unroll 1
    for (int kc = 0; kc < 8; kc++) {
        if (kc) __syncthreads();
        const int* nidx = (kc < 4) ? s_recv : s_send;
        const int kk0 = (kc < 4) ? kc * 32 : kc * 32 - 128;
        #pragma unroll
        for (int i = 0; i < 4; i++) {
            int it = tid + i * 256;
            int e = it >> 3, v = it & 7;
            float4 f = *(const float4*)(hb + (size_t)nidx[e] * HH + kk0 + v * 4);
            uint4 r;
            r.x = rna(f.x); r.y = rna(f.y); r.z = rna(f.z); r.w = rna(f.w);
            *(uint4*)(sm + HM_A_OFF + e * 36 + v * 4) = r;
        }
        const float4* wsrc = (const float4*)g_w1p + kc * 32 * 32;
        #pragma unroll
        for (int i = 0; i < 4; i++) {
            int it = tid + i * 256;
            int r = it >> 5, c = it & 31;
            *(float4*)(sm + HM_B_OFF + r * 132 + c * 4) = wsrc[r * 32 + c];
        }
        __syncthreads();

        const unsigned* Au = (const unsigned*)(sm + HM_A_OFF);
        const float4*   B4 = (const float4*)(sm + HM_B_OFF);
        #pragma unroll
        for (int ks = 0; ks < 4; ks++) {
            int kr = ks * 8;
            int bb0 = (kr + q) * 33 + g * 4 + wn * 2;
            int bb1 = (kr + q + 4) * 33 + g * 4 + wn * 2;
            float4 u0 = B4[bb0], u1 = B4[bb0 + 1];
            float4 v0 = B4[bb1], v1 = B4[bb1 + 1];
            unsigned bu[8] = {__float_as_uint(u0.x), __float_as_uint(u0.y),
                              __float_as_uint(u0.z), __float_as_uint(u0.w),
                              __float_as_uint(u1.x), __float_as_uint(u1.y),
                              __float_as_uint(u1.z), __float_as_uint(u1.w)};
            unsigned bv[8] = {__float_as_uint(v0.x), __float_as_uint(v0.y),
                              __float_as_uint(v0.z), __float_as_uint(v0.w),
                              __float_as_uint(v1.x), __float_as_uint(v1.y),
                              __float_as_uint(v1.z), __float_as_uint(v1.w)};
            #pragma unroll
            for (int t = 0; t < 2; t++) {
                int r0 = (m0 + t * 16 + g) * 36 + kr + q;
                unsigned a0 = Au[r0], a1 = Au[r0 + 8 * 36];
                unsigned a2 = Au[r0 + 4], a3 = Au[r0 + 8 * 36 + 4];
                #pragma unroll
                for (int j = 0; j < 8; j++) mma8(acc[t][j], a0, a1, a2, a3, bu[j], bv[j]);
            }
        }
    }

    #pragma unroll
    for (int t = 0; t < 2; t++) {
        int r = m0 + t * 16 + g;
        #pragma unroll
        for (int j = 0; j < 8; j++) {
            int c0 = n0 + 8 * j + 2 * q;
            sm[HM_M_OFF + r * 132 + c0]           = uif(rna(tanhf(acc[t][j][0])));
            sm[HM_M_OFF + r * 132 + c0 + 1]       = uif(rna(tanhf(acc[t][j][1])));
            sm[HM_M_OFF + (r + 8) * 132 + c0]     = uif(rna(tanhf(acc[t][j][2])));
            sm[HM_M_OFF + (r + 8) * 132 + c0 + 1] = uif(rna(tanhf(acc[t][j][3])));
        }
    }

    float acc2[2][8][4];
    #pragma unroll
    for (int j = 0; j < 8; j++) {
        int c0 = n0 + 8 * j + 2 * q;
        float b0v = __ldg(mb2 + c0), b1v = __ldg(mb2 + c0 + 1);
        #pragma unroll
        for (int t = 0; t < 2; t++) {
            acc2[t][j][0] = b0v; acc2[t][j][1] = b1v;
            acc2[t][j][2] = b0v; acc2[t][j][3] = b1v;
        }
    }

    #pragma unroll 1
    for (int c2 = 0; c2 < 4; c2++) {
        __syncthreads();
        const float4* wsrc = (const float4*)g_w2p + c2 * 32 * 32;
        #pragma unroll
        for (int i = 0; i < 4; i++) {
            int it = tid + i * 256;
            int r = it >> 5, c = it & 31;
            *(float4*)(sm + HM_B_OFF + r * 132 + c * 4) = wsrc[r * 32 + c];
        }
        __syncthreads();

        const unsigned* Mu = (const unsigned*)(sm + HM_M_OFF);
        const float4*   B4 = (const float4*)(sm + HM_B_OFF);
        #pragma unroll
        for (int ks = 0; ks < 4; ks++) {
            int kr = ks * 8;
            int bb0 = (kr + q) * 33 + g * 4 + wn * 2;
            int bb1 = (kr + q + 4) * 33 + g * 4 + wn * 2;
            float4 u0 = B4[bb0], u1 = B4[bb0 + 1];
            float4 v0 = B4[bb1], v1 = B4[bb1 + 1];
            unsigned bu[8] = {__float_as_uint(u0.x), __float_as_uint(u0.y),
                              __float_as_uint(u0.z), __float_as_uint(u0.w),
                              __float_as_uint(u1.x), __float_as_uint(u1.y),
                              __float_as_uint(u1.z), __float_as_uint(u1.w)};
            unsigned bv[8] = {__float_as_uint(v0.x), __float_as_uint(v0.y),
                              __float_as_uint(v0.z), __float_as_uint(v0.w),
                              __float_as_uint(v1.x), __float_as_uint(v1.y),
                              __float_as_uint(v1.z), __float_as_uint(v1.w)};
            #pragma unroll
            for (int t = 0; t < 2; t++) {
                int r0 = (m0 + t * 16 + g) * 132 + c2 * 32 + kr + q;
                unsigned a0 = Mu[r0], a1 = Mu[r0 + 8 * 132];
                unsigned a2 = Mu[r0 + 4], a3 = Mu[r0 + 8 * 132 + 4];
                #pragma unroll
                for (int j = 0; j < 8; j++) mma8(acc2[t][j], a0, a1, a2, a3, bu[j], bv[j]);
            }
        }
    }

    __syncthreads();
    #pragma unroll
    for (int t = 0; t < 2; t++) {
        int r = m0 + t * 16 + g;
        #pragma unroll
        for (int j = 0; j < 8; j++) {
            int c0 = n0 + 8 * j + 2 * q;
            sm[HM_M_OFF + r * 132 + c0]           = tanhf(acc2[t][j][0]);
            sm[HM_M_OFF + r * 132 + c0 + 1]       = tanhf(acc2[t][j][1]);
            sm[HM_M_OFF + (r + 8) * 132 + c0]     = tanhf(acc2[t][j][2]);
            sm[HM_M_OFF + (r + 8) * 132 + c0 + 1] = tanhf(acc2[t][j][3]);
        }
    }
    __syncthreads();

    // vectorized coalesced scatter: red.global.add.v4.f32
    float* dst = g_hm_sum + (size_t)b * NN * HH;
    const int c4 = tid & 31;
    #pragma unroll 1
    for (int e = tid >> 5; e < 128; e += 8) {
        float4 v = *(const float4*)(sm + HM_M_OFF + e * 132 + c4 * 4);
        red4(dst + (size_t)s_recv[e] * HH + c4 * 4, v);
    }
}

// ---------------- pm edge kernel (tf32) ----------------
// layer 1: K padded 140 -> 160, 5 chunks of 32, A-pitch 36 (same layout as hm).
// smem floats: Ac[128][36] | Bc[32][132] | mid[128][132] | idx[128] = 103,424 B
#define PM_A_OFF 0
#define PM_B_OFF (128 * 36)
#define PM_M_OFF (PM_B_OFF + 32 * 132)
#define PM_SMEMF (PM_M_OFF + 128 * 132 + 128)

__global__ void __launch_bounds__(256, 2) pm_kernel(
    const float* __restrict__ edge_attr,
    const int* __restrict__ recv_e,
    const float* __restrict__ pb1, const float* __restrict__ pb2)
{
    extern __shared__ __align__(16) float sm[];
    int* s_recv = (int*)(sm + PM_M_OFF + 128 * 132);

    const int tid = threadIdx.x;
    const int b   = blockIdx.y;
    const int e0  = blockIdx.x * 128;

    if (tid < 128) s_recv[tid] = recv_e[e0 + tid];

    const int warp = tid >> 5, lane = tid & 31;
    const int wm = warp >> 1, wn = warp & 1;
    const int m0 = wm * 32, n0 = wn * 64;
    const int g = lane >> 2, q = lane & 3;

    float acc[2][8][4];
    #pragma unroll
    for (int j = 0; j < 8; j++) {
        int c0 = n0 + 8 * j + 2 * q;
        float b0v = __ldg(pb1 + c0), b1v = __ldg(pb1 + c0 + 1);
        #pragma unroll
        for (int t = 0; t < 2; t++) {
            acc[t][j][0] = b0v; acc[t][j][1] = b1v;
            acc[t][j][2] = b0v; acc[t][j][3] = b1v;
        }
    }
    __syncthreads();

    const float* ea = edge_attr + ((size_t)b * EE + e0) * FF;

    // ---------------- layer 1: 5 chunks of 32 (K padded to 160) ----------------
    #pragma unroll 1
    for (int kc = 0; kc < 5; kc++) {
        if (kc) __syncthreads();
        const int k0 = kc * 32;
        #pragma unroll
        for (int i = 0; i < 4; i++) {
            int it = tid + i * 256;              // 0..1023
            int e = it >> 3, v = it & 7;
            int f = k0 + v * 4;
            float4 fv;
            if (f < FF) fv = *(const float4*)(ea + (size_t)e * FF + f);   // FF%4==0
            else { fv.x = 0.0f; fv.y = 0.0f; fv.z = 0.0f; fv.w = 0.0f; }
            uint4 r;
            r.x = rna(fv.x); r.y = rna(fv.y); r.z = rna(fv.z); r.w = rna(fv.w);
            *(uint4*)(sm + PM_A_OFF + e * 36 + v * 4) = r;
        }
        const float4* wsrc = (const float4*)g_pw1p + kc * 32 * 32;
        #pragma unroll
        for (int i = 0; i < 4; i++) {
            int it = tid + i * 256;
            int r = it >> 5, c = it & 31;
            *(float4*)(sm + PM_B_OFF + r * 132 + c * 4) = wsrc[r * 32 + c];
        }
        __syncthreads();

        const unsigned* Au = (const unsigned*)(sm + PM_A_OFF);
        const float4*   B4 = (const float4*)(sm + PM_B_OFF);
        #pragma unroll
        for (int ks = 0; ks < 4; ks++) {
            int kr = ks * 8;
            int bb0 = (kr + q) * 33 + g * 4 + wn * 2;
            int bb1 = (kr + q + 4) * 33 + g * 4 + wn * 2;
            float4 u0 = B4[bb0], u1 = B4[bb0 + 1];
            float4 v0 = B4[bb1], v1 = B4[bb1 + 1];
            unsigned bu[8] = {__float_as_uint(u0.x), __float_as_uint(u0.y),
                              __float_as_uint(u0.z), __float_as_uint(u0.w),
                              __float_as_uint(u1.x), __float_as_uint(u1.y),
                              __float_as_uint(u1.z), __float_as_uint(u1.w)};
            unsigned bv[8] = {__float_as_uint(v0.x), __float_as_uint(v0.y),
                              __float_as_uint(v0.z), __float_as_uint(v0.w),
                              __float_as_uint(v1.x), __float_as_uint(v1.y),
                              __float_as_uint(v1.z), __float_as_uint(v1.w)};
            #pragma unroll
            for (int t = 0; t < 2; t++) {
                int r0 = (m0 + t * 16 + g) * 36 + kr + q;
                unsigned a0 = Au[r0], a1 = Au[r0 + 8 * 36];
                unsigned a2 = Au[r0 + 4], a3 = Au[r0 + 8 * 36 + 4];
                #pragma unroll
                for (int j = 0; j < 8; j++) mma8(acc[t][j], a0, a1, a2, a3, bu[j], bv[j]);
            }
        }
    }

    #pragma unroll
    for (int t = 0; t < 2; t++) {
        int r = m0 + t * 16 + g;
        #pragma unroll
        for (int j = 0; j < 8; j++) {
            int c0 = n0 + 8 * j + 2 * q;
            sm[PM_M_OFF + r * 132 + c0]           = uif(rna(fmaxf(acc[t][j][0], 0.0f)));
            sm[PM_M_OFF + r * 132 + c0 + 1]       = uif(rna(fmaxf(acc[t][j][1], 0.0f)));
            sm[PM_M_OFF + (r + 8) * 132 + c0]     = uif(rna(fmaxf(acc[t][j][2], 0.0f)));
            sm[PM_M_OFF + (r + 8) * 132 + c0 + 1] = uif(rna(fmaxf(acc[t][j][3], 0.0f)));
        }
    }

    float acc2[2][8][4];
    #pragma unroll
    for (int j = 0; j < 8; j++) {
        int c0 = n0 + 8 * j + 2 * q;
        float b0v = __ldg(pb2 + c0), b1v = __ldg(pb2 + c0 + 1);
        #pragma unroll
        for (int t = 0; t < 2; t++) {
            acc2[t][j][0] = b0v; acc2[t][j][1] = b1v;
            acc2[t][j][2] = b0v; acc2[t][j][3] = b1v;
        }
    }

    #pragma unroll 1
    for (int c2 = 0; c2 < 4; c2++) {
        __syncthreads();
        const float4* wsrc = (const float4*)g_pw2p + c2 * 32 * 32;
        #pragma unroll
        for (int i = 0; i < 4; i++) {
            int it = tid + i * 256;
            int r = it >> 5, c = it & 31;
            *(float4*)(sm + PM_B_OFF + r * 132 + c * 4) = wsrc[r * 32 + c];
        }
        __syncthreads();

        const unsigned* Mu = (const unsigned*)(sm + PM_M_OFF);
        const float4*   B4 = (const float4*)(sm + PM_B_OFF);
        #pragma unroll
        for (int ks = 0; ks < 4; ks++) {
            int kr = ks * 8;
            int bb0 = (kr + q) * 33 + g * 4 + wn * 2;
            int bb1 = (kr + q + 4) * 33 + g * 4 + wn * 2;
            float4 u0 = B4[bb0], u1 = B4[bb0 + 1];
            float4 v0 = B4[bb1], v1 = B4[bb1 + 1];
            unsigned bu[8] = {__float_as_uint(u0.x), __float_as_uint(u0.y),
                              __float_as_uint(u0.z), __float_as_uint(u0.w),
                              __float_as_uint(u1.x), __float_as_uint(u1.y),
                              __float_as_uint(u1.z), __float_as_uint(u1.w)};
            unsigned bv[8] = {__float_as_uint(v0.x), __float_as_uint(v0.y),
                              __float_as_uint(v0.z), __float_as_uint(v0.w),
                              __float_as_uint(v1.x), __float_as_uint(v1.y),
                              __float_as_uint(v1.z), __float_as_uint(v1.w)};
            #pragma unroll
            for (int t = 0; t < 2; t++) {
                int r0 = (m0 + t * 16 + g) * 132 + c2 * 32 + kr + q;
                unsigned a0 = Mu[r0], a1 = Mu[r0 + 8 * 132];
                unsigned a2 = Mu[r0 + 4], a3 = Mu[r0 + 8 * 132 + 4];
                #pragma unroll
                for (int j = 0; j < 8; j++) mma8(acc2[t][j], a0, a1, a2, a3, bu[j], bv[j]);
            }
        }
    }

    __syncthreads();
    #pragma unroll
    for (int t = 0; t < 2; t++) {
        int r = m0 + t * 16 + g;
        #pragma unroll
        for (int j = 0; j < 8; j++) {
            int c0 = n0 + 8 * j + 2 * q;
            sm[PM_M_OFF + r * 132 + c0]           = fmaxf(acc2[t][j][0], 0.0f);
            sm[PM_M_OFF + r * 132 + c0 + 1]       = fmaxf(acc2[t][j][1], 0.0f);
            sm[PM_M_OFF + (r + 8) * 132 + c0]     = fmaxf(acc2[t][j][2], 0.0f);
            sm[PM_M_OFF + (r + 8) * 132 + c0 + 1] = fmaxf(acc2[t][j][3], 0.0f);
        }
    }
    __syncthreads();

    float* dst = g_pm_sum + (size_t)b * NN * HH;
    const int c4 = tid & 31;
    #pragma unroll 1
    for (int e = tid >> 5; e < 128; e += 8) {
        float4 v = *(const float4*)(sm + PM_M_OFF + e * 132 + c4 * 4);
        red4(dst + (size_t)s_recv[e] * HH + c4 * 4, v);
    }
}

// ---------------- node kernel (tf32 tensor cores) ----------------
// 128 rows per CTA. smem: s_pres[128*132] | s_hemb[128*132] | s_x[128*132] | s_B[32*132]
#define ND_PRES 0
#define ND_HEMB (128 * 132)
#define ND_X    (2 * 128 * 132)
#define ND_B    (3 * 128 * 132)
#define ND_SMEMF (ND_B + 32 * 132)

__device__ __forceinline__ void acc_init_n(float acc[2][8][4], const float* bias,
                                           int n0, int q) {
    #pragma unroll
    for (int j = 0; j < 8; j++) {
        float b0v = 0.0f, b1v = 0.0f;
        if (bias) {
            int c0 = n0 + 8 * j + 2 * q;
            b0v = __ldg(bias + c0); b1v = __ldg(bias + c0 + 1);
        }
        #pragma unroll
        for (int t = 0; t < 2; t++) {
            acc[t][j][0] = b0v; acc[t][j][1] = b1v;
            acc[t][j][2] = b0v; acc[t][j][3] = b1v;
        }
    }
}

// one K=128 GEMM pass: acc += A(smem, pitch 132, tf32 bits) @ Wg(permuted global)
__device__ __forceinline__ void gemm128(const float* As, const float* Wg, float* sB,
                                        float acc[2][8][4], int tid) {
    const int warp = tid >> 5, lane = tid & 31;
    const int wm = warp >> 1, wn = warp & 1;
    const int m0 = wm * 32;
    const int g = lane >> 2, q = lane & 3;

    #pragma unroll 1
    for (int c2 = 0; c2 < 4; c2++) {
        __syncthreads();
        const float4* wsrc = (const float4*)Wg + c2 * 32 * 32;
        #pragma unroll
        for (int i = 0; i < 4; i++) {
            int it = tid + i * 256;
            int r = it >> 5, c = it & 31;
            *(float4*)(sB + r * 132 + c * 4) = wsrc[r * 32 + c];
        }
        __syncthreads();

        const unsigned* Mu = (const unsigned*)As;
        const float4*   B4 = (const float4*)sB;
        #pragma unroll
        for (int ks = 0; ks < 4; ks++) {
            int kr = ks * 8;
            int bb0 = (kr + q) * 33 + g * 4 + wn * 2;
            int bb1 = (kr + q + 4) * 33 + g * 4 + wn * 2;
            float4 u0 = B4[bb0], u1 = B4[bb0 + 1];
            float4 v0 = B4[bb1], v1 = B4[bb1 + 1];
            unsigned bu[8] = {__float_as_uint(u0.x), __float_as_uint(u0.y),
                              __float_as_uint(u0.z), __float_as_uint(u0.w),
                              __float_as_uint(u1.x), __float_as_uint(u1.y),
                              __float_as_uint(u1.z), __float_as_uint(u1.w)};
            unsigned bv[8] = {__float_as_uint(v0.x), __float_as_uint(v0.y),
                              __float_as_uint(v0.z), __float_as_uint(v0.w),
                              __float_as_uint(v1.x), __float_as_uint(v1.y),
                              __float_as_uint(v1.z), __float_as_uint(v1.w)};
            #pragma unroll
            for (int t = 0; t < 2; t++) {
                int r0 = (m0 + t * 16 + g) * 132 + c2 * 32 + kr + q;
                unsigned a0 = Mu[r0], a1 = Mu[r0 + 8 * 132];
                unsigned a2 = Mu[r0 + 4], a3 = Mu[r0 + 8 * 132 + 4];
                #pragma unroll
                for (int j = 0; j < 8; j++) mma8(acc[t][j], a0, a1, a2, a3, bu[j], bv[j]);
            }
        }
    }
    __syncthreads();   // all reads of As/sB done before caller writes
}

__global__ void __launch_bounds__(256) node_kernel(
    const float* __restrict__ inputs,
    const float* __restrict__ hidden,
    const float* __restrict__ res_b1, const float* __restrict__ res_b2,
    const float* __restrict__ ir_b,   const float* __restrict__ ii_b,
    const float* __restrict__ in_b,
    const float* __restrict__ out_b1, const float* __restrict__ out_b2,
    const float* __restrict__ out_b3,
    float* __restrict__ out_pred,
    float* __restrict__ out_hidden)
{
    extern __shared__ __align__(16) float sm[];
    float* s_pres = sm + ND_PRES;
    float* s_hemb = sm + ND_HEMB;
    float* s_x    = sm + ND_X;
    float* s_B    = sm + ND_B;

    const int tid  = threadIdx.x;
    const int row0 = blockIdx.x * 128;

    // stage: hemb=rna(hm_mean), pres=pm_mean (raw), x=rna(inputs)
    #pragma unroll
    for (int i = 0; i < 16; i++) {
        int it = tid + i * 256;            // 0..4095
        int r = it >> 5, c4v = it & 31;
        size_t off = (size_t)(row0 + r) * HH + c4v * 4;
        float invc = 1.0f / fmaxf((float)__ldg(&g_cnt[(row0 + r) & (NN - 1)]), 1.0f);
        float4 hm4 = *(const float4*)(g_hm_sum + off);
        float4 pm4 = *(const float4*)(g_pm_sum + off);
        float4 in4 = *(const float4*)(inputs + off);
        uint4 a;
        a.x = rna(hm4.x * invc); a.y = rna(hm4.y * invc);
        a.z = rna(hm4.z * invc); a.w = rna(hm4.w * invc);
        *(uint4*)(s_hemb + r * 132 + c4v * 4) = a;
        float4 p;
        p.x = pm4.x * invc; p.y = pm4.y * invc; p.z = pm4.z * invc; p.w = pm4.w * invc;
        *(float4*)(s_pres + r * 132 + c4v * 4) = p;
        uint4 x;
        x.x = rna(in4.x); x.y = rna(in4.y); x.z = rna(in4.z); x.w = rna(in4.w);
        *(uint4*)(s_x + r * 132 + c4v * 4) = x;
    }
    // gemm128 begins with __syncthreads(): staging visible.

    const int warp = tid >> 5, lane = tid & 31;
    const int wm = warp >> 1, wn = warp & 1;
    const int m0 = wm * 32, n0 = wn * 64;
    const int g = lane >> 2, q = lane & 3;

    float acc[2][8][4];

    // fragment coordinate helpers (variadic: bodies may contain commas)
    #define FRAG_LOOP(...)                                               \
        _Pragma("unroll")                                                \
        for (int t = 0; t < 2; t++) {                                    \
            int r_ = m0 + t * 16 + g;                                    \
            _Pragma("unroll")                                            \
            for (int j = 0; j < 8; j++) {                                \
                int c0 = n0 + 8 * j + 2 * q;                             \
                int i0 = r_ * 132 + c0;                                  \
                int i2 = (r_ + 8) * 132 + c0;                            \
                (void)i0; (void)i2;                                      \
                __VA_ARGS__                                              \
            }                                                            \
        }

    // 1) res1 = relu(x @ res_w1 + b) -> s_x (in place; gemm's trailing sync protects)
    acc_init_n(acc, res_b1, n0, q);
    gemm128(s_x, g_nw[0], s_B, acc, tid);
    FRAG_LOOP({
        s_x[i0]     = uif(rna(fmaxf(acc[t][j][0], 0.0f)));
        s_x[i0 + 1] = uif(rna(fmaxf(acc[t][j][1], 0.0f)));
        s_x[i2]     = uif(rna(fmaxf(acc[t][j][2], 0.0f)));
        s_x[i2 + 1] = uif(rna(fmaxf(acc[t][j][3], 0.0f)));
    })

    // 2) pres = relu(res1 @ res_w2 + b) + pm_mean -> s_pres
    acc_init_n(acc, res_b2, n0, q);
    gemm128(s_x, g_nw[1], s_B, acc, tid);
    FRAG_LOOP({
        s_pres[i0]     = uif(rna(fmaxf(acc[t][j][0], 0.0f) + s_pres[i0]));
        s_pres[i0 + 1] = uif(rna(fmaxf(acc[t][j][1], 0.0f) + s_pres[i0 + 1]));
        s_pres[i2]     = uif(rna(fmaxf(acc[t][j][2], 0.0f) + s_pres[i2]));
        s_pres[i2 + 1] = uif(rna(fmaxf(acc[t][j][3], 0.0f) + s_pres[i2 + 1]));
    })

    // 3) hh = hemb @ hh_w -> s_x (raw)
    acc_init_n(acc, nullptr, n0, q);
    gemm128(s_hemb, g_nw[7], s_B, acc, tid);
    FRAG_LOOP({
        s_x[i0]     = acc[t][j][0];
        s_x[i0 + 1] = acc[t][j][1];
        s_x[i2]     = acc[t][j][2];
        s_x[i2 + 1] = acc[t][j][3];
    })

    // 4) r = sigmoid(pres@ir_w + ir_b + hemb@hr_w); s_x <- r * hh
    acc_init_n(acc, ir_b, n0, q);
    gemm128(s_pres, g_nw[2], s_B, acc, tid);
    gemm128(s_hemb, g_nw[3], s_B, acc, tid);
    FRAG_LOOP({
        s_x[i0]     = sigmoidf_(acc[t][j][0]) * s_x[i0];
        s_x[i0 + 1] = sigmoidf_(acc[t][j][1]) * s_x[i0 + 1];
        s_x[i2]     = sigmoidf_(acc[t][j][2]) * s_x[i2];
        s_x[i2 + 1] = sigmoidf_(acc[t][j][3]) * s_x[i2 + 1];
    })

    // 5) i = sigmoid(pres@ii_w + ii_b + hemb@hi_w) -> s_hemb (hemb dead after this)
    acc_init_n(acc, ii_b, n0, q);
    gemm128(s_pres, g_nw[4], s_B, acc, tid);
    gemm128(s_hemb, g_nw[5], s_B, acc, tid);
    FRAG_LOOP({
        s_hemb[i0]     = sigmoidf_(acc[t][j][0]);
        s_hemb[i0 + 1] = sigmoidf_(acc[t][j][1]);
        s_hemb[i2]     = sigmoidf_(acc[t][j][2]);
        s_hemb[i2 + 1] = sigmoidf_(acc[t][j][3]);
    })

    // 6) n = tanh(pres@in_w + in_b + r*hh); new_h = (1-i)*n + i*hidden
    acc_init_n(acc, in_b, n0, q);
    gemm128(s_pres, g_nw[6], s_B, acc, tid);
    FRAG_LOOP({
        float n_0 = tanhf(acc[t][j][0] + s_x[i0]);
        float n_1 = tanhf(acc[t][j][1] + s_x[i0 + 1]);
        float n_2 = tanhf(acc[t][j][2] + s_x[i2]);
        float n_3 = tanhf(acc[t][j][3] + s_x[i2 + 1]);
        float i_0 = s_hemb[i0];
        float i_1 = s_hemb[i0 + 1];
        float i_2 = s_hemb[i2];
        float i_3 = s_hemb[i2 + 1];
        size_t go0 = (size_t)(row0 + r_) * HH + c0;
        size_t go2 = (size_t)(row0 + r_ + 8) * HH + c0;
        float2 h0 = *(const float2*)(hidden + go0);
        float2 h2 = *(const float2*)(hidden + go2);
        float2 nh0;
        float2 nh2;
        nh0.x = (1.0f - i_0) * n_0 + i_0 * h0.x;
        nh0.y = (1.0f - i_1) * n_1 + i_1 * h0.y;
        nh2.x = (1.0f - i_2) * n_2 + i_2 * h2.x;
        nh2.y = (1.0f - i_3) * n_3 + i_3 * h2.y;
        *(float2*)(out_hidden + go0) = nh0;
        *(float2*)(out_hidden + go2) = nh2;
        s_x[i0]     = uif(rna(nh0.x));
        s_x[i0 + 1] = uif(rna(nh0.y));
        s_x[i2]     = uif(rna(nh2.x));
        s_x[i2 + 1] = uif(rna(nh2.y));
    })

    // 7) o1 = relu(new_h @ out_w1 + b) -> s_hemb
    acc_init_n(acc, out_b1, n0, q);
    gemm128(s_x, g_nw[8], s_B, acc, tid);
    FRAG_LOOP({
        s_hemb[i0]     = uif(rna(fmaxf(acc[t][j][0], 0.0f)));
        s_hemb[i0 + 1] = uif(rna(fmaxf(acc[t][j][1], 0.0f)));
        s_hemb[i2]     = uif(rna(fmaxf(acc[t][j][2], 0.0f)));
        s_hemb[i2 + 1] = uif(rna(fmaxf(acc[t][j][3], 0.0f)));
    })

    // 8) o2 = relu(o1 @ out_w2 + b) -> s_x
    acc_init_n(acc, out_b2, n0, q);
    gemm128(s_hemb, g_nw[9], s_B, acc, tid);
    FRAG_LOOP({
        s_x[i0]     = uif(rna(fmaxf(acc[t][j][0], 0.0f)));
        s_x[i0 + 1] = uif(rna(fmaxf(acc[t][j][1], 0.0f)));
        s_x[i2]     = uif(rna(fmaxf(acc[t][j][2], 0.0f)));
        s_x[i2 + 1] = uif(rna(fmaxf(acc[t][j][3], 0.0f)));
    })

    // 9) pred = o2 @ out_w3 + b -> global
    acc_init_n(acc, out_b3, n0, q);
    gemm128(s_x, g_nw[10], s_B, acc, tid);
    FRAG_LOOP({
        size_t go0 = (size_t)(row0 + r_) * II + c0;
        size_t go2 = (size_t)(row0 + r_ + 8) * II + c0;
        float2 p0;
        float2 p2;
        p0.x = acc[t][j][0]; p0.y = acc[t][j][1];
        p2.x = acc[t][j][2]; p2.y = acc[t][j][3];
        *(float2*)(out_pred + go0) = p0;
        *(float2*)(out_pred + go2) = p2;
    })
    #undef FRAG_LOOP
}

// ---------------- launch ----------------
extern "C" void kernel_launch(void* const* d_in, const int* in_sizes, int n_in,
                              void* d_out, int out_size) {
    const float* inputs    = (const float*)d_in[0];
    const float* edge_attr = (const float*)d_in[1];
    const int*   send_e    = (const int*)  d_in[2];
    const int*   recv_e    = (const int*)  d_in[3];
    const float* hidden    = (const float*)d_in[4];
    const float* msg_w1 = (const float*)d_in[5];
    const float* msg_b1 = (const float*)d_in[6];
    const float* msg_w2 = (const float*)d_in[7];
    const float* msg_b2 = (const float*)d_in[8];
    const float* pm_w1  = (const float*)d_in[9];
    const float* pm_b1  = (const float*)d_in[10];
    const float* pm_w2  = (const float*)d_in[11];
    const float* pm_b2  = (const float*)d_in[12];
    const float* res_w1 = (const float*)d_in[13];
    const float* res_b1 = (const float*)d_in[14];
    const float* res_w2 = (const float*)d_in[15];
    const float* res_b2 = (const float*)d_in[16];
    const float* ir_w   = (const float*)d_in[17];
    const float* ir_b   = (const float*)d_in[18];
    const float* ii_w   = (const float*)d_in[19];
    const float* ii_b   = (const float*)d_in[20];
    const float* in_w   = (const float*)d_in[21];
    const float* in_b   = (const float*)d_in[22];
    const float* hr_w   = (const float*)d_in[23];
    const float* hi_w   = (const float*)d_in[24];
    const float* hh_w   = (const float*)d_in[25];
    const float* out_w1 = (const float*)d_in[26];
    const float* out_b1 = (const float*)d_in[27];
    const float* out_w2 = (const float*)d_in[28];
    const float* out_b2 = (const float*)d_in[29];
    const float* out_w3 = (const float*)d_in[30];
    const float* out_b3 = (const float*)d_in[31];

    float* out_pred   = (float*)d_out;
    float* out_hidden = (float*)d_out + (size_t)BB * NN * II;

    const int HM_SMEM = HM_SMEMF * 4;     // 103,936 B -> 2 CTAs/SM
    const int PM_SMEM = PM_SMEMF * 4;     // 103,424 B -> 2 CTAs/SM
    const int ND_SMEM = ND_SMEMF * 4;     // 219,648 B
    cudaFuncSetAttribute(hm_kernel, cudaFuncAttributeMaxDynamicSharedMemorySize, HM_SMEM);
    cudaFuncSetAttribute(pm_kernel, cudaFuncAttributeMaxDynamicSharedMemorySize, PM_SMEM);
    cudaFuncSetAttribute(node_kernel, cudaFuncAttributeMaxDynamicSharedMemorySize, ND_SMEM);

    zero_kernel<<<1024, 256>>>();
    count_kernel<<<EE / 256, 256>>>(recv_e);
    prep_kernel<<<128, 256>>>(msg_w1, msg_w2, pm_w1, pm_w2,
                              res_w1, res_w2, ir_w, hr_w, ii_w, hi_w,
                              in_w, hh_w, out_w1, out_w2, out_w3);

    hm_kernel<<<dim3(EE / 128, BB), 256, HM_SMEM>>>(hidden, send_e, recv_e, msg_b1, msg_b2);
    pm_kernel<<<dim3(EE / 128, BB), 256, PM_SMEM>>>(edge_attr, recv_e, pm_b1, pm_b2);

    node_kernel<<<(BB * NN) / 128, 256, ND_SMEM>>>(
        inputs, hidden,
        res_b1, res_b2, ir_b, ii_b, in_b,
        out_b1, out_b2, out_b3,
        out_pred, out_hidden);
}

// round 12
// speedup vs baseline: 3.9259x; 1.0666x over previous
#include <cuda_runtime.h>
#include <math.h>
#include <stdint.h>

// Problem constants
#define BB 4
#define NN 4096
#define EE 131072
#define II 128
#define HH 128
#define FF 140

// ---------------- scratch (__device__ globals; no allocs allowed) ----------
__device__ float g_hm_sum[(size_t)BB * NN * HH];   // 8 MB
__device__ float g_pm_sum[(size_t)BB * NN * HH];   // 8 MB
__device__ int   g_cnt[NN];

// permuted tf32-rounded weights: w[k][ (n%8)*16 + n/8 ]
__device__ float g_w1p[256 * 128];
__device__ float g_w2p[128 * 128];
__device__ float g_pw1p[160 * 128];   // K padded 140 -> 160 with zeros
__device__ float g_pw2p[128 * 128];
// node weights: 0:res_w1 1:res_w2 2:ir_w 3:hr_w 4:ii_w 5:hi_w 6:in_w 7:hh_w 8:out_w1 9:out_w2 10:out_w3
__device__ float g_nw[11][128 * 128];

__device__ __forceinline__ float sigmoidf_(float x) {
    return 1.0f / (1.0f + expf(-x));
}

__device__ __forceinline__ unsigned rna(float x) {
    unsigned r;
    asm("cvt.rna.tf32.f32 %0, %1;" : "=r"(r) : "f"(x));
    return r;
}
__device__ __forceinline__ float uif(unsigned x) { return __uint_as_float(x); }

__device__ __forceinline__ void mma8(float* c,
                                     unsigned a0, unsigned a1, unsigned a2, unsigned a3,
                                     unsigned b0, unsigned b1) {
    asm volatile(
        "mma.sync.aligned.m16n8k8.row.col.f32.tf32.tf32.f32 "
        "{%0,%1,%2,%3}, {%4,%5,%6,%7}, {%8,%9}, {%0,%1,%2,%3};"
        : "+f"(c[0]), "+f"(c[1]), "+f"(c[2]), "+f"(c[3])
        : "r"(a0), "r"(a1), "r"(a2), "r"(a3), "r"(b0), "r"(b1));
}

__device__ __forceinline__ void red4(float* p, float4 v) {
    asm volatile("red.global.add.v4.f32 [%0], {%1,%2,%3,%4};"
                 :: "l"(p), "f"(v.x), "f"(v.y), "f"(v.z), "f"(v.w) : "memory");
}

__device__ __forceinline__ void cpa16(uint32_t dst_smem, const void* src) {
    asm volatile("cp.async.cg.shared.global [%0], [%1], 16;"
                 :: "r"(dst_smem), "l"(src) : "memory");
}
#define CP_COMMIT() asm volatile("cp.async.commit_group;" ::: "memory")
#define CP_WAIT0()  asm volatile("cp.async.wait_group 0;" ::: "memory")

// ---------------- helper kernels ----------------

__global__ void zero_kernel() {
    const size_t M = (size_t)BB * NN * HH;
    size_t stride = (size_t)gridDim.x * blockDim.x;
    size_t i = (size_t)blockIdx.x * blockDim.x + threadIdx.x;
    for (size_t j = i; j < M; j += stride) {
        g_hm_sum[j] = 0.0f;
        g_pm_sum[j] = 0.0f;
    }
    if (i < NN) g_cnt[i] = 0;
}

__global__ void count_kernel(const int* __restrict__ recv_e) {
    int e = blockIdx.x * blockDim.x + threadIdx.x;
    if (e < EE) atomicAdd(&g_cnt[recv_e[e]], 1);
}

__global__ void prep_kernel(const float* __restrict__ mw1,
                            const float* __restrict__ mw2,
                            const float* __restrict__ pw1,
                            const float* __restrict__ pw2,
                            const float* __restrict__ res_w1,
                            const float* __restrict__ res_w2,
                            const float* __restrict__ ir_w,
                            const float* __restrict__ hr_w,
                            const float* __restrict__ ii_w,
                            const float* __restrict__ hi_w,
                            const float* __restrict__ in_w,
                            const float* __restrict__ hh_w,
                            const float* __restrict__ out_w1,
                            const float* __restrict__ out_w2,
                            const float* __restrict__ out_w3) {
    int i = blockIdx.x * blockDim.x + threadIdx.x;   // up to 32768
    if (i < 256 * 128) {
        int k = i >> 7, n = i & 127;
        g_w1p[k * 128 + ((n & 7) * 16 + (n >> 3))] = uif(rna(mw1[i]));
    }
    if (i < 128 * 128) {
        int k = i >> 7, n = i & 127;
        int s = k * 128 + ((n & 7) * 16 + (n >> 3));
        g_w2p[s]  = uif(rna(mw2[i]));
        g_pw2p[s] = uif(rna(pw2[i]));
        g_nw[0][s]  = uif(rna(res_w1[i]));
        g_nw[1][s]  = uif(rna(res_w2[i]));
        g_nw[2][s]  = uif(rna(ir_w[i]));
        g_nw[3][s]  = uif(rna(hr_w[i]));
        g_nw[4][s]  = uif(rna(ii_w[i]));
        g_nw[5][s]  = uif(rna(hi_w[i]));
        g_nw[6][s]  = uif(rna(in_w[i]));
        g_nw[7][s]  = uif(rna(hh_w[i]));
        g_nw[8][s]  = uif(rna(out_w1[i]));
        g_nw[9][s]  = uif(rna(out_w2[i]));
        g_nw[10][s] = uif(rna(out_w3[i]));
    }
    if (i < 160 * 128) {
        int k = i >> 7, n = i & 127;
        float v = (k < 140) ? pw1[i] : 0.0f;
        g_pw1p[k * 128 + ((n & 7) * 16 + (n >> 3))] = uif(rna(v));
    }
}

// ---------------- shared edge-kernel layout (floats) ----------------
// mid[128*132] hosts A double-buffers (2 x 128*36) during layer 1 (A dead before
// mid is written). B double-buffered after mid. idx at the end.
// EK_MID = 0
#define EK_AB(buf)  ((buf) * (128 * 36))              // inside mid region
#define EK_B(buf)   (128 * 132 + (buf) * (32 * 132))
#define EK_IDX      (128 * 132 + 2 * 32 * 132)
#define HM_SMEMF    (EK_IDX + 256)                    // 25,600 fl = 102,400 B
#define PM_SMEMF    (EK_IDX + 128)                    // 101,888 B

// mma over one staged chunk: A(base Ab, pitch Ap, k-col offset kofs), B(base Bb)
#define CHUNK_MMA(ACC, Ab, Ap, kofs, Bb)                                     \
    {                                                                        \
        const unsigned* Au_ = (const unsigned*)(sm + (Ab));                  \
        const float4*   B4_ = (const float4*)(sm + (Bb));                    \
        _Pragma("unroll")                                                    \
        for (int ks = 0; ks < 4; ks++) {                                     \
            int kr = ks * 8;                                                 \
            int bb0 = (kr + q) * 33 + g * 4 + wn * 2;                        \
            int bb1 = (kr + q + 4) * 33 + g * 4 + wn * 2;                    \
            float4 u0 = B4_[bb0], u1 = B4_[bb0 + 1];                         \
            float4 v0 = B4_[bb1], v1 = B4_[bb1 + 1];                         \
            unsigned bu[8] = {__float_as_uint(u0.x), __float_as_uint(u0.y),  \
                              __float_as_uint(u0.z), __float_as_uint(u0.w),  \
                              __float_as_uint(u1.x), __float_as_uint(u1.y),  \
                              __float_as_uint(u1.z), __float_as_uint(u1.w)}; \
            unsigned bv[8] = {__float_as_uint(v0.x), __float_as_uint(v0.y),  \
                              __float_as_uint(v0.z), __float_as_uint(v0.w),  \
                              __float_as_uint(v1.x), __float_as_uint(v1.y),  \
                              __float_as_uint(v1.z), __float_as_uint(v1.w)}; \
            _Pragma("unroll")                                                \
            for (int t = 0; t < 2; t++) {                                    \
                int r0 = (m0 + t * 16 + g) * (Ap) + (kofs) + kr + q;         \
                unsigned a0 = Au_[r0], a1 = Au_[r0 + 8 * (Ap)];              \
                unsigned a2 = Au_[r0 + 4], a3 = Au_[r0 + 8 * (Ap) + 4];      \
                _Pragma("unroll")                                            \
                for (int j = 0; j < 8; j++)                                  \
                    mma8(ACC[t][j], a0, a1, a2, a3, bu[j], bv[j]);           \
            }                                                                \
        }                                                                    \
    }

#define ACC_INIT(ACC, BIAS)                                                  \
    _Pragma("unroll")                                                        \
    for (int j = 0; j < 8; j++) {                                            \
        int c0 = n0 + 8 * j + 2 * q;                                         \
        float b0v = __ldg((BIAS) + c0), b1v = __ldg((BIAS) + c0 + 1);        \
        _Pragma("unroll")                                                    \
        for (int t = 0; t < 2; t++) {                                        \
            ACC[t][j][0] = b0v; ACC[t][j][1] = b1v;                          \
            ACC[t][j][2] = b0v; ACC[t][j][3] = b1v;                          \
        }                                                                    \
    }

// issue B-chunk cp.async (4 x 16B per thread)
#define B_CPASYNC(dstbuf, WSRC)                                              \
    {                                                                        \
        const float4* wsrc_ = (WSRC);                                        \
        _Pragma("unroll")                                                    \
        for (int i = 0; i < 4; i++) {                                        \
            int it = tid + i * 256;                                          \
            int r = it >> 5, c = it & 31;                                    \
            cpa16(smem_u32 + (uint32_t)((EK_B(dstbuf) + r * 132 + c * 4) * 4), \
                  wsrc_ + r * 32 + c);                                       \
        }                                                                    \
        CP_COMMIT();                                                         \
    }

// ---------------- hm edge kernel (pipelined tf32) ----------------
__global__ void __launch_bounds__(256, 2) hm_kernel(
    const float* __restrict__ hidden,
    const int* __restrict__ send_e, const int* __restrict__ recv_e,
    const float* __restrict__ mb1, const float* __restrict__ mb2)
{
    extern __shared__ __align__(16) float sm[];
    int* s_recv = (int*)(sm + EK_IDX);
    int* s_send = s_recv + 128;

    const int tid = threadIdx.x;
    const int b   = blockIdx.y;
    const int e0  = blockIdx.x * 128;
    const uint32_t smem_u32 = (uint32_t)__cvta_generic_to_shared(sm);

    if (tid < 128) s_recv[tid] = recv_e[e0 + tid];
    else           s_send[tid - 128] = send_e[e0 + tid - 128];

    const int warp = tid >> 5, lane = tid & 31;
    const int wm = warp >> 1, wn = warp & 1;
    const int m0 = wm * 32, n0 = wn * 64;
    const int g = lane >> 2, q = lane & 3;
    const int se = tid >> 3, sv = tid & 7;   // A-staging coords (i-step adds 32 to e)

    float acc[2][8][4];
    ACC_INIT(acc, mb1)
    __syncthreads();   // idx visible

    const float* hb = hidden + (size_t)b * NN * HH;

    // ---- stage chunk 0 ----
    {
        #pragma unroll
        for (int i = 0; i < 4; i++) {
            int e = se + i * 32;
            float4 f = *(const float4*)(hb + (size_t)s_recv[e] * HH + sv * 4);
            uint4 r; r.x = rna(f.x); r.y = rna(f.y); r.z = rna(f.z); r.w = rna(f.w);
            *(uint4*)(sm + EK_AB(0) + e * 36 + sv * 4) = r;
        }
        B_CPASYNC(0, (const float4*)g_w1p)
        CP_WAIT0();
    }
    __syncthreads();

    // ---- layer 1: 8 chunks, pipelined ----
    #pragma unroll 1
    for (int kc = 0; kc < 8; kc++) {
        const int cur = kc & 1, nxt = cur ^ 1;
        const bool has = (kc + 1) < 8;
        float4 pf[4];
        if (has) {
            const int* nidx = (kc + 1 < 4) ? s_recv : s_send;
            const int kk0 = ((kc + 1) & 3) * 32;
            #pragma unroll
            for (int i = 0; i < 4; i++) {
                int e = se + i * 32;
                pf[i] = *(const float4*)(hb + (size_t)nidx[e] * HH + kk0 + sv * 4);
            }
            B_CPASYNC(nxt, (const float4*)g_w1p + (kc + 1) * 32 * 32)
        }
        CHUNK_MMA(acc, EK_AB(cur), 36, 0, EK_B(cur))
        if (has) {
            #pragma unroll
            for (int i = 0; i < 4; i++) {
                int e = se + i * 32;
                uint4 r;
                r.x = rna(pf[i].x); r.y = rna(pf[i].y);
                r.z = rna(pf[i].z); r.w = rna(pf[i].w);
                *(uint4*)(sm + EK_AB(nxt) + e * 36 + sv * 4) = r;
            }
            CP_WAIT0();
        }
        __syncthreads();
    }

    // ---- layer-1 epilogue: write mid (overwrites A buffers; all mma done) ----
    // prefetch layer-2 B chunk 0 first (targets B region, disjoint from mid)
    B_CPASYNC(0, (const float4*)g_w2p)
    #pragma unroll
    for (int t = 0; t < 2; t++) {
        int r = m0 + t * 16 + g;
        #pragma unroll
        for (int j = 0; j < 8; j++) {
            int c0 = n0 + 8 * j + 2 * q;
            sm[r * 132 + c0]           = uif(rna(tanhf(acc[t][j][0])));
            sm[r * 132 + c0 + 1]       = uif(rna(tanhf(acc[t][j][1])));
            sm[(r + 8) * 132 + c0]     = uif(rna(tanhf(acc[t][j][2])));
            sm[(r + 8) * 132 + c0 + 1] = uif(rna(tanhf(acc[t][j][3])));
        }
    }
    float acc2[2][8][4];
    ACC_INIT(acc2, mb2)
    CP_WAIT0();
    __syncthreads();   // mid + B0 visible

    // ---- layer 2: 4 chunks, pipelined B ----
    #pragma unroll 1
    for (int c2 = 0; c2 < 4; c2++) {
        const int cur = c2 & 1, nxt = cur ^ 1;
        const bool has = (c2 + 1) < 4;
        if (has) B_CPASYNC(nxt, (const float4*)g_w2p + (c2 + 1) * 32 * 32)
        CHUNK_MMA(acc2, 0, 132, c2 * 32, EK_B(cur))
        if (has) CP_WAIT0();
        __syncthreads();
    }

    // ---- layer-2 epilogue -> mid, then coalesced scatter ----
    #pragma unroll
    for (int t = 0; t < 2; t++) {
        int r = m0 + t * 16 + g;
        #pragma unroll
        for (int j = 0; j < 8; j++) {
            int c0 = n0 + 8 * j + 2 * q;
            sm[r * 132 + c0]           = tanhf(acc2[t][j][0]);
            sm[r * 132 + c0 + 1]       = tanhf(acc2[t][j][1]);
            sm[(r + 8) * 132 + c0]     = tanhf(acc2[t][j][2]);
            sm[(r + 8) * 132 + c0 + 1] = tanhf(acc2[t][j][3]);
        }
    }
    __syncthreads();

    float* dst = g_hm_sum + (size_t)b * NN * HH;
    const int c4 = tid & 31;
    #pragma unroll 1
    for (int e = tid >> 5; e < 128; e += 8) {
        float4 v = *(const float4*)(sm + e * 132 + c4 * 4);
        red4(dst + (size_t)s_recv[e] * HH + c4 * 4, v);
    }
}

// ---------------- pm edge kernel (pipelined tf32) ----------------
__global__ void __launch_bounds__(256, 2) pm_kernel(
    const float* __restrict__ edge_attr,
    const int* __restrict__ recv_e,
    const float* __restrict__ pb1, const float* __restrict__ pb2)
{
    extern __shared__ __align__(16) float sm[];
    int* s_recv = (int*)(sm + EK_IDX);

    const int tid = threadIdx.x;
    const int b   = blockIdx.y;
    const int e0  = blockIdx.x * 128;
    const uint32_t smem_u32 = (uint32_t)__cvta_generic_to_shared(sm);

    if (tid < 128) s_recv[tid] = recv_e[e0 + tid];

    const int warp = tid >> 5, lane = tid & 31;
    const int wm = warp >> 1, wn = warp & 1;
    const int m0 = wm * 32, n0 = wn * 64;
    const int g = lane >> 2, q = lane & 3;
    const int se = tid >> 3, sv = tid & 7;

    float acc[2][8][4];
    ACC_INIT(acc, pb1)

    const float* ea = edge_attr + ((size_t)b * EE + e0) * FF;

    // ---- stage chunk 0 ----
    {
        #pragma unroll
        for (int i = 0; i < 4; i++) {
            int e = se + i * 32;
            int f = sv * 4;
            float4 fv = *(const float4*)(ea + (size_t)e * FF + f);   // f<32<FF
            uint4 r; r.x = rna(fv.x); r.y = rna(fv.y); r.z = rna(fv.z); r.w = rna(fv.w);
            *(uint4*)(sm + EK_AB(0) + e * 36 + sv * 4) = r;
        }
        B_CPASYNC(0, (const float4*)g_pw1p)
        CP_WAIT0();
    }
    __syncthreads();

    // ---- layer 1: 5 chunks (K padded to 160), pipelined ----
    #pragma unroll 1
    for (int kc = 0; kc < 5; kc++) {
        const int cur = kc & 1, nxt = cur ^ 1;
        const bool has = (kc + 1) < 5;
        float4 pf[4];
        if (has) {
            const int k0 = (kc + 1) * 32;
            #pragma unroll
            for (int i = 0; i < 4; i++) {
                int e = se + i * 32;
                int f = k0 + sv * 4;
                if (f < FF) pf[i] = *(const float4*)(ea + (size_t)e * FF + f);
                else { pf[i].x = 0.0f; pf[i].y = 0.0f; pf[i].z = 0.0f; pf[i].w = 0.0f; }
            }
            B_CPASYNC(nxt, (const float4*)g_pw1p + (kc + 1) * 32 * 32)
        }
        CHUNK_MMA(acc, EK_AB(cur), 36, 0, EK_B(cur))
        if (has) {
            #pragma unroll
            for (int i = 0; i < 4; i++) {
                int e = se + i * 32;
                uint4 r;
                r.x = rna(pf[i].x); r.y = rna(pf[i].y);
                r.z = rna(pf[i].z); r.w = rna(pf[i].w);
                *(uint4*)(sm + EK_AB(nxt) + e * 36 + sv * 4) = r;
            }
            CP_WAIT0();
        }
        __syncthreads();
    }

    // ---- layer-1 epilogue -> mid ----
    B_CPASYNC(0, (const float4*)g_pw2p)
    #pragma unroll
    for (int t = 0; t < 2; t++) {
        int r = m0 + t * 16 + g;
        #pragma unroll
        for (int j = 0; j < 8; j++) {
            int c0 = n0 + 8 * j + 2 * q;
            sm[r * 132 + c0]           = uif(rna(fmaxf(acc[t][j][0], 0.0f)));
            sm[r * 132 + c0 + 1]       = uif(rna(fmaxf(acc[t][j][1], 0.0f)));
            sm[(r + 8) * 132 + c0]     = uif(rna(fmaxf(acc[t][j][2], 0.0f)));
            sm[(r + 8) * 132 + c0 + 1] = uif(rna(fmaxf(acc[t][j][3], 0.0f)));
        }
    }
    float acc2[2][8][4];
    ACC_INIT(acc2, pb2)
    CP_WAIT0();
    __syncthreads();

    // ---- layer 2: 4 chunks, pipelined B ----
    #pragma unroll 1
    for (int c2 = 0; c2 < 4; c2++) {
        const int cur = c2 & 1, nxt = cur ^ 1;
        const bool has = (c2 + 1) < 4;
        if (has) B_CPASYNC(nxt, (const float4*)g_pw2p + (c2 + 1) * 32 * 32)
        CHUNK_MMA(acc2, 0, 132, c2 * 32, EK_B(cur))
        if (has) CP_WAIT0();
        __syncthreads();
    }

    // ---- epilogue + scatter ----
    #pragma unroll
    for (int t = 0; t < 2; t++) {
        int r = m0 + t * 16 + g;
        #pragma unroll
        for (int j = 0; j < 8; j++) {
            int c0 = n0 + 8 * j + 2 * q;
            sm[r * 132 + c0]           = fmaxf(acc2[t][j][0], 0.0f);
            sm[r * 132 + c0 + 1]       = fmaxf(acc2[t][j][1], 0.0f);
            sm[(r + 8) * 132 + c0]     = fmaxf(acc2[t][j][2], 0.0f);
            sm[(r + 8) * 132 + c0 + 1] = fmaxf(acc2[t][j][3], 0.0f);
        }
    }
    __syncthreads();

    float* dst = g_pm_sum + (size_t)b * NN * HH;
    const int c4 = tid & 31;
    #pragma unroll 1
    for (int e = tid >> 5; e < 128; e += 8) {
        float4 v = *(const float4*)(sm + e * 132 + c4 * 4);
        red4(dst + (size_t)s_recv[e] * HH + c4 * 4, v);
    }
}

// ---------------- node kernel (tf32 tensor cores, unchanged from R11) ----------------
#define ND_PRES 0
#define ND_HEMB (128 * 132)
#define ND_X    (2 * 128 * 132)
#define ND_B    (3 * 128 * 132)
#define ND_SMEMF (ND_B + 32 * 132)

__device__ __forceinline__ void acc_init_n(float acc[2][8][4], const float* bias,
                                           int n0, int q) {
    #pragma unroll
    for (int j = 0; j < 8; j++) {
        float b0v = 0.0f, b1v = 0.0f;
        if (bias) {
            int c0 = n0 + 8 * j + 2 * q;
            b0v = __ldg(bias + c0); b1v = __ldg(bias + c0 + 1);
        }
        #pragma unroll
        for (int t = 0; t < 2; t++) {
            acc[t][j][0] = b0v; acc[t][j][1] = b1v;
            acc[t][j][2] = b0v; acc[t][j][3] = b1v;
        }
    }
}

__device__ __forceinline__ void gemm128(const float* As, const float* Wg, float* sB,
                                        float acc[2][8][4], int tid) {
    const int warp = tid >> 5, lane = tid & 31;
    const int wm = warp >> 1, wn = warp & 1;
    const int m0 = wm * 32;
    const int g = lane >> 2, q = lane & 3;

    #pragma unroll 1
    for (int c2 = 0; c2 < 4; c2++) {
        __syncthreads();
        const float4* wsrc = (const float4*)Wg + c2 * 32 * 32;
        #pragma unroll
        for (int i = 0; i < 4; i++) {
            int it = tid + i * 256;
            int r = it >> 5, c = it & 31;
            *(float4*)(sB + r * 132 + c * 4) = wsrc[r * 32 + c];
        }
        __syncthreads();

        const unsigned* Mu = (const unsigned*)As;
        const float4*   B4 = (const float4*)sB;
        #pragma unroll
        for (int ks = 0; ks < 4; ks++) {
            int kr = ks * 8;
            int bb0 = (kr + q) * 33 + g * 4 + wn * 2;
            int bb1 = (kr + q + 4) * 33 + g * 4 + wn * 2;
            float4 u0 = B4[bb0], u1 = B4[bb0 + 1];
            float4 v0 = B4[bb1], v1 = B4[bb1 + 1];
            unsigned bu[8] = {__float_as_uint(u0.x), __float_as_uint(u0.y),
                              __float_as_uint(u0.z), __float_as_uint(u0.w),
                              __float_as_uint(u1.x), __float_as_uint(u1.y),
                              __float_as_uint(u1.z), __float_as_uint(u1.w)};
            unsigned bv[8] = {__float_as_uint(v0.x), __float_as_uint(v0.y),
                              __float_as_uint(v0.z), __float_as_uint(v0.w),
                              __float_as_uint(v1.x), __float_as_uint(v1.y),
                              __float_as_uint(v1.z), __float_as_uint(v1.w)};
            #pragma unroll
            for (int t = 0; t < 2; t++) {
                int r0 = (m0 + t * 16 + g) * 132 + c2 * 32 + kr + q;
                unsigned a0 = Mu[r0], a1 = Mu[r0 + 8 * 132];
                unsigned a2 = Mu[r0 + 4], a3 = Mu[r0 + 8 * 132 + 4];
                #pragma unroll
                for (int j = 0; j < 8; j++) mma8(acc[t][j], a0, a1, a2, a3, bu[j], bv[j]);
            }
        }
    }
    __syncthreads();
}

__global__ void __launch_bounds__(256) node_kernel(
    const float* __restrict__ inputs,
    const float* __restrict__ hidden,
    const float* __restrict__ res_b1, const float* __restrict__ res_b2,
    const float* __restrict__ ir_b,   const float* __restrict__ ii_b,
    const float* __restrict__ in_b,
    const float* __restrict__ out_b1, const float* __restrict__ out_b2,
    const float* __restrict__ out_b3,
    float* __restrict__ out_pred,
    float* __restrict__ out_hidden)
{
    extern __shared__ __align__(16) float sm[];
    float* s_pres = sm + ND_PRES;
    float* s_hemb = sm + ND_HEMB;
    float* s_x    = sm + ND_X;
    float* s_B    = sm + ND_B;

    const int tid  = threadIdx.x;
    const int row0 = blockIdx.x * 128;

    #pragma unroll
    for (int i = 0; i < 16; i++) {
        int it = tid + i * 256;
        int r = it >> 5, c4v = it & 31;
        size_t off = (size_t)(row0 + r) * HH + c4v * 4;
        float invc = 1.0f / fmaxf((float)__ldg(&g_cnt[(row0 + r) & (NN - 1)]), 1.0f);
        float4 hm4 = *(const float4*)(g_hm_sum + off);
        float4 pm4 = *(const float4*)(g_pm_sum + off);
        float4 in4 = *(const float4*)(inputs + off);
        uint4 a;
        a.x = rna(hm4.x * invc); a.y = rna(hm4.y * invc);
        a.z = rna(hm4.z * invc); a.w = rna(hm4.w * invc);
        *(uint4*)(s_hemb + r * 132 + c4v * 4) = a;
        float4 p;
        p.x = pm4.x * invc; p.y = pm4.y * invc; p.z = pm4.z * invc; p.w = pm4.w * invc;
        *(float4*)(s_pres + r * 132 + c4v * 4) = p;
        uint4 x;
        x.x = rna(in4.x); x.y = rna(in4.y); x.z = rna(in4.z); x.w = rna(in4.w);
        *(uint4*)(s_x + r * 132 + c4v * 4) = x;
    }

    const int warp = tid >> 5, lane = tid & 31;
    const int wm = warp >> 1, wn = warp & 1;
    const int m0 = wm * 32, n0 = wn * 64;
    const int g = lane >> 2, q = lane & 3;
    (void)wn;

    float acc[2][8][4];

    #define FRAG_LOOP(...)                                               \
        _Pragma("unroll")                                                \
        for (int t = 0; t < 2; t++) {                                    \
            int r_ = m0 + t * 16 + g;                                    \
            _Pragma("unroll")                                            \
            for (int j = 0; j < 8; j++) {                                \
                int c0 = n0 + 8 * j + 2 * q;                             \
                int i0 = r_ * 132 + c0;                                  \
                int i2 = (r_ + 8) * 132 + c0;                            \
                (void)i0; (void)i2;                                      \
                __VA_ARGS__                                              \
            }                                                            \
        }

    acc_init_n(acc, res_b1, n0, q);
    gemm128(s_x, g_nw[0], s_B, acc, tid);
    FRAG_LOOP({
        s_x[i0]     = uif(rna(fmaxf(acc[t][j][0], 0.0f)));
        s_x[i0 + 1] = uif(rna(fmaxf(acc[t][j][1], 0.0f)));
        s_x[i2]     = uif(rna(fmaxf(acc[t][j][2], 0.0f)));
        s_x[i2 + 1] = uif(rna(fmaxf(acc[t][j][3], 0.0f)));
    })

    acc_init_n(acc, res_b2, n0, q);
    gemm128(s_x, g_nw[1], s_B, acc, tid);
    FRAG_LOOP({
        s_pres[i0]     = uif(rna(fmaxf(acc[t][j][0], 0.0f) + s_pres[i0]));
        s_pres[i0 + 1] = uif(rna(fmaxf(acc[t][j][1], 0.0f) + s_pres[i0 + 1]));
        s_pres[i2]     = uif(rna(fmaxf(acc[t][j][2], 0.0f) + s_pres[i2]));
        s_pres[i2 + 1] = uif(rna(fmaxf(acc[t][j][3], 0.0f) + s_pres[i2 + 1]));
    })

    acc_init_n(acc, nullptr, n0, q);
    gemm128(s_hemb, g_nw[7], s_B, acc, tid);
    FRAG_LOOP({
        s_x[i0]     = acc[t][j][0];
        s_x[i0 + 1] = acc[t][j][1];
        s_x[i2]     = acc[t][j][2];
        s_x[i2 + 1] = acc[t][j][3];
    })

    acc_init_n(acc, ir_b, n0, q);
    gemm128(s_pres, g_nw[2], s_B, acc, tid);
    gemm128(s_hemb, g_nw[3], s_B, acc, tid);
    FRAG_LOOP({
        s_x[i0]     = sigmoidf_(acc[t][j][0]) * s_x[i0];
        s_x[i0 + 1] = sigmoidf_(acc[t][j][1]) * s_x[i0 + 1];
        s_x[i2]     = sigmoidf_(acc[t][j][2]) * s_x[i2];
        s_x[i2 + 1] = sigmoidf_(acc[t][j][3]) * s_x[i2 + 1];
    })

    acc_init_n(acc, ii_b, n0, q);
    gemm128(s_pres, g_nw[4], s_B, acc, tid);
    gemm128(s_hemb, g_nw[5], s_B, acc, tid);
    FRAG_LOOP({
        s_hemb[i0]     = sigmoidf_(acc[t][j][0]);
        s_hemb[i0 + 1] = sigmoidf_(acc[t][j][1]);
        s_hemb[i2]     = sigmoidf_(acc[t][j][2]);
        s_hemb[i2 + 1] = sigmoidf_(acc[t][j][3]);
    })

    acc_init_n(acc, in_b, n0, q);
    gemm128(s_pres, g_nw[6], s_B, acc, tid);
    FRAG_LOOP({
        float n_0 = tanhf(acc[t][j][0] + s_x[i0]);
        float n_1 = tanhf(acc[t][j][1] + s_x[i0 + 1]);
        float n_2 = tanhf(acc[t][j][2] + s_x[i2]);
        float n_3 = tanhf(acc[t][j][3] + s_x[i2 + 1]);
        float i_0 = s_hemb[i0];
        float i_1 = s_hemb[i0 + 1];
        float i_2 = s_hemb[i2];
        float i_3 = s_hemb[i2 + 1];
        size_t go0 = (size_t)(row0 + r_) * HH + c0;
        size_t go2 = (size_t)(row0 + r_ + 8) * HH + c0;
        float2 h0 = *(const float2*)(hidden + go0);
        float2 h2 = *(const float2*)(hidden + go2);
        float2 nh0;
        float2 nh2;
        nh0.x = (1.0f - i_0) * n_0 + i_0 * h0.x;
        nh0.y = (1.0f - i_1) * n_1 + i_1 * h0.y;
        nh2.x = (1.0f - i_2) * n_2 + i_2 * h2.x;
        nh2.y = (1.0f - i_3) * n_3 + i_3 * h2.y;
        *(float2*)(out_hidden + go0) = nh0;
        *(float2*)(out_hidden + go2) = nh2;
        s_x[i0]     = uif(rna(nh0.x));
        s_x[i0 + 1] = uif(rna(nh0.y));
        s_x[i2]     = uif(rna(nh2.x));
        s_x[i2 + 1] = uif(rna(nh2.y));
    })

    acc_init_n(acc, out_b1, n0, q);
    gemm128(s_x, g_nw[8], s_B, acc, tid);
    FRAG_LOOP({
        s_hemb[i0]     = uif(rna(fmaxf(acc[t][j][0], 0.0f)));
        s_hemb[i0 + 1] = uif(rna(fmaxf(acc[t][j][1], 0.0f)));
        s_hemb[i2]     = uif(rna(fmaxf(acc[t][j][2], 0.0f)));
        s_hemb[i2 + 1] = uif(rna(fmaxf(acc[t][j][3], 0.0f)));
    })

    acc_init_n(acc, out_b2, n0, q);
    gemm128(s_hemb, g_nw[9], s_B, acc, tid);
    FRAG_LOOP({
        s_x[i0]     = uif(rna(fmaxf(acc[t][j][0], 0.0f)));
        s_x[i0 + 1] = uif(rna(fmaxf(acc[t][j][1], 0.0f)));
        s_x[i2]     = uif(rna(fmaxf(acc[t][j][2], 0.0f)));
        s_x[i2 + 1] = uif(rna(fmaxf(acc[t][j][3], 0.0f)));
    })

    acc_init_n(acc, out_b3, n0, q);
    gemm128(s_x, g_nw[10], s_B, acc, tid);
    FRAG_LOOP({
        size_t go0 = (size_t)(row0 + r_) * II + c0;
        size_t go2 = (size_t)(row0 + r_ + 8) * II + c0;
        float2 p0;
        float2 p2;
        p0.x = acc[t][j][0]; p0.y = acc[t][j][1];
        p2.x = acc[t][j][2]; p2.y = acc[t][j][3];
        *(float2*)(out_pred + go0) = p0;
        *(float2*)(out_pred + go2) = p2;
    })
    #undef FRAG_LOOP
}

// ---------------- launch ----------------
extern "C" void kernel_launch(void* const* d_in, const int* in_sizes, int n_in,
                              void* d_out, int out_size) {
    const float* inputs    = (const float*)d_in[0];
    const float* edge_attr = (const float*)d_in[1];
    const int*   send_e    = (const int*)  d_in[2];
    const int*   recv_e    = (const int*)  d_in[3];
    const float* hidden    = (const float*)d_in[4];
    const float* msg_w1 = (const float*)d_in[5];
    const float* msg_b1 = (const float*)d_in[6];
    const float* msg_w2 = (const float*)d_in[7];
    const float* msg_b2 = (const float*)d_in[8];
    const float* pm_w1  = (const float*)d_in[9];
    const float* pm_b1  = (const float*)d_in[10];
    const float* pm_w2  = (const float*)d_in[11];
    const float* pm_b2  = (const float*)d_in[12];
    const float* res_w1 = (const float*)d_in[13];
    const float* res_b1 = (const float*)d_in[14];
    const float* res_w2 = (const float*)d_in[15];
    const float* res_b2 = (const float*)d_in[16];
    const float* ir_w   = (const float*)d_in[17];
    const float* ir_b   = (const float*)d_in[18];
    const float* ii_w   = (const float*)d_in[19];
    const float* ii_b   = (const float*)d_in[20];
    const float* in_w   = (const float*)d_in[21];
    const float* in_b   = (const float*)d_in[22];
    const float* hr_w   = (const float*)d_in[23];
    const float* hi_w   = (const float*)d_in[24];
    const float* hh_w   = (const float*)d_in[25];
    const float* out_w1 = (const float*)d_in[26];
    const float* out_b1 = (const float*)d_in[27];
    const float* out_w2 = (const float*)d_in[28];
    const float* out_b2 = (const float*)d_in[29];
    const float* out_w3 = (const float*)d_in[30];
    const float* out_b3 = (const float*)d_in[31];

    float* out_pred   = (float*)d_out;
    float* out_hidden = (float*)d_out + (size_t)BB * NN * II;

    const int HM_SMEM = HM_SMEMF * 4;     // 102,400 B -> 2 CTAs/SM
    const int PM_SMEM = PM_SMEMF * 4;     // 101,888 B -> 2 CTAs/SM
    const int ND_SMEM = ND_SMEMF * 4;     // 219,648 B
    cudaFuncSetAttribute(hm_kernel, cudaFuncAttributeMaxDynamicSharedMemorySize, HM_SMEM);
    cudaFuncSetAttribute(pm_kernel, cudaFuncAttributeMaxDynamicSharedMemorySize, PM_SMEM);
    cudaFuncSetAttribute(node_kernel, cudaFuncAttributeMaxDynamicSharedMemorySize, ND_SMEM);

    zero_kernel<<<1024, 256>>>();
    count_kernel<<<EE / 256, 256>>>(recv_e);
    prep_kernel<<<128, 256>>>(msg_w1, msg_w2, pm_w1, pm_w2,
                              res_w1, res_w2, ir_w, hr_w, ii_w, hi_w,
                              in_w, hh_w, out_w1, out_w2, out_w3);

    hm_kernel<<<dim3(EE / 128, BB), 256, HM_SMEM>>>(hidden, send_e, recv_e, msg_b1, msg_b2);
    pm_kernel<<<dim3(EE / 128, BB), 256, PM_SMEM>>>(edge_attr, recv_e, pm_b1, pm_b2);

    node_kernel<<<(BB * NN) / 128, 256, ND_SMEM>>>(
        inputs, hidden,
        res_b1, res_b2, ir_b, ii_b, in_b,
        out_b1, out_b2, out_b3,
        out_pred, out_hidden);
}

// round 14
// speedup vs baseline: 4.1450x; 1.0558x over previous
#include <cuda_runtime.h>
#include <math.h>
#include <stdint.h>

// Problem constants
#define BB 4
#define NN 4096
#define EE 131072
#define II 128
#define HH 128
#define FF 140

// ---------------- scratch (__device__ globals; no allocs allowed) ----------
__device__ float g_hm_sum[(size_t)BB * NN * HH];   // 8 MB
__device__ float g_pm_sum[(size_t)BB * NN * HH];   // 8 MB
__device__ float g_hr[(size_t)BB * NN * HH];       // hidden @ W1_top + b1
__device__ float g_hs[(size_t)BB * NN * HH];       // hidden @ W1_bot
__device__ int   g_cnt[NN];

// legacy-permuted tf32 weights: w[k][ (n%8)*16 + n/8 ]
__device__ float g_w1tp[128 * 128];   // msg_w1 rows 0..127   (recv half)
__device__ float g_w1bp[128 * 128];   // msg_w1 rows 128..255 (send half)
__device__ float g_w2p[128 * 128];
__device__ float g_pw1p[160 * 128];   // K padded 140 -> 160 with zeros
__device__ float g_pw2p[128 * 128];
// node weights: 0:res_w1 1:res_w2 2:ir_w 3:hr_w 4:ii_w 5:hi_w 6:in_w 7:hh_w 8:out_w1 9:out_w2 10:out_w3
__device__ float g_nw[11][128 * 128];

__device__ __forceinline__ float sigmoidf_(float x) {
    return 1.0f / (1.0f + expf(-x));
}

__device__ __forceinline__ unsigned rna(float x) {
    unsigned r;
    asm("cvt.rna.tf32.f32 %0, %1;" : "=r"(r) : "f"(x));
    return r;
}
__device__ __forceinline__ float uif(unsigned x) { return __uint_as_float(x); }

__device__ __forceinline__ void mma8(float* c,
                                     unsigned a0, unsigned a1, unsigned a2, unsigned a3,
                                     unsigned b0, unsigned b1) {
    asm volatile(
        "mma.sync.aligned.m16n8k8.row.col.f32.tf32.tf32.f32 "
        "{%0,%1,%2,%3}, {%4,%5,%6,%7}, {%8,%9}, {%0,%1,%2,%3};"
        : "+f"(c[0]), "+f"(c[1]), "+f"(c[2]), "+f"(c[3])
        : "r"(a0), "r"(a1), "r"(a2), "r"(a3), "r"(b0), "r"(b1));
}

__device__ __forceinline__ void red4(float* p, float4 v) {
    asm volatile("red.global.add.v4.f32 [%0], {%1,%2,%3,%4};"
                 :: "l"(p), "f"(v.x), "f"(v.y), "f"(v.z), "f"(v.w) : "memory");
}

__device__ __forceinline__ void cpa16(uint32_t dst_smem, const void* src) {
    asm volatile("cp.async.cg.shared.global [%0], [%1], 16;"
                 :: "r"(dst_smem), "l"(src) : "memory");
}
#define CP_COMMIT() asm volatile("cp.async.commit_group;" ::: "memory")
#define CP_WAIT0()  asm volatile("cp.async.wait_group 0;" ::: "memory")

// ---------------- helper kernels ----------------

__global__ void zero_kernel() {
    const size_t M = (size_t)BB * NN * HH;
    size_t stride = (size_t)gridDim.x * blockDim.x;
    size_t i = (size_t)blockIdx.x * blockDim.x + threadIdx.x;
    for (size_t j = i; j < M; j += stride) {
        g_hm_sum[j] = 0.0f;
        g_pm_sum[j] = 0.0f;
    }
    if (i < NN) g_cnt[i] = 0;
}

__global__ void count_kernel(const int* __restrict__ recv_e) {
    int e = blockIdx.x * blockDim.x + threadIdx.x;
    if (e < EE) atomicAdd(&g_cnt[recv_e[e]], 1);
}

__global__ void prep_kernel(const float* __restrict__ mw1,
                            const float* __restrict__ mw2,
                            const float* __restrict__ pw1,
                            const float* __restrict__ pw2,
                            const float* __restrict__ res_w1,
                            const float* __restrict__ res_w2,
                            const float* __restrict__ ir_w,
                            const float* __restrict__ hr_w,
                            const float* __restrict__ ii_w,
                            const float* __restrict__ hi_w,
                            const float* __restrict__ in_w,
                            const float* __restrict__ hh_w,
                            const float* __restrict__ out_w1,
                            const float* __restrict__ out_w2,
                            const float* __restrict__ out_w3) {
    int i = blockIdx.x * blockDim.x + threadIdx.x;   // up to 32768
    if (i < 128 * 128) {
        int k = i >> 7, n = i & 127;
        int s = k * 128 + ((n & 7) * 16 + (n >> 3));
        g_w1tp[s] = uif(rna(mw1[i]));                 // rows 0..127
        g_w1bp[s] = uif(rna(mw1[128 * 128 + i]));     // rows 128..255
        g_w2p[s]  = uif(rna(mw2[i]));
        g_pw2p[s] = uif(rna(pw2[i]));
        g_nw[0][s]  = uif(rna(res_w1[i]));
        g_nw[1][s]  = uif(rna(res_w2[i]));
        g_nw[2][s]  = uif(rna(ir_w[i]));
        g_nw[3][s]  = uif(rna(hr_w[i]));
        g_nw[4][s]  = uif(rna(ii_w[i]));
        g_nw[5][s]  = uif(rna(hi_w[i]));
        g_nw[6][s]  = uif(rna(in_w[i]));
        g_nw[7][s]  = uif(rna(hh_w[i]));
        g_nw[8][s]  = uif(rna(out_w1[i]));
        g_nw[9][s]  = uif(rna(out_w2[i]));
        g_nw[10][s] = uif(rna(out_w3[i]));
    }
    if (i < 160 * 128) {
        int k = i >> 7, n = i & 127;
        float v = (k < 140) ? pw1[i] : 0.0f;
        g_pw1p[k * 128 + ((n & 7) * 16 + (n >> 3))] = uif(rna(v));
    }
}

// ---------------- shared legacy-mma machinery ----------------
#define EK_AB(buf)  ((buf) * (128 * 36))
#define EK_B(buf)   (128 * 132 + (buf) * (32 * 132))
#define EK_IDX      (128 * 132 + 2 * 32 * 132)
#define HM_SMEMF    (EK_IDX + 256)                    // 102,400 B
#define PM_SMEMF    (EK_IDX + 128)                    // 101,888 B

#define CHUNK_MMA(ACC, Ab, Ap, kofs, Bb)                                     \
    {                                                                        \
        const unsigned* Au_ = (const unsigned*)(sm + (Ab));                  \
        const float4*   B4_ = (const float4*)(sm + (Bb));                    \
        _Pragma("unroll")                                                    \
        for (int ks = 0; ks < 4; ks++) {                                     \
            int kr = ks * 8;                                                 \
            int bb0 = (kr + q) * 33 + g * 4 + wn * 2;                        \
            int bb1 = (kr + q + 4) * 33 + g * 4 + wn * 2;                    \
            float4 u0 = B4_[bb0], u1 = B4_[bb0 + 1];                         \
            float4 v0 = B4_[bb1], v1 = B4_[bb1 + 1];                         \
            unsigned bu[8] = {__float_as_uint(u0.x), __float_as_uint(u0.y),  \
                              __float_as_uint(u0.z), __float_as_uint(u0.w),  \
                              __float_as_uint(u1.x), __float_as_uint(u1.y),  \
                              __float_as_uint(u1.z), __float_as_uint(u1.w)}; \
            unsigned bv[8] = {__float_as_uint(v0.x), __float_as_uint(v0.y),  \
                              __float_as_uint(v0.z), __float_as_uint(v0.w),  \
                              __float_as_uint(v1.x), __float_as_uint(v1.y),  \
                              __float_as_uint(v1.z), __float_as_uint(v1.w)}; \
            _Pragma("unroll")                                                \
            for (int t = 0; t < 2; t++) {                                    \
                int r0 = (m0 + t * 16 + g) * (Ap) + (kofs) + kr + q;         \
                unsigned a0 = Au_[r0], a1 = Au_[r0 + 8 * (Ap)];              \
                unsigned a2 = Au_[r0 + 4], a3 = Au_[r0 + 8 * (Ap) + 4];      \
                _Pragma("unroll")                                            \
                for (int j = 0; j < 8; j++)                                  \
                    mma8(ACC[t][j], a0, a1, a2, a3, bu[j], bv[j]);           \
            }                                                                \
        }                                                                    \
    }

#define ACC_INIT(ACC, BIAS)                                                  \
    _Pragma("unroll")                                                        \
    for (int j = 0; j < 8; j++) {                                            \
        int c0 = n0 + 8 * j + 2 * q;                                         \
        float b0v = __ldg((BIAS) + c0), b1v = __ldg((BIAS) + c0 + 1);        \
        _Pragma("unroll")                                                    \
        for (int t = 0; t < 2; t++) {                                        \
            ACC[t][j][0] = b0v; ACC[t][j][1] = b1v;                          \
            ACC[t][j][2] = b0v; ACC[t][j][3] = b1v;                          \
        }                                                                    \
    }

#define B_CPASYNC(dstbuf, WSRC)                                              \
    {                                                                        \
        const float4* wsrc_ = (WSRC);                                        \
        _Pragma("unroll")                                                    \
        for (int i = 0; i < 4; i++) {                                        \
            int it = tid + i * 256;                                          \
            int r = it >> 5, c = it & 31;                                    \
            cpa16(smem_u32 + (uint32_t)((EK_B(dstbuf) + r * 132 + c * 4) * 4), \
                  wsrc_ + r * 32 + c);                                       \
        }                                                                    \
        CP_COMMIT();                                                         \
    }

// ---------------- hm_pre: H_r = hidden@W1_top + b1 ; H_s = hidden@W1_bot ----
// 128 rows/CTA. smem: s_x[128*132] | s_B[32*132]
#define HP_X 0
#define HP_B (128 * 132)
#define HP_SMEMF (HP_B + 32 * 132)     // 84,480 B

__device__ __forceinline__ void gemm128s(const float* As, const float* Wg, float* sB,
                                         float acc[2][8][4], int tid) {
    const int warp = tid >> 5, lane = tid & 31;
    const int wm = warp >> 1, wn = warp & 1;
    const int m0 = wm * 32;
    const int g = lane >> 2, q = lane & 3;

    #pragma unroll 1
    for (int c2 = 0; c2 < 4; c2++) {
        __syncthreads();
        const float4* wsrc = (const float4*)Wg + c2 * 32 * 32;
        #pragma unroll
        for (int i = 0; i < 4; i++) {
            int it = tid + i * 256;
            int r = it >> 5, c = it & 31;
            *(float4*)(sB + r * 132 + c * 4) = wsrc[r * 32 + c];
        }
        __syncthreads();

        const unsigned* Mu = (const unsigned*)As;
        const float4*   B4 = (const float4*)sB;
        #pragma unroll
        for (int ks = 0; ks < 4; ks++) {
            int kr = ks * 8;
            int bb0 = (kr + q) * 33 + g * 4 + wn * 2;
            int bb1 = (kr + q + 4) * 33 + g * 4 + wn * 2;
            float4 u0 = B4[bb0], u1 = B4[bb0 + 1];
            float4 v0 = B4[bb1], v1 = B4[bb1 + 1];
            unsigned bu[8] = {__float_as_uint(u0.x), __float_as_uint(u0.y),
                              __float_as_uint(u0.z), __float_as_uint(u0.w),
                              __float_as_uint(u1.x), __float_as_uint(u1.y),
                              __float_as_uint(u1.z), __float_as_uint(u1.w)};
            unsigned bv[8] = {__float_as_uint(v0.x), __float_as_uint(v0.y),
                              __float_as_uint(v0.z), __float_as_uint(v0.w),
                              __float_as_uint(v1.x), __float_as_uint(v1.y),
                              __float_as_uint(v1.z), __float_as_uint(v1.w)};
            #pragma unroll
            for (int t = 0; t < 2; t++) {
                int r0 = (m0 + t * 16 + g) * 132 + c2 * 32 + kr + q;
                unsigned a0 = Mu[r0], a1 = Mu[r0 + 8 * 132];
                unsigned a2 = Mu[r0 + 4], a3 = Mu[r0 + 8 * 132 + 4];
                #pragma unroll
                for (int j = 0; j < 8; j++) mma8(acc[t][j], a0, a1, a2, a3, bu[j], bv[j]);
            }
        }
    }
    __syncthreads();
}

__global__ void __launch_bounds__(256) hm_pre_kernel(
    const float* __restrict__ hidden,
    const float* __restrict__ mb1)
{
    extern __shared__ __align__(16) float sm[];
    float* s_x = sm + HP_X;
    float* s_B = sm + HP_B;

    const int tid  = threadIdx.x;
    const int row0 = blockIdx.x * 128;   // linear row in [0, BB*NN)

    #pragma unroll
    for (int i = 0; i < 16; i++) {
        int it = tid + i * 256;
        int r = it >> 5, c4v = it & 31;
        float4 h = *(const float4*)(hidden + (size_t)(row0 + r) * HH + c4v * 4);
        uint4 x; x.x = rna(h.x); x.y = rna(h.y); x.z = rna(h.z); x.w = rna(h.w);
        *(uint4*)(s_x + r * 132 + c4v * 4) = x;
    }

    const int warp = tid >> 5, lane = tid & 31;
    const int wm = warp >> 1, wn = warp & 1;
    const int m0 = wm * 32, n0 = wn * 64;
    const int g = lane >> 2, q = lane & 3;

    float acc[2][8][4];

    // H_r = x @ W1_top + b1
    ACC_INIT(acc, mb1)
    gemm128s(s_x, g_w1tp, s_B, acc, tid);
    #pragma unroll
    for (int t = 0; t < 2; t++) {
        int r_ = m0 + t * 16 + g;
        #pragma unroll
        for (int j = 0; j < 8; j++) {
            int c0 = n0 + 8 * j + 2 * q;
            float2 p0, p2;
            p0.x = acc[t][j][0]; p0.y = acc[t][j][1];
            p2.x = acc[t][j][2]; p2.y = acc[t][j][3];
            *(float2*)(g_hr + (size_t)(row0 + r_) * HH + c0) = p0;
            *(float2*)(g_hr + (size_t)(row0 + r_ + 8) * HH + c0) = p2;
        }
    }

    // H_s = x @ W1_bot
    #pragma unroll
    for (int j = 0; j < 8; j++)
        #pragma unroll
        for (int t = 0; t < 2; t++) {
            acc[t][j][0] = 0.0f; acc[t][j][1] = 0.0f;
            acc[t][j][2] = 0.0f; acc[t][j][3] = 0.0f;
        }
    gemm128s(s_x, g_w1bp, s_B, acc, tid);
    #pragma unroll
    for (int t = 0; t < 2; t++) {
        int r_ = m0 + t * 16 + g;
        #pragma unroll
        for (int j = 0; j < 8; j++) {
            int c0 = n0 + 8 * j + 2 * q;
            float2 p0, p2;
            p0.x = acc[t][j][0]; p0.y = acc[t][j][1];
            p2.x = acc[t][j][2]; p2.y = acc[t][j][3];
            *(float2*)(g_hs + (size_t)(row0 + r_) * HH + c0) = p0;
            *(float2*)(g_hs + (size_t)(row0 + r_ + 8) * HH + c0) = p2;
        }
    }
}

// ---------------- hm edge kernel (factored layer 1 + legacy layer 2) --------
__global__ void __launch_bounds__(256, 2) hm_kernel(
    const int* __restrict__ send_e, const int* __restrict__ recv_e,
    const float* __restrict__ mb2)
{
    extern __shared__ __align__(16) float sm[];
    int* s_recv = (int*)(sm + EK_IDX);
    int* s_send = s_recv + 128;

    const int tid = threadIdx.x;
    const int b   = blockIdx.y;
    const int e0  = blockIdx.x * 128;
    const uint32_t smem_u32 = (uint32_t)__cvta_generic_to_shared(sm);

    if (tid < 128) s_recv[tid] = recv_e[e0 + tid];
    else           s_send[tid - 128] = send_e[e0 + tid - 128];

    const int warp = tid >> 5, lane = tid & 31;
    const int wm = warp >> 1, wn = warp & 1;
    const int m0 = wm * 32, n0 = wn * 64;
    const int g = lane >> 2, q = lane & 3;

    float acc2[2][8][4];
    ACC_INIT(acc2, mb2)
    B_CPASYNC(0, (const float4*)g_w2p)
    __syncthreads();   // idx visible

    // ---- stage mid = rna(tanh(H_r[recv] + H_s[send])) ----
    {
        const float* hr = g_hr + (size_t)b * NN * HH;
        const float* hs = g_hs + (size_t)b * NN * HH;
        const int er = tid >> 1, hf = (tid & 1) * 64;
        const float* pr = hr + (size_t)s_recv[er] * HH + hf;
        const float* ps = hs + (size_t)s_send[er] * HH + hf;
        float* dst = sm + er * 132 + hf;
        #pragma unroll
        for (int v = 0; v < 16; v++) {
            float4 a = *(const float4*)(pr + v * 4);
            float4 c = *(const float4*)(ps + v * 4);
            uint4 r;
            r.x = rna(tanhf(a.x + c.x));
            r.y = rna(tanhf(a.y + c.y));
            r.z = rna(tanhf(a.z + c.z));
            r.w = rna(tanhf(a.w + c.w));
            *(uint4*)(dst + v * 4) = r;
        }
    }
    CP_WAIT0();
    __syncthreads();

    // ---- layer 2: 4 chunks, pipelined B ----
    #pragma unroll 1
    for (int c2 = 0; c2 < 4; c2++) {
        const int cur = c2 & 1, nxt = cur ^ 1;
        const bool has = (c2 + 1) < 4;
        if (has) B_CPASYNC(nxt, (const float4*)g_w2p + (c2 + 1) * 32 * 32)
        CHUNK_MMA(acc2, 0, 132, c2 * 32, EK_B(cur))
        if (has) CP_WAIT0();
        __syncthreads();
    }

    // ---- epilogue -> mid, scatter ----
    #pragma unroll
    for (int t = 0; t < 2; t++) {
        int r = m0 + t * 16 + g;
        #pragma unroll
        for (int j = 0; j < 8; j++) {
            int c0 = n0 + 8 * j + 2 * q;
            sm[r * 132 + c0]           = tanhf(acc2[t][j][0]);
            sm[r * 132 + c0 + 1]       = tanhf(acc2[t][j][1]);
            sm[(r + 8) * 132 + c0]     = tanhf(acc2[t][j][2]);
            sm[(r + 8) * 132 + c0 + 1] = tanhf(acc2[t][j][3]);
        }
    }
    __syncthreads();

    float* dst = g_hm_sum + (size_t)b * NN * HH;
    const int c4 = tid & 31;
    #pragma unroll 1
    for (int e = tid >> 5; e < 128; e += 8) {
        float4 v = *(const float4*)(sm + e * 132 + c4 * 4);
        red4(dst + (size_t)s_recv[e] * HH + c4 * 4, v);
    }
}

// ---------------- pm edge kernel (legacy pipelined tf32, proven R12) --------
__global__ void __launch_bounds__(256, 2) pm_kernel(
    const float* __restrict__ edge_attr,
    const int* __restrict__ recv_e,
    const float* __restrict__ pb1, const float* __restrict__ pb2)
{
    extern __shared__ __align__(16) float sm[];
    int* s_recv = (int*)(sm + EK_IDX);

    const int tid = threadIdx.x;
    const int b   = blockIdx.y;
    const int e0  = blockIdx.x * 128;
    const uint32_t smem_u32 = (uint32_t)__cvta_generic_to_shared(sm);

    if (tid < 128) s_recv[tid] = recv_e[e0 + tid];

    const int warp = tid >> 5, lane = tid & 31;
    const int wm = warp >> 1, wn = warp & 1;
    const int m0 = wm * 32, n0 = wn * 64;
    const int g = lane >> 2, q = lane & 3;
    const int se = tid >> 3, sv = tid & 7;

    float acc[2][8][4];
    ACC_INIT(acc, pb1)

    const float* ea = edge_attr + ((size_t)b * EE + e0) * FF;

    {
        #pragma unroll
        for (int i = 0; i < 4; i++) {
            int e = se + i * 32;
            int f = sv * 4;
            float4 fv = *(const float4*)(ea + (size_t)e * FF + f);
            uint4 r; r.x = rna(fv.x); r.y = rna(fv.y); r.z = rna(fv.z); r.w = rna(fv.w);
            *(uint4*)(sm + EK_AB(0) + e * 36 + sv * 4) = r;
        }
        B_CPASYNC(0, (const float4*)g_pw1p)
        CP_WAIT0();
    }
    __syncthreads();

    #pragma unroll 1
    for (int kc = 0; kc < 5; kc++) {
        const int cur = kc & 1, nxt = cur ^ 1;
        const bool has = (kc + 1) < 5;
        float4 pf[4];
        if (has) {
            const int k0 = (kc + 1) * 32;
            #pragma unroll
            for (int i = 0; i < 4; i++) {
                int e = se + i * 32;
                int f = k0 + sv * 4;
                if (f < FF) pf[i] = *(const float4*)(ea + (size_t)e * FF + f);
                else { pf[i].x = 0.0f; pf[i].y = 0.0f; pf[i].z = 0.0f; pf[i].w = 0.0f; }
            }
            B_CPASYNC(nxt, (const float4*)g_pw1p + (kc + 1) * 32 * 32)
        }
        CHUNK_MMA(acc, EK_AB(cur), 36, 0, EK_B(cur))
        if (has) {
            #pragma unroll
            for (int i = 0; i < 4; i++) {
                int e = se + i * 32;
                uint4 r;
                r.x = rna(pf[i].x); r.y = rna(pf[i].y);
                r.z = rna(pf[i].z); r.w = rna(pf[i].w);
                *(uint4*)(sm + EK_AB(nxt) + e * 36 + sv * 4) = r;
            }
            CP_WAIT0();
        }
        __syncthreads();
    }

    B_CPASYNC(0, (const float4*)g_pw2p)
    #pragma unroll
    for (int t = 0; t < 2; t++) {
        int r = m0 + t * 16 + g;
        #pragma unroll
        for (int j = 0; j < 8; j++) {
            int c0 = n0 + 8 * j + 2 * q;
            sm[r * 132 + c0]           = uif(rna(fmaxf(acc[t][j][0], 0.0f)));
            sm[r * 132 + c0 + 1]       = uif(rna(fmaxf(acc[t][j][1], 0.0f)));
            sm[(r + 8) * 132 + c0]     = uif(rna(fmaxf(acc[t][j][2], 0.0f)));
            sm[(r + 8) * 132 + c0 + 1] = uif(rna(fmaxf(acc[t][j][3], 0.0f)));
        }
    }
    float acc2[2][8][4];
    ACC_INIT(acc2, pb2)
    CP_WAIT0();
    __syncthreads();

    #pragma unroll 1
    for (int c2 = 0; c2 < 4; c2++) {
        const int cur = c2 & 1, nxt = cur ^ 1;
        const bool has = (c2 + 1) < 4;
        if (has) B_CPASYNC(nxt, (const float4*)g_pw2p + (c2 + 1) * 32 * 32)
        CHUNK_MMA(acc2, 0, 132, c2 * 32, EK_B(cur))
        if (has) CP_WAIT0();
        __syncthreads();
    }

    #pragma unroll
    for (int t = 0; t < 2; t++) {
        int r = m0 + t * 16 + g;
        #pragma unroll
        for (int j = 0; j < 8; j++) {
            int c0 = n0 + 8 * j + 2 * q;
            sm[r * 132 + c0]           = fmaxf(acc2[t][j][0], 0.0f);
            sm[r * 132 + c0 + 1]       = fmaxf(acc2[t][j][1], 0.0f);
            sm[(r + 8) * 132 + c0]     = fmaxf(acc2[t][j][2], 0.0f);
            sm[(r + 8) * 132 + c0 + 1] = fmaxf(acc2[t][j][3], 0.0f);
        }
    }
    __syncthreads();

    float* dst = g_pm_sum + (size_t)b * NN * HH;
    const int c4 = tid & 31;
    #pragma unroll 1
    for (int e = tid >> 5; e < 128; e += 8) {
        float4 v = *(const float4*)(sm + e * 132 + c4 * 4);
        red4(dst + (size_t)s_recv[e] * HH + c4 * 4, v);
    }
}

// ---------------- node kernel (tf32 legacy, proven) ----------------
#define ND_PRES 0
#define ND_HEMB (128 * 132)
#define ND_X    (2 * 128 * 132)
#define ND_B    (3 * 128 * 132)
#define ND_SMEMF (ND_B + 32 * 132)

__device__ __forceinline__ void acc_init_n(float acc[2][8][4], const float* bias,
                                           int n0, int q) {
    #pragma unroll
    for (int j = 0; j < 8; j++) {
        float b0v = 0.0f, b1v = 0.0f;
        if (bias) {
            int c0 = n0 + 8 * j + 2 * q;
            b0v = __ldg(bias + c0); b1v = __ldg(bias + c0 + 1);
        }
        #pragma unroll
        for (int t = 0; t < 2; t++) {
            acc[t][j][0] = b0v; acc[t][j][1] = b1v;
            acc[t][j][2] = b0v; acc[t][j][3] = b1v;
        }
    }
}

__global__ void __launch_bounds__(256) node_kernel(
    const float* __restrict__ inputs,
    const float* __restrict__ hidden,
    const float* __restrict__ res_b1, const float* __restrict__ res_b2,
    const float* __restrict__ ir_b,   const float* __restrict__ ii_b,
    const float* __restrict__ in_b,
    const float* __restrict__ out_b1, const float* __restrict__ out_b2,
    const float* __restrict__ out_b3,
    float* __restrict__ out_pred,
    float* __restrict__ out_hidden)
{
    extern __shared__ __align__(16) float sm[];
    float* s_pres = sm + ND_PRES;
    float* s_hemb = sm + ND_HEMB;
    float* s_x    = sm + ND_X;
    float* s_B    = sm + ND_B;

    const int tid  = threadIdx.x;
    const int row0 = blockIdx.x * 128;

    #pragma unroll
    for (int i = 0; i < 16; i++) {
        int it = tid + i * 256;
        int r = it >> 5, c4v = it & 31;
        size_t off = (size_t)(row0 + r) * HH + c4v * 4;
        float invc = 1.0f / fmaxf((float)__ldg(&g_cnt[(row0 + r) & (NN - 1)]), 1.0f);
        float4 hm4 = *(const float4*)(g_hm_sum + off);
        float4 pm4 = *(const float4*)(g_pm_sum + off);
        float4 in4 = *(const float4*)(inputs + off);
        uint4 a;
        a.x = rna(hm4.x * invc); a.y = rna(hm4.y * invc);
        a.z = rna(hm4.z * invc); a.w = rna(hm4.w * invc);
        *(uint4*)(s_hemb + r * 132 + c4v * 4) = a;
        float4 p;
        p.x = pm4.x * invc; p.y = pm4.y * invc; p.z = pm4.z * invc; p.w = pm4.w * invc;
        *(float4*)(s_pres + r * 132 + c4v * 4) = p;
        uint4 x;
        x.x = rna(in4.x); x.y = rna(in4.y); x.z = rna(in4.z); x.w = rna(in4.w);
        *(uint4*)(s_x + r * 132 + c4v * 4) = x;
    }

    const int warp = tid >> 5, lane = tid & 31;
    const int wm = warp >> 1, wn = warp & 1;
    const int m0 = wm * 32, n0 = wn * 64;
    const int g = lane >> 2, q = lane & 3;
    (void)wn;

    float acc[2][8][4];

    #define FRAG_LOOP(...)                                               \
        _Pragma("unroll")                                                \
        for (int t = 0; t < 2; t++) {                                    \
            int r_ = m0 + t * 16 + g;                                    \
            _Pragma("unroll")                                            \
            for (int j = 0; j < 8; j++) {                                \
                int c0 = n0 + 8 * j + 2 * q;                             \
                int i0 = r_ * 132 + c0;                                  \
                int i2 = (r_ + 8) * 132 + c0;                            \
                (void)i0; (void)i2;                                      \
                __VA_ARGS__                                              \
            }                                                            \
        }

    acc_init_n(acc, res_b1, n0, q);
    gemm128s(s_x, g_nw[0], s_B, acc, tid);
    FRAG_LOOP({
        s_x[i0]     = uif(rna(fmaxf(acc[t][j][0], 0.0f)));
        s_x[i0 + 1] = uif(rna(fmaxf(acc[t][j][1], 0.0f)));
        s_x[i2]     = uif(rna(fmaxf(acc[t][j][2], 0.0f)));
        s_x[i2 + 1] = uif(rna(fmaxf(acc[t][j][3], 0.0f)));
    })

    acc_init_n(acc, res_b2, n0, q);
    gemm128s(s_x, g_nw[1], s_B, acc, tid);
    FRAG_LOOP({
        s_pres[i0]     = uif(rna(fmaxf(acc[t][j][0], 0.0f) + s_pres[i0]));
        s_pres[i0 + 1] = uif(rna(fmaxf(acc[t][j][1], 0.0f) + s_pres[i0 + 1]));
        s_pres[i2]     = uif(rna(fmaxf(acc[t][j][2], 0.0f) + s_pres[i2]));
        s_pres[i2 + 1] = uif(rna(fmaxf(acc[t][j][3], 0.0f) + s_pres[i2 + 1]));
    })

    acc_init_n(acc, nullptr, n0, q);
    gemm128s(s_hemb, g_nw[7], s_B, acc, tid);
    FRAG_LOOP({
        s_x[i0]     = acc[t][j][0];
        s_x[i0 + 1] = acc[t][j][1];
        s_x[i2]     = acc[t][j][2];
        s_x[i2 + 1] = acc[t][j][3];
    })

    acc_init_n(acc, ir_b, n0, q);
    gemm128s(s_pres, g_nw[2], s_B, acc, tid);
    gemm128s(s_hemb, g_nw[3], s_B, acc, tid);
    FRAG_LOOP({
        s_x[i0]     = sigmoidf_(acc[t][j][0]) * s_x[i0];
        s_x[i0 + 1] = sigmoidf_(acc[t][j][1]) * s_x[i0 + 1];
        s_x[i2]     = sigmoidf_(acc[t][j][2]) * s_x[i2];
        s_x[i2 + 1] = sigmoidf_(acc[t][j][3]) * s_x[i2 + 1];
    })

    acc_init_n(acc, ii_b, n0, q);
    gemm128s(s_pres, g_nw[4], s_B, acc, tid);
    gemm128s(s_hemb, g_nw[5], s_B, acc, tid);
    FRAG_LOOP({
        s_hemb[i0]     = sigmoidf_(acc[t][j][0]);
        s_hemb[i0 + 1] = sigmoidf_(acc[t][j][1]);
        s_hemb[i2]     = sigmoidf_(acc[t][j][2]);
        s_hemb[i2 + 1] = sigmoidf_(acc[t][j][3]);
    })

    acc_init_n(acc, in_b, n0, q);
    gemm128s(s_pres, g_nw[6], s_B, acc, tid);
    FRAG_LOOP({
        float n_0 = tanhf(acc[t][j][0] + s_x[i0]);
        float n_1 = tanhf(acc[t][j][1] + s_x[i0 + 1]);
        float n_2 = tanhf(acc[t][j][2] + s_x[i2]);
        float n_3 = tanhf(acc[t][j][3] + s_x[i2 + 1]);
        float i_0 = s_hemb[i0];
        float i_1 = s_hemb[i0 + 1];
        float i_2 = s_hemb[i2];
        float i_3 = s_hemb[i2 + 1];
        size_t go0 = (size_t)(row0 + r_) * HH + c0;
        size_t go2 = (size_t)(row0 + r_ + 8) * HH + c0;
        float2 h0 = *(const float2*)(hidden + go0);
        float2 h2 = *(const float2*)(hidden + go2);
        float2 nh0;
        float2 nh2;
        nh0.x = (1.0f - i_0) * n_0 + i_0 * h0.x;
        nh0.y = (1.0f - i_1) * n_1 + i_1 * h0.y;
        nh2.x = (1.0f - i_2) * n_2 + i_2 * h2.x;
        nh2.y = (1.0f - i_3) * n_3 + i_3 * h2.y;
        *(float2*)(out_hidden + go0) = nh0;
        *(float2*)(out_hidden + go2) = nh2;
        s_x[i0]     = uif(rna(nh0.x));
        s_x[i0 + 1] = uif(rna(nh0.y));
        s_x[i2]     = uif(rna(nh2.x));
        s_x[i2 + 1] = uif(rna(nh2.y));
    })

    acc_init_n(acc, out_b1, n0, q);
    gemm128s(s_x, g_nw[8], s_B, acc, tid);
    FRAG_LOOP({
        s_hemb[i0]     = uif(rna(fmaxf(acc[t][j][0], 0.0f)));
        s_hemb[i0 + 1] = uif(rna(fmaxf(acc[t][j][1], 0.0f)));
        s_hemb[i2]     = uif(rna(fmaxf(acc[t][j][2], 0.0f)));
        s_hemb[i2 + 1] = uif(rna(fmaxf(acc[t][j][3], 0.0f)));
    })

    acc_init_n(acc, out_b2, n0, q);
    gemm128s(s_hemb, g_nw[9], s_B, acc, tid);
    FRAG_LOOP({
        s_x[i0]     = uif(rna(fmaxf(acc[t][j][0], 0.0f)));
        s_x[i0 + 1] = uif(rna(fmaxf(acc[t][j][1], 0.0f)));
        s_x[i2]     = uif(rna(fmaxf(acc[t][j][2], 0.0f)));
        s_x[i2 + 1] = uif(rna(fmaxf(acc[t][j][3], 0.0f)));
    })

    acc_init_n(acc, out_b3, n0, q);
    gemm128s(s_x, g_nw[10], s_B, acc, tid);
    FRAG_LOOP({
        size_t go0 = (size_t)(row0 + r_) * II + c0;
        size_t go2 = (size_t)(row0 + r_ + 8) * II + c0;
        float2 p0;
        float2 p2;
        p0.x = acc[t][j][0]; p0.y = acc[t][j][1];
        p2.x = acc[t][j][2]; p2.y = acc[t][j][3];
        *(float2*)(out_pred + go0) = p0;
        *(float2*)(out_pred + go2) = p2;
    })
    #undef FRAG_LOOP
}

// ---------------- launch ----------------
extern "C" void kernel_launch(void* const* d_in, const int* in_sizes, int n_in,
                              void* d_out, int out_size) {
    const float* inputs    = (const float*)d_in[0];
    const float* edge_attr = (const float*)d_in[1];
    const int*   send_e    = (const int*)  d_in[2];
    const int*   recv_e    = (const int*)  d_in[3];
    const float* hidden    = (const float*)d_in[4];
    const float* msg_w1 = (const float*)d_in[5];
    const float* msg_b1 = (const float*)d_in[6];
    const float* msg_w2 = (const float*)d_in[7];
    const float* msg_b2 = (const float*)d_in[8];
    const float* pm_w1  = (const float*)d_in[9];
    const float* pm_b1  = (const float*)d_in[10];
    const float* pm_w2  = (const float*)d_in[11];
    const float* pm_b2  = (const float*)d_in[12];
    const float* res_w1 = (const float*)d_in[13];
    const float* res_b1 = (const float*)d_in[14];
    const float* res_w2 = (const float*)d_in[15];
    const float* res_b2 = (const float*)d_in[16];
    const float* ir_w   = (const float*)d_in[17];
    const float* ir_b   = (const float*)d_in[18];
    const float* ii_w   = (const float*)d_in[19];
    const float* ii_b   = (const float*)d_in[20];
    const float* in_w   = (const float*)d_in[21];
    const float* in_b   = (const float*)d_in[22];
    const float* hr_w   = (const float*)d_in[23];
    const float* hi_w   = (const float*)d_in[24];
    const float* hh_w   = (const float*)d_in[25];
    const float* out_w1 = (const float*)d_in[26];
    const float* out_b1 = (const float*)d_in[27];
    const float* out_w2 = (const float*)d_in[28];
    const float* out_b2 = (const float*)d_in[29];
    const float* out_w3 = (const float*)d_in[30];
    const float* out_b3 = (const float*)d_in[31];

    float* out_pred   = (float*)d_out;
    float* out_hidden = (float*)d_out + (size_t)BB * NN * II;

    const int HM_SMEM = HM_SMEMF * 4;     // 102,400 B -> 2 CTAs/SM
    const int PM_SMEM = PM_SMEMF * 4;     // 101,888 B -> 2 CTAs/SM
    const int HP_SMEM = HP_SMEMF * 4;     //  84,480 B
    const int ND_SMEM = ND_SMEMF * 4;     // 219,648 B
    cudaFuncSetAttribute(hm_kernel, cudaFuncAttributeMaxDynamicSharedMemorySize, HM_SMEM);
    cudaFuncSetAttribute(pm_kernel, cudaFuncAttributeMaxDynamicSharedMemorySize, PM_SMEM);
    cudaFuncSetAttribute(hm_pre_kernel, cudaFuncAttributeMaxDynamicSharedMemorySize, HP_SMEM);
    cudaFuncSetAttribute(node_kernel, cudaFuncAttributeMaxDynamicSharedMemorySize, ND_SMEM);

    zero_kernel<<<1024, 256>>>();
    count_kernel<<<EE / 256, 256>>>(recv_e);
    prep_kernel<<<128, 256>>>(msg_w1, msg_w2, pm_w1, pm_w2,
                              res_w1, res_w2, ir_w, hr_w, ii_w, hi_w,
                              in_w, hh_w, out_w1, out_w2, out_w3);

    hm_pre_kernel<<<(BB * NN) / 128, 256, HP_SMEM>>>(hidden, msg_b1);
    hm_kernel<<<dim3(EE / 128, BB), 256, HM_SMEM>>>(send_e, recv_e, msg_b2);
    pm_kernel<<<dim3(EE / 128, BB), 256, PM_SMEM>>>(edge_attr, recv_e, pm_b1, pm_b2);

    node_kernel<<<(BB * NN) / 128, 256, ND_SMEM>>>(
        inputs, hidden,
        res_b1, res_b2, ir_b, ii_b, in_b,
        out_b1, out_b2, out_b3,
        out_pred, out_hidden);
}

// round 15
// speedup vs baseline: 4.7313x; 1.1414x over previous
#include <cuda_runtime.h>
#include <math.h>
#include <stdint.h>

// Problem constants
#define BB 4
#define NN 4096
#define EE 131072
#define II 128
#define HH 128
#define FF 140

// ---------------- scratch (__device__ globals; no allocs allowed) ----------
__device__ float g_hm_sum[(size_t)BB * NN * HH];   // 8 MB
__device__ float g_pm_sum[(size_t)BB * NN * HH];   // 8 MB
__device__ float g_hr[(size_t)BB * NN * HH];       // hidden @ W1_top + b1
__device__ float g_hs[(size_t)BB * NN * HH];       // hidden @ W1_bot
__device__ int   g_cnt[NN];

// legacy-permuted tf32 weights: w[k][ (n%8)*16 + n/8 ]
__device__ float g_w1tp[128 * 128];   // msg_w1 rows 0..127   (recv half)
__device__ float g_w1bp[128 * 128];   // msg_w1 rows 128..255 (send half)
__device__ float g_w2p[128 * 128];
__device__ float g_pw1p[160 * 128];   // K padded 140 -> 160 with zeros
__device__ float g_pw2p[128 * 128];
// node weights: 0:res_w1 1:res_w2 2:ir_w 3:hr_w 4:ii_w 5:hi_w 6:in_w 7:hh_w 8:out_w1 9:out_w2 10:out_w3
__device__ float g_nw[11][128 * 128];

__device__ __forceinline__ float sigmoidf_(float x) {
    return 1.0f / (1.0f + expf(-x));
}

__device__ __forceinline__ unsigned rna(float x) {
    unsigned r;
    asm("cvt.rna.tf32.f32 %0, %1;" : "=r"(r) : "f"(x));
    return r;
}
__device__ __forceinline__ float uif(unsigned x) { return __uint_as_float(x); }

__device__ __forceinline__ void mma8(float* c,
                                     unsigned a0, unsigned a1, unsigned a2, unsigned a3,
                                     unsigned b0, unsigned b1) {
    asm volatile(
        "mma.sync.aligned.m16n8k8.row.col.f32.tf32.tf32.f32 "
        "{%0,%1,%2,%3}, {%4,%5,%6,%7}, {%8,%9}, {%0,%1,%2,%3};"
        : "+f"(c[0]), "+f"(c[1]), "+f"(c[2]), "+f"(c[3])
        : "r"(a0), "r"(a1), "r"(a2), "r"(a3), "r"(b0), "r"(b1));
}

__device__ __forceinline__ void red4(float* p, float4 v) {
    asm volatile("red.global.add.v4.f32 [%0], {%1,%2,%3,%4};"
                 :: "l"(p), "f"(v.x), "f"(v.y), "f"(v.z), "f"(v.w) : "memory");
}

__device__ __forceinline__ void cpa16(uint32_t dst_smem, const void* src) {
    asm volatile("cp.async.cg.shared.global [%0], [%1], 16;"
                 :: "r"(dst_smem), "l"(src) : "memory");
}
#define CP_COMMIT() asm volatile("cp.async.commit_group;" ::: "memory")
#define CP_WAIT0()  asm volatile("cp.async.wait_group 0;" ::: "memory")

// ---------------- helper kernels ----------------

__global__ void zero_kernel() {
    const size_t M = (size_t)BB * NN * HH;
    size_t stride = (size_t)gridDim.x * blockDim.x;
    size_t i = (size_t)blockIdx.x * blockDim.x + threadIdx.x;
    for (size_t j = i; j < M; j += stride) {
        g_hm_sum[j] = 0.0f;
        g_pm_sum[j] = 0.0f;
    }
    if (i < NN) g_cnt[i] = 0;
}

__global__ void count_kernel(const int* __restrict__ recv_e) {
    int e = blockIdx.x * blockDim.x + threadIdx.x;
    if (e < EE) atomicAdd(&g_cnt[recv_e[e]], 1);
}

__global__ void prep_kernel(const float* __restrict__ mw1,
                            const float* __restrict__ mw2,
                            const float* __restrict__ pw1,
                            const float* __restrict__ pw2,
                            const float* __restrict__ res_w1,
                            const float* __restrict__ res_w2,
                            const float* __restrict__ ir_w,
                            const float* __restrict__ hr_w,
                            const float* __restrict__ ii_w,
                            const float* __restrict__ hi_w,
                            const float* __restrict__ in_w,
                            const float* __restrict__ hh_w,
                            const float* __restrict__ out_w1,
                            const float* __restrict__ out_w2,
                            const float* __restrict__ out_w3) {
    int i = blockIdx.x * blockDim.x + threadIdx.x;   // up to 32768
    if (i < 128 * 128) {
        int k = i >> 7, n = i & 127;
        int s = k * 128 + ((n & 7) * 16 + (n >> 3));
        g_w1tp[s] = uif(rna(mw1[i]));                 // rows 0..127
        g_w1bp[s] = uif(rna(mw1[128 * 128 + i]));     // rows 128..255
        g_w2p[s]  = uif(rna(mw2[i]));
        g_pw2p[s] = uif(rna(pw2[i]));
        g_nw[0][s]  = uif(rna(res_w1[i]));
        g_nw[1][s]  = uif(rna(res_w2[i]));
        g_nw[2][s]  = uif(rna(ir_w[i]));
        g_nw[3][s]  = uif(rna(hr_w[i]));
        g_nw[4][s]  = uif(rna(ii_w[i]));
        g_nw[5][s]  = uif(rna(hi_w[i]));
        g_nw[6][s]  = uif(rna(in_w[i]));
        g_nw[7][s]  = uif(rna(hh_w[i]));
        g_nw[8][s]  = uif(rna(out_w1[i]));
        g_nw[9][s]  = uif(rna(out_w2[i]));
        g_nw[10][s] = uif(rna(out_w3[i]));
    }
    if (i < 160 * 128) {
        int k = i >> 7, n = i & 127;
        float v = (k < 140) ? pw1[i] : 0.0f;
        g_pw1p[k * 128 + ((n & 7) * 16 + (n >> 3))] = uif(rna(v));
    }
}

// ---------------- shared legacy-mma machinery ----------------
#define EK_AB(buf)  ((buf) * (128 * 36))
#define EK_B(buf)   (128 * 132 + (buf) * (32 * 132))
#define EK_IDX      (128 * 132 + 2 * 32 * 132)
#define HM_SMEMF    (EK_IDX + 256)                    // 102,400 B
#define PM_SMEMF    (EK_IDX + 128)                    // 101,888 B

#define CHUNK_MMA(ACC, Ab, Ap, kofs, Bb)                                     \
    {                                                                        \
        const unsigned* Au_ = (const unsigned*)(sm + (Ab));                  \
        const float4*   B4_ = (const float4*)(sm + (Bb));                    \
        _Pragma("unroll")                                                    \
        for (int ks = 0; ks < 4; ks++) {                                     \
            int kr = ks * 8;                                                 \
            int bb0 = (kr + q) * 33 + g * 4 + wn * 2;                        \
            int bb1 = (kr + q + 4) * 33 + g * 4 + wn * 2;                    \
            float4 u0 = B4_[bb0], u1 = B4_[bb0 + 1];                         \
            float4 v0 = B4_[bb1], v1 = B4_[bb1 + 1];                         \
            unsigned bu[8] = {__float_as_uint(u0.x), __float_as_uint(u0.y),  \
                              __float_as_uint(u0.z), __float_as_uint(u0.w),  \
                              __float_as_uint(u1.x), __float_as_uint(u1.y),  \
                              __float_as_uint(u1.z), __float_as_uint(u1.w)}; \
            unsigned bv[8] = {__float_as_uint(v0.x), __float_as_uint(v0.y),  \
                              __float_as_uint(v0.z), __float_as_uint(v0.w),  \
                              __float_as_uint(v1.x), __float_as_uint(v1.y),  \
                              __float_as_uint(v1.z), __float_as_uint(v1.w)}; \
            _Pragma("unroll")                                                \
            for (int t = 0; t < 2; t++) {                                    \
                int r0 = (m0 + t * 16 + g) * (Ap) + (kofs) + kr + q;         \
                unsigned a0 = Au_[r0], a1 = Au_[r0 + 8 * (Ap)];              \
                unsigned a2 = Au_[r0 + 4], a3 = Au_[r0 + 8 * (Ap) + 4];      \
                _Pragma("unroll")                                            \
                for (int j = 0; j < 8; j++)                                  \
                    mma8(ACC[t][j], a0, a1, a2, a3, bu[j], bv[j]);           \
            }                                                                \
        }                                                                    \
    }

#define ACC_INIT(ACC, BIAS)                                                  \
    _Pragma("unroll")                                                        \
    for (int j = 0; j < 8; j++) {                                            \
        int c0 = n0 + 8 * j + 2 * q;                                         \
        float b0v = __ldg((BIAS) + c0), b1v = __ldg((BIAS) + c0 + 1);        \
        _Pragma("unroll")                                                    \
        for (int t = 0; t < 2; t++) {                                        \
            ACC[t][j][0] = b0v; ACC[t][j][1] = b1v;                          \
            ACC[t][j][2] = b0v; ACC[t][j][3] = b1v;                          \
        }                                                                    \
    }

#define B_CPASYNC(dstbuf, WSRC)                                              \
    {                                                                        \
        const float4* wsrc_ = (WSRC);                                        \
        _Pragma("unroll")                                                    \
        for (int i = 0; i < 4; i++) {                                        \
            int it = tid + i * 256;                                          \
            int r = it >> 5, c = it & 31;                                    \
            cpa16(smem_u32 + (uint32_t)((EK_B(dstbuf) + r * 132 + c * 4) * 4), \
                  wsrc_ + r * 32 + c);                                       \
        }                                                                    \
        CP_COMMIT();                                                         \
    }

// ---------------- hm_pre: H_r = hidden@W1_top + b1 ; H_s = hidden@W1_bot ----
#define HP_X 0
#define HP_B (128 * 132)
#define HP_SMEMF (HP_B + 32 * 132)     // 84,480 B

__device__ __forceinline__ void gemm128s(const float* As, const float* Wg, float* sB,
                                         float acc[2][8][4], int tid) {
    const int warp = tid >> 5, lane = tid & 31;
    const int wm = warp >> 1, wn = warp & 1;
    const int m0 = wm * 32;
    const int g = lane >> 2, q = lane & 3;

    #pragma unroll 1
    for (int c2 = 0; c2 < 4; c2++) {
        __syncthreads();
        const float4* wsrc = (const float4*)Wg + c2 * 32 * 32;
        #pragma unroll
        for (int i = 0; i < 4; i++) {
            int it = tid + i * 256;
            int r = it >> 5, c = it & 31;
            *(float4*)(sB + r * 132 + c * 4) = wsrc[r * 32 + c];
        }
        __syncthreads();

        const unsigned* Mu = (const unsigned*)As;
        const float4*   B4 = (const float4*)sB;
        #pragma unroll
        for (int ks = 0; ks < 4; ks++) {
            int kr = ks * 8;
            int bb0 = (kr + q) * 33 + g * 4 + wn * 2;
            int bb1 = (kr + q + 4) * 33 + g * 4 + wn * 2;
            float4 u0 = B4[bb0], u1 = B4[bb0 + 1];
            float4 v0 = B4[bb1], v1 = B4[bb1 + 1];
            unsigned bu[8] = {__float_as_uint(u0.x), __float_as_uint(u0.y),
                              __float_as_uint(u0.z), __float_as_uint(u0.w),
                              __float_as_uint(u1.x), __float_as_uint(u1.y),
                              __float_as_uint(u1.z), __float_as_uint(u1.w)};
            unsigned bv[8] = {__float_as_uint(v0.x), __float_as_uint(v0.y),
                              __float_as_uint(v0.z), __float_as_uint(v0.w),
                              __float_as_uint(v1.x), __float_as_uint(v1.y),
                              __float_as_uint(v1.z), __float_as_uint(v1.w)};
            #pragma unroll
            for (int t = 0; t < 2; t++) {
                int r0 = (m0 + t * 16 + g) * 132 + c2 * 32 + kr + q;
                unsigned a0 = Mu[r0], a1 = Mu[r0 + 8 * 132];
                unsigned a2 = Mu[r0 + 4], a3 = Mu[r0 + 8 * 132 + 4];
                #pragma unroll
                for (int j = 0; j < 8; j++) mma8(acc[t][j], a0, a1, a2, a3, bu[j], bv[j]);
            }
        }
    }
    __syncthreads();
}

__global__ void __launch_bounds__(256) hm_pre_kernel(
    const float* __restrict__ hidden,
    const float* __restrict__ mb1)
{
    extern __shared__ __align__(16) float sm[];
    float* s_x = sm + HP_X;
    float* s_B = sm + HP_B;

    const int tid  = threadIdx.x;
    const int row0 = blockIdx.x * 128;   // linear row in [0, BB*NN)

    #pragma unroll
    for (int i = 0; i < 16; i++) {
        int it = tid + i * 256;
        int r = it >> 5, c4v = it & 31;
        float4 h = *(const float4*)(hidden + (size_t)(row0 + r) * HH + c4v * 4);
        uint4 x; x.x = rna(h.x); x.y = rna(h.y); x.z = rna(h.z); x.w = rna(h.w);
        *(uint4*)(s_x + r * 132 + c4v * 4) = x;
    }

    const int warp = tid >> 5, lane = tid & 31;
    const int wm = warp >> 1, wn = warp & 1;
    const int m0 = wm * 32, n0 = wn * 64;
    const int g = lane >> 2, q = lane & 3;

    float acc[2][8][4];

    // H_r = x @ W1_top + b1
    ACC_INIT(acc, mb1)
    gemm128s(s_x, g_w1tp, s_B, acc, tid);
    #pragma unroll
    for (int t = 0; t < 2; t++) {
        int r_ = m0 + t * 16 + g;
        #pragma unroll
        for (int j = 0; j < 8; j++) {
            int c0 = n0 + 8 * j + 2 * q;
            float2 p0, p2;
            p0.x = acc[t][j][0]; p0.y = acc[t][j][1];
            p2.x = acc[t][j][2]; p2.y = acc[t][j][3];
            *(float2*)(g_hr + (size_t)(row0 + r_) * HH + c0) = p0;
            *(float2*)(g_hr + (size_t)(row0 + r_ + 8) * HH + c0) = p2;
        }
    }

    // H_s = x @ W1_bot
    #pragma unroll
    for (int j = 0; j < 8; j++)
        #pragma unroll
        for (int t = 0; t < 2; t++) {
            acc[t][j][0] = 0.0f; acc[t][j][1] = 0.0f;
            acc[t][j][2] = 0.0f; acc[t][j][3] = 0.0f;
        }
    gemm128s(s_x, g_w1bp, s_B, acc, tid);
    #pragma unroll
    for (int t = 0; t < 2; t++) {
        int r_ = m0 + t * 16 + g;
        #pragma unroll
        for (int j = 0; j < 8; j++) {
            int c0 = n0 + 8 * j + 2 * q;
            float2 p0, p2;
            p0.x = acc[t][j][0]; p0.y = acc[t][j][1];
            p2.x = acc[t][j][2]; p2.y = acc[t][j][3];
            *(float2*)(g_hs + (size_t)(row0 + r_) * HH + c0) = p0;
            *(float2*)(g_hs + (size_t)(row0 + r_ + 8) * HH + c0) = p2;
        }
    }
}

// ---------------- hm edge kernel (factored + chunk-pipelined layer 2) -------
// Each chunk kc stages A[e][0..31] = rna(tanh(H_r[recv[e]][kc*32+..] + H_s[send[e]][..]))
// into a pitch-36 double buffer, prefetched ahead of the mma like R12's layer 1.
__global__ void __launch_bounds__(256, 2) hm_kernel(
    const int* __restrict__ send_e, const int* __restrict__ recv_e,
    const float* __restrict__ mb2)
{
    extern __shared__ __align__(16) float sm[];
    int* s_recv = (int*)(sm + EK_IDX);
    int* s_send = s_recv + 128;

    const int tid = threadIdx.x;
    const int b   = blockIdx.y;
    const int e0  = blockIdx.x * 128;
    const uint32_t smem_u32 = (uint32_t)__cvta_generic_to_shared(sm);

    if (tid < 128) s_recv[tid] = recv_e[e0 + tid];
    else           s_send[tid - 128] = send_e[e0 + tid - 128];

    const int warp = tid >> 5, lane = tid & 31;
    const int wm = warp >> 1, wn = warp & 1;
    const int m0 = wm * 32, n0 = wn * 64;
    const int g = lane >> 2, q = lane & 3;
    const int se = tid >> 1, half = (tid & 1) * 16;   // staging: edge, 16-col half

    float acc2[2][8][4];
    ACC_INIT(acc2, mb2)
    __syncthreads();   // idx visible

    const float* hr = g_hr + (size_t)b * NN * HH;
    const float* hs = g_hs + (size_t)b * NN * HH;
    const float* pr_base = hr + (size_t)s_recv[se] * HH + half;
    const float* ps_base = hs + (size_t)s_send[se] * HH + half;

    // ---- stage chunk 0 + B chunk 0 ----
    {
        B_CPASYNC(0, (const float4*)g_w2p)
        #pragma unroll
        for (int v = 0; v < 4; v++) {
            float4 a = *(const float4*)(pr_base + v * 4);
            float4 c = *(const float4*)(ps_base + v * 4);
            uint4 r;
            r.x = rna(tanhf(a.x + c.x));
            r.y = rna(tanhf(a.y + c.y));
            r.z = rna(tanhf(a.z + c.z));
            r.w = rna(tanhf(a.w + c.w));
            *(uint4*)(sm + EK_AB(0) + se * 36 + half + v * 4) = r;
        }
        CP_WAIT0();
    }
    __syncthreads();

    // ---- 4 chunks, pipelined ----
    #pragma unroll 1
    for (int c2 = 0; c2 < 4; c2++) {
        const int cur = c2 & 1, nxt = cur ^ 1;
        const bool has = (c2 + 1) < 4;
        float4 pr4[4], ps4[4];
        if (has) {
            const int k0 = (c2 + 1) * 32;
            #pragma unroll
            for (int v = 0; v < 4; v++) {
                pr4[v] = *(const float4*)(pr_base + k0 + v * 4);
                ps4[v] = *(const float4*)(ps_base + k0 + v * 4);
            }
            B_CPASYNC(nxt, (const float4*)g_w2p + (c2 + 1) * 32 * 32)
        }
        CHUNK_MMA(acc2, EK_AB(cur), 36, 0, EK_B(cur))
        if (has) {
            #pragma unroll
            for (int v = 0; v < 4; v++) {
                uint4 r;
                r.x = rna(tanhf(pr4[v].x + ps4[v].x));
                r.y = rna(tanhf(pr4[v].y + ps4[v].y));
                r.z = rna(tanhf(pr4[v].z + ps4[v].z));
                r.w = rna(tanhf(pr4[v].w + ps4[v].w));
                *(uint4*)(sm + EK_AB(nxt) + se * 36 + half + v * 4) = r;
            }
            CP_WAIT0();
        }
        __syncthreads();
    }

    // ---- epilogue -> mid, scatter ----
    #pragma unroll
    for (int t = 0; t < 2; t++) {
        int r = m0 + t * 16 + g;
        #pragma unroll
        for (int j = 0; j < 8; j++) {
            int c0 = n0 + 8 * j + 2 * q;
            sm[r * 132 + c0]           = tanhf(acc2[t][j][0]);
            sm[r * 132 + c0 + 1]       = tanhf(acc2[t][j][1]);
            sm[(r + 8) * 132 + c0]     = tanhf(acc2[t][j][2]);
            sm[(r + 8) * 132 + c0 + 1] = tanhf(acc2[t][j][3]);
        }
    }
    __syncthreads();

    float* dst = g_hm_sum + (size_t)b * NN * HH;
    const int c4 = tid & 31;
    #pragma unroll 1
    for (int e = tid >> 5; e < 128; e += 8) {
        float4 v = *(const float4*)(sm + e * 132 + c4 * 4);
        red4(dst + (size_t)s_recv[e] * HH + c4 * 4, v);
    }
}

// ---------------- pm edge kernel (legacy pipelined tf32, proven R12) --------
__global__ void __launch_bounds__(256, 2) pm_kernel(
    const float* __restrict__ edge_attr,
    const int* __restrict__ recv_e,
    const float* __restrict__ pb1, const float* __restrict__ pb2)
{
    extern __shared__ __align__(16) float sm[];
    int* s_recv = (int*)(sm + EK_IDX);

    const int tid = threadIdx.x;
    const int b   = blockIdx.y;
    const int e0  = blockIdx.x * 128;
    const uint32_t smem_u32 = (uint32_t)__cvta_generic_to_shared(sm);

    if (tid < 128) s_recv[tid] = recv_e[e0 + tid];

    const int warp = tid >> 5, lane = tid & 31;
    const int wm = warp >> 1, wn = warp & 1;
    const int m0 = wm * 32, n0 = wn * 64;
    const int g = lane >> 2, q = lane & 3;
    const int se = tid >> 3, sv = tid & 7;

    float acc[2][8][4];
    ACC_INIT(acc, pb1)

    const float* ea = edge_attr + ((size_t)b * EE + e0) * FF;

    {
        #pragma unroll
        for (int i = 0; i < 4; i++) {
            int e = se + i * 32;
            int f = sv * 4;
            float4 fv = *(const float4*)(ea + (size_t)e * FF + f);
            uint4 r; r.x = rna(fv.x); r.y = rna(fv.y); r.z = rna(fv.z); r.w = rna(fv.w);
            *(uint4*)(sm + EK_AB(0) + e * 36 + sv * 4) = r;
        }
        B_CPASYNC(0, (const float4*)g_pw1p)
        CP_WAIT0();
    }
    __syncthreads();

    #pragma unroll 1
    for (int kc = 0; kc < 5; kc++) {
        const int cur = kc & 1, nxt = cur ^ 1;
        const bool has = (kc + 1) < 5;
        float4 pf[4];
        if (has) {
            const int k0 = (kc + 1) * 32;
            #pragma unroll
            for (int i = 0; i < 4; i++) {
                int e = se + i * 32;
                int f = k0 + sv * 4;
                if (f < FF) pf[i] = *(const float4*)(ea + (size_t)e * FF + f);
                else { pf[i].x = 0.0f; pf[i].y = 0.0f; pf[i].z = 0.0f; pf[i].w = 0.0f; }
            }
            B_CPASYNC(nxt, (const float4*)g_pw1p + (kc + 1) * 32 * 32)
        }
        CHUNK_MMA(acc, EK_AB(cur), 36, 0, EK_B(cur))
        if (has) {
            #pragma unroll
            for (int i = 0; i < 4; i++) {
                int e = se + i * 32;
                uint4 r;
                r.x = rna(pf[i].x); r.y = rna(pf[i].y);
                r.z = rna(pf[i].z); r.w = rna(pf[i].w);
                *(uint4*)(sm + EK_AB(nxt) + e * 36 + sv * 4) = r;
            }
            CP_WAIT0();
        }
        __syncthreads();
    }

    B_CPASYNC(0, (const float4*)g_pw2p)
    #pragma unroll
    for (int t = 0; t < 2; t++) {
        int r = m0 + t * 16 + g;
        #pragma unroll
        for (int j = 0; j < 8; j++) {
            int c0 = n0 + 8 * j + 2 * q;
            sm[r * 132 + c0]           = uif(rna(fmaxf(acc[t][j][0], 0.0f)));
            sm[r * 132 + c0 + 1]       = uif(rna(fmaxf(acc[t][j][1], 0.0f)));
            sm[(r + 8) * 132 + c0]     = uif(rna(fmaxf(acc[t][j][2], 0.0f)));
            sm[(r + 8) * 132 + c0 + 1] = uif(rna(fmaxf(acc[t][j][3], 0.0f)));
        }
    }
    float acc2[2][8][4];
    ACC_INIT(acc2, pb2)
    CP_WAIT0();
    __syncthreads();

    #pragma unroll 1
    for (int c2 = 0; c2 < 4; c2++) {
        const int cur = c2 & 1, nxt = cur ^ 1;
        const bool has = (c2 + 1) < 4;
        if (has) B_CPASYNC(nxt, (const float4*)g_pw2p + (c2 + 1) * 32 * 32)
        CHUNK_MMA(acc2, 0, 132, c2 * 32, EK_B(cur))
        if (has) CP_WAIT0();
        __syncthreads();
    }

    #pragma unroll
    for (int t = 0; t < 2; t++) {
        int r = m0 + t * 16 + g;
        #pragma unroll
        for (int j = 0; j < 8; j++) {
            int c0 = n0 + 8 * j + 2 * q;
            sm[r * 132 + c0]           = fmaxf(acc2[t][j][0], 0.0f);
            sm[r * 132 + c0 + 1]       = fmaxf(acc2[t][j][1], 0.0f);
            sm[(r + 8) * 132 + c0]     = fmaxf(acc2[t][j][2], 0.0f);
            sm[(r + 8) * 132 + c0 + 1] = fmaxf(acc2[t][j][3], 0.0f);
        }
    }
    __syncthreads();

    float* dst = g_pm_sum + (size_t)b * NN * HH;
    const int c4 = tid & 31;
    #pragma unroll 1
    for (int e = tid >> 5; e < 128; e += 8) {
        float4 v = *(const float4*)(sm + e * 132 + c4 * 4);
        red4(dst + (size_t)s_recv[e] * HH + c4 * 4, v);
    }
}

// ---------------- node kernel (tf32 legacy, proven) ----------------
#define ND_PRES 0
#define ND_HEMB (128 * 132)
#define ND_X    (2 * 128 * 132)
#define ND_B    (3 * 128 * 132)
#define ND_SMEMF (ND_B + 32 * 132)

__device__ __forceinline__ void acc_init_n(float acc[2][8][4], const float* bias,
                                           int n0, int q) {
    #pragma unroll
    for (int j = 0; j < 8; j++) {
        float b0v = 0.0f, b1v = 0.0f;
        if (bias) {
            int c0 = n0 + 8 * j + 2 * q;
            b0v = __ldg(bias + c0); b1v = __ldg(bias + c0 + 1);
        }
        #pragma unroll
        for (int t = 0; t < 2; t++) {
            acc[t][j][0] = b0v; acc[t][j][1] = b1v;
            acc[t][j][2] = b0v; acc[t][j][3] = b1v;
        }
    }
}

__global__ void __launch_bounds__(256) node_kernel(
    const float* __restrict__ inputs,
    const float* __restrict__ hidden,
    const float* __restrict__ res_b1, const float* __restrict__ res_b2,
    const float* __restrict__ ir_b,   const float* __restrict__ ii_b,
    const float* __restrict__ in_b,
    const float* __restrict__ out_b1, const float* __restrict__ out_b2,
    const float* __restrict__ out_b3,
    float* __restrict__ out_pred,
    float* __restrict__ out_hidden)
{
    extern __shared__ __align__(16) float sm[];
    float* s_pres = sm + ND_PRES;
    float* s_hemb = sm + ND_HEMB;
    float* s_x    = sm + ND_X;
    float* s_B    = sm + ND_B;

    const int tid  = threadIdx.x;
    const int row0 = blockIdx.x * 128;

    #pragma unroll
    for (int i = 0; i < 16; i++) {
        int it = tid + i * 256;
        int r = it >> 5, c4v = it & 31;
        size_t off = (size_t)(row0 + r) * HH + c4v * 4;
        float invc = 1.0f / fmaxf((float)__ldg(&g_cnt[(row0 + r) & (NN - 1)]), 1.0f);
        float4 hm4 = *(const float4*)(g_hm_sum + off);
        float4 pm4 = *(const float4*)(g_pm_sum + off);
        float4 in4 = *(const float4*)(inputs + off);
        uint4 a;
        a.x = rna(hm4.x * invc); a.y = rna(hm4.y * invc);
        a.z = rna(hm4.z * invc); a.w = rna(hm4.w * invc);
        *(uint4*)(s_hemb + r * 132 + c4v * 4) = a;
        float4 p;
        p.x = pm4.x * invc; p.y = pm4.y * invc; p.z = pm4.z * invc; p.w = pm4.w * invc;
        *(float4*)(s_pres + r * 132 + c4v * 4) = p;
        uint4 x;
        x.x = rna(in4.x); x.y = rna(in4.y); x.z = rna(in4.z); x.w = rna(in4.w);
        *(uint4*)(s_x + r * 132 + c4v * 4) = x;
    }

    const int warp = tid >> 5, lane = tid & 31;
    const int wm = warp >> 1, wn = warp & 1;
    const int m0 = wm * 32, n0 = wn * 64;
    const int g = lane >> 2, q = lane & 3;
    (void)wn;

    float acc[2][8][4];

    #define FRAG_LOOP(...)                                               \
        _Pragma("unroll")                                                \
        for (int t = 0; t < 2; t++) {                                    \
            int r_ = m0 + t * 16 + g;                                    \
            _Pragma("unroll")                                            \
            for (int j = 0; j < 8; j++) {                                \
                int c0 = n0 + 8 * j + 2 * q;                             \
                int i0 = r_ * 132 + c0;                                  \
                int i2 = (r_ + 8) * 132 + c0;                            \
                (void)i0; (void)i2;                                      \
                __VA_ARGS__                                              \
            }                                                            \
        }

    acc_init_n(acc, res_b1, n0, q);
    gemm128s(s_x, g_nw[0], s_B, acc, tid);
    FRAG_LOOP({
        s_x[i0]     = uif(rna(fmaxf(acc[t][j][0], 0.0f)));
        s_x[i0 + 1] = uif(rna(fmaxf(acc[t][j][1], 0.0f)));
        s_x[i2]     = uif(rna(fmaxf(acc[t][j][2], 0.0f)));
        s_x[i2 + 1] = uif(rna(fmaxf(acc[t][j][3], 0.0f)));
    })

    acc_init_n(acc, res_b2, n0, q);
    gemm128s(s_x, g_nw[1], s_B, acc, tid);
    FRAG_LOOP({
        s_pres[i0]     = uif(rna(fmaxf(acc[t][j][0], 0.0f) + s_pres[i0]));
        s_pres[i0 + 1] = uif(rna(fmaxf(acc[t][j][1], 0.0f) + s_pres[i0 + 1]));
        s_pres[i2]     = uif(rna(fmaxf(acc[t][j][2], 0.0f) + s_pres[i2]));
        s_pres[i2 + 1] = uif(rna(fmaxf(acc[t][j][3], 0.0f) + s_pres[i2 + 1]));
    })

    acc_init_n(acc, nullptr, n0, q);
    gemm128s(s_hemb, g_nw[7], s_B, acc, tid);
    FRAG_LOOP({
        s_x[i0]     = acc[t][j][0];
        s_x[i0 + 1] = acc[t][j][1];
        s_x[i2]     = acc[t][j][2];
        s_x[i2 + 1] = acc[t][j][3];
    })

    acc_init_n(acc, ir_b, n0, q);
    gemm128s(s_pres, g_nw[2], s_B, acc, tid);
    gemm128s(s_hemb, g_nw[3], s_B, acc, tid);
    FRAG_LOOP({
        s_x[i0]     = sigmoidf_(acc[t][j][0]) * s_x[i0];
        s_x[i0 + 1] = sigmoidf_(acc[t][j][1]) * s_x[i0 + 1];
        s_x[i2]     = sigmoidf_(acc[t][j][2]) * s_x[i2];
        s_x[i2 + 1] = sigmoidf_(acc[t][j][3]) * s_x[i2 + 1];
    })

    acc_init_n(acc, ii_b, n0, q);
    gemm128s(s_pres, g_nw[4], s_B, acc, tid);
    gemm128s(s_hemb, g_nw[5], s_B, acc, tid);
    FRAG_LOOP({
        s_hemb[i0]     = sigmoidf_(acc[t][j][0]);
        s_hemb[i0 + 1] = sigmoidf_(acc[t][j][1]);
        s_hemb[i2]     = sigmoidf_(acc[t][j][2]);
        s_hemb[i2 + 1] = sigmoidf_(acc[t][j][3]);
    })

    acc_init_n(acc, in_b, n0, q);
    gemm128s(s_pres, g_nw[6], s_B, acc, tid);
    FRAG_LOOP({
        float n_0 = tanhf(acc[t][j][0] + s_x[i0]);
        float n_1 = tanhf(acc[t][j][1] + s_x[i0 + 1]);
        float n_2 = tanhf(acc[t][j][2] + s_x[i2]);
        float n_3 = tanhf(acc[t][j][3] + s_x[i2 + 1]);
        float i_0 = s_hemb[i0];
        float i_1 = s_hemb[i0 + 1];
        float i_2 = s_hemb[i2];
        float i_3 = s_hemb[i2 + 1];
        size_t go0 = (size_t)(row0 + r_) * HH + c0;
        size_t go2 = (size_t)(row0 + r_ + 8) * HH + c0;
        float2 h0 = *(const float2*)(hidden + go0);
        float2 h2 = *(const float2*)(hidden + go2);
        float2 nh0;
        float2 nh2;
        nh0.x = (1.0f - i_0) * n_0 + i_0 * h0.x;
        nh0.y = (1.0f - i_1) * n_1 + i_1 * h0.y;
        nh2.x = (1.0f - i_2) * n_2 + i_2 * h2.x;
        nh2.y = (1.0f - i_3) * n_3 + i_3 * h2.y;
        *(float2*)(out_hidden + go0) = nh0;
        *(float2*)(out_hidden + go2) = nh2;
        s_x[i0]     = uif(rna(nh0.x));
        s_x[i0 + 1] = uif(rna(nh0.y));
        s_x[i2]     = uif(rna(nh2.x));
        s_x[i2 + 1] = uif(rna(nh2.y));
    })

    acc_init_n(acc, out_b1, n0, q);
    gemm128s(s_x, g_nw[8], s_B, acc, tid);
    FRAG_LOOP({
        s_hemb[i0]     = uif(rna(fmaxf(acc[t][j][0], 0.0f)));
        s_hemb[i0 + 1] = uif(rna(fmaxf(acc[t][j][1], 0.0f)));
        s_hemb[i2]     = uif(rna(fmaxf(acc[t][j][2], 0.0f)));
        s_hemb[i2 + 1] = uif(rna(fmaxf(acc[t][j][3], 0.0f)));
    })

    acc_init_n(acc, out_b2, n0, q);
    gemm128s(s_hemb, g_nw[9], s_B, acc, tid);
    FRAG_LOOP({
        s_x[i0]     = uif(rna(fmaxf(acc[t][j][0], 0.0f)));
        s_x[i0 + 1] = uif(rna(fmaxf(acc[t][j][1], 0.0f)));
        s_x[i2]     = uif(rna(fmaxf(acc[t][j][2], 0.0f)));
        s_x[i2 + 1] = uif(rna(fmaxf(acc[t][j][3], 0.0f)));
    })

    acc_init_n(acc, out_b3, n0, q);
    gemm128s(s_x, g_nw[10], s_B, acc, tid);
    FRAG_LOOP({
        size_t go0 = (size_t)(row0 + r_) * II + c0;
        size_t go2 = (size_t)(row0 + r_ + 8) * II + c0;
        float2 p0;
        float2 p2;
        p0.x = acc[t][j][0]; p0.y = acc[t][j][1];
        p2.x = acc[t][j][2]; p2.y = acc[t][j][3];
        *(float2*)(out_pred + go0) = p0;
        *(float2*)(out_pred + go2) = p2;
    })
    #undef FRAG_LOOP
}

// ---------------- launch ----------------
extern "C" void kernel_launch(void* const* d_in, const int* in_sizes, int n_in,
                              void* d_out, int out_size) {
    const float* inputs    = (const float*)d_in[0];
    const float* edge_attr = (const float*)d_in[1];
    const int*   send_e    = (const int*)  d_in[2];
    const int*   recv_e    = (const int*)  d_in[3];
    const float* hidden    = (const float*)d_in[4];
    const float* msg_w1 = (const float*)d_in[5];
    const float* msg_b1 = (const float*)d_in[6];
    const float* msg_w2 = (const float*)d_in[7];
    const float* msg_b2 = (const float*)d_in[8];
    const float* pm_w1  = (const float*)d_in[9];
    const float* pm_b1  = (const float*)d_in[10];
    const float* pm_w2  = (const float*)d_in[11];
    const float* pm_b2  = (const float*)d_in[12];
    const float* res_w1 = (const float*)d_in[13];
    const float* res_b1 = (const float*)d_in[14];
    const float* res_w2 = (const float*)d_in[15];
    const float* res_b2 = (const float*)d_in[16];
    const float* ir_w   = (const float*)d_in[17];
    const float* ir_b   = (const float*)d_in[18];
    const float* ii_w   = (const float*)d_in[19];
    const float* ii_b   = (const float*)d_in[20];
    const float* in_w   = (const float*)d_in[21];
    const float* in_b   = (const float*)d_in[22];
    const float* hr_w   = (const float*)d_in[23];
    const float* hi_w   = (const float*)d_in[24];
    const float* hh_w   = (const float*)d_in[25];
    const float* out_w1 = (const float*)d_in[26];
    const float* out_b1 = (const float*)d_in[27];
    const float* out_w2 = (const float*)d_in[28];
    const float* out_b2 = (const float*)d_in[29];
    const float* out_w3 = (const float*)d_in[30];
    const float* out_b3 = (const float*)d_in[31];

    float* out_pred   = (float*)d_out;
    float* out_hidden = (float*)d_out + (size_t)BB * NN * II;

    const int HM_SMEM = HM_SMEMF * 4;     // 102,400 B -> 2 CTAs/SM
    const int PM_SMEM = PM_SMEMF * 4;     // 101,888 B -> 2 CTAs/SM
    const int HP_SMEM = HP_SMEMF * 4;     //  84,480 B
    const int ND_SMEM = ND_SMEMF * 4;     // 219,648 B
    cudaFuncSetAttribute(hm_kernel, cudaFuncAttributeMaxDynamicSharedMemorySize, HM_SMEM);
    cudaFuncSetAttribute(pm_kernel, cudaFuncAttributeMaxDynamicSharedMemorySize, PM_SMEM);
    cudaFuncSetAttribute(hm_pre_kernel, cudaFuncAttributeMaxDynamicSharedMemorySize, HP_SMEM);
    cudaFuncSetAttribute(node_kernel, cudaFuncAttributeMaxDynamicSharedMemorySize, ND_SMEM);

    zero_kernel<<<1024, 256>>>();
    count_kernel<<<EE / 256, 256>>>(recv_e);
    prep_kernel<<<128, 256>>>(msg_w1, msg_w2, pm_w1, pm_w2,
                              res_w1, res_w2, ir_w, hr_w, ii_w, hi_w,
                              in_w, hh_w, out_w1, out_w2, out_w3);

    hm_pre_kernel<<<(BB * NN) / 128, 256, HP_SMEM>>>(hidden, msg_b1);
    hm_kernel<<<dim3(EE / 128, BB), 256, HM_SMEM>>>(send_e, recv_e, msg_b2);
    pm_kernel<<<dim3(EE / 128, BB), 256, PM_SMEM>>>(edge_attr, recv_e, pm_b1, pm_b2);

    node_kernel<<<(BB * NN) / 128, 256, ND_SMEM>>>(
        inputs, hidden,
        res_b1, res_b2, ir_b, ii_b, in_b,
        out_b1, out_b2, out_b3,
        out_pred, out_hidden);
}

// round 16
// speedup vs baseline: 5.1057x; 1.0791x over previous
#include <cuda_runtime.h>
#include <math.h>
#include <stdint.h>

// Problem constants
#define BB 4
#define NN 4096
#define EE 131072
#define II 128
#define HH 128
#define FF 140

// ---------------- scratch (__device__ globals; no allocs allowed) ----------
__device__ float g_hm_sum[(size_t)BB * NN * HH];   // 8 MB
__device__ float g_pm_sum[(size_t)BB * NN * HH];   // 8 MB
__device__ float g_hr[(size_t)BB * NN * HH];       // hidden @ W1_top + b1
__device__ float g_hs[(size_t)BB * NN * HH];       // hidden @ W1_bot
__device__ int   g_cnt[NN];

// legacy-permuted tf32 weights: w[k][ (n%8)*16 + n/8 ]
__device__ float g_w1tp[128 * 128];   // msg_w1 rows 0..127   (recv half)
__device__ float g_w1bp[128 * 128];   // msg_w1 rows 128..255 (send half)
__device__ float g_w2p[128 * 128];
__device__ float g_pw1p[160 * 128];   // K padded 140 -> 160 with zeros
__device__ float g_pw2p[128 * 128];
// node weights: 0:res_w1 1:res_w2 2:ir_w 3:hr_w 4:ii_w 5:hi_w 6:in_w 7:hh_w 8:out_w1 9:out_w2 10:out_w3
__device__ float g_nw[11][128 * 128];

__device__ __forceinline__ float sigmoidf_(float x) {
    return 1.0f / (1.0f + expf(-x));
}

__device__ __forceinline__ unsigned rna(float x) {
    unsigned r;
    asm("cvt.rna.tf32.f32 %0, %1;" : "=r"(r) : "f"(x));
    return r;
}
__device__ __forceinline__ float uif(unsigned x) { return __uint_as_float(x); }

__device__ __forceinline__ void mma8(float* c,
                                     unsigned a0, unsigned a1, unsigned a2, unsigned a3,
                                     unsigned b0, unsigned b1) {
    asm volatile(
        "mma.sync.aligned.m16n8k8.row.col.f32.tf32.tf32.f32 "
        "{%0,%1,%2,%3}, {%4,%5,%6,%7}, {%8,%9}, {%0,%1,%2,%3};"
        : "+f"(c[0]), "+f"(c[1]), "+f"(c[2]), "+f"(c[3])
        : "r"(a0), "r"(a1), "r"(a2), "r"(a3), "r"(b0), "r"(b1));
}

__device__ __forceinline__ void red4(float* p, float4 v) {
    asm volatile("red.global.add.v4.f32 [%0], {%1,%2,%3,%4};"
                 :: "l"(p), "f"(v.x), "f"(v.y), "f"(v.z), "f"(v.w) : "memory");
}

__device__ __forceinline__ void cpa16(uint32_t dst_smem, const void* src) {
    asm volatile("cp.async.cg.shared.global [%0], [%1], 16;"
                 :: "r"(dst_smem), "l"(src) : "memory");
}
#define CP_COMMIT() asm volatile("cp.async.commit_group;" ::: "memory")
#define CP_WAIT0()  asm volatile("cp.async.wait_group 0;" ::: "memory")

// ---------------- helper kernels ----------------

__global__ void zero_kernel() {
    const size_t M = (size_t)BB * NN * HH;
    size_t stride = (size_t)gridDim.x * blockDim.x;
    size_t i = (size_t)blockIdx.x * blockDim.x + threadIdx.x;
    for (size_t j = i; j < M; j += stride) {
        g_hm_sum[j] = 0.0f;
        g_pm_sum[j] = 0.0f;
    }
    if (i < NN) g_cnt[i] = 0;
}

__global__ void count_kernel(const int* __restrict__ recv_e) {
    int e = blockIdx.x * blockDim.x + threadIdx.x;
    if (e < EE) atomicAdd(&g_cnt[recv_e[e]], 1);
}

__global__ void prep_kernel(const float* __restrict__ mw1,
                            const float* __restrict__ mw2,
                            const float* __restrict__ pw1,
                            const float* __restrict__ pw2,
                            const float* __restrict__ res_w1,
                            const float* __restrict__ res_w2,
                            const float* __restrict__ ir_w,
                            const float* __restrict__ hr_w,
                            const float* __restrict__ ii_w,
                            const float* __restrict__ hi_w,
                            const float* __restrict__ in_w,
                            const float* __restrict__ hh_w,
                            const float* __restrict__ out_w1,
                            const float* __restrict__ out_w2,
                            const float* __restrict__ out_w3) {
    int i = blockIdx.x * blockDim.x + threadIdx.x;   // up to 32768
    if (i < 128 * 128) {
        int k = i >> 7, n = i & 127;
        int s = k * 128 + ((n & 7) * 16 + (n >> 3));
        g_w1tp[s] = uif(rna(mw1[i]));                 // rows 0..127
        g_w1bp[s] = uif(rna(mw1[128 * 128 + i]));     // rows 128..255
        g_w2p[s]  = uif(rna(mw2[i]));
        g_pw2p[s] = uif(rna(pw2[i]));
        g_nw[0][s]  = uif(rna(res_w1[i]));
        g_nw[1][s]  = uif(rna(res_w2[i]));
        g_nw[2][s]  = uif(rna(ir_w[i]));
        g_nw[3][s]  = uif(rna(hr_w[i]));
        g_nw[4][s]  = uif(rna(ii_w[i]));
        g_nw[5][s]  = uif(rna(hi_w[i]));
        g_nw[6][s]  = uif(rna(in_w[i]));
        g_nw[7][s]  = uif(rna(hh_w[i]));
        g_nw[8][s]  = uif(rna(out_w1[i]));
        g_nw[9][s]  = uif(rna(out_w2[i]));
        g_nw[10][s] = uif(rna(out_w3[i]));
    }
    if (i < 160 * 128) {
        int k = i >> 7, n = i & 127;
        float v = (k < 140) ? pw1[i] : 0.0f;
        g_pw1p[k * 128 + ((n & 7) * 16 + (n >> 3))] = uif(rna(v));
    }
}

// ---------------- shared legacy-mma machinery (256-thread edge kernels) -----
#define EK_AB(buf)  ((buf) * (128 * 36))
#define EK_B(buf)   (128 * 132 + (buf) * (32 * 132))
#define EK_IDX      (128 * 132 + 2 * 32 * 132)
#define HM_SMEMF    (EK_IDX + 256)                    // 102,400 B
#define PM_SMEMF    (EK_IDX + 128)                    // 101,888 B

#define CHUNK_MMA(ACC, Ab, Ap, kofs, Bb, NKS)                                \
    {                                                                        \
        const unsigned* Au_ = (const unsigned*)(sm + (Ab));                  \
        const float4*   B4_ = (const float4*)(sm + (Bb));                    \
        _Pragma("unroll")                                                    \
        for (int ks = 0; ks < (NKS); ks++) {                                 \
            int kr = ks * 8;                                                 \
            int bb0 = (kr + q) * 33 + g * 4 + wn * 2;                        \
            int bb1 = (kr + q + 4) * 33 + g * 4 + wn * 2;                    \
            float4 u0 = B4_[bb0], u1 = B4_[bb0 + 1];                         \
            float4 v0 = B4_[bb1], v1 = B4_[bb1 + 1];                         \
            unsigned bu[8] = {__float_as_uint(u0.x), __float_as_uint(u0.y),  \
                              __float_as_uint(u0.z), __float_as_uint(u0.w),  \
                              __float_as_uint(u1.x), __float_as_uint(u1.y),  \
                              __float_as_uint(u1.z), __float_as_uint(u1.w)}; \
            unsigned bv[8] = {__float_as_uint(v0.x), __float_as_uint(v0.y),  \
                              __float_as_uint(v0.z), __float_as_uint(v0.w),  \
                              __float_as_uint(v1.x), __float_as_uint(v1.y),  \
                              __float_as_uint(v1.z), __float_as_uint(v1.w)}; \
            _Pragma("unroll")                                                \
            for (int t = 0; t < 2; t++) {                                    \
                int r0 = (m0 + t * 16 + g) * (Ap) + (kofs) + kr + q;         \
                unsigned a0 = Au_[r0], a1 = Au_[r0 + 8 * (Ap)];              \
                unsigned a2 = Au_[r0 + 4], a3 = Au_[r0 + 8 * (Ap) + 4];      \
                _Pragma("unroll")                                            \
                for (int j = 0; j < 8; j++)                                  \
                    mma8(ACC[t][j], a0, a1, a2, a3, bu[j], bv[j]);           \
            }                                                                \
        }                                                                    \
    }

#define ACC_INIT(ACC, BIAS)                                                  \
    _Pragma("unroll")                                                        \
    for (int j = 0; j < 8; j++) {                                            \
        int c0 = n0 + 8 * j + 2 * q;                                         \
        float b0v = __ldg((BIAS) + c0), b1v = __ldg((BIAS) + c0 + 1);        \
        _Pragma("unroll")                                                    \
        for (int t = 0; t < 2; t++) {                                        \
            ACC[t][j][0] = b0v; ACC[t][j][1] = b1v;                          \
            ACC[t][j][2] = b0v; ACC[t][j][3] = b1v;                          \
        }                                                                    \
    }

#define B_CPASYNC(dstbuf, WSRC)                                              \
    {                                                                        \
        const float4* wsrc_ = (WSRC);                                        \
        _Pragma("unroll")                                                    \
        for (int i = 0; i < 4; i++) {                                        \
            int it = tid + i * 256;                                          \
            int r = it >> 5, c = it & 31;                                    \
            cpa16(smem_u32 + (uint32_t)((EK_B(dstbuf) + r * 132 + c * 4) * 4), \
                  wsrc_ + r * 32 + c);                                       \
        }                                                                    \
        CP_COMMIT();                                                         \
    }

// ---------------- 512-thread gemm machinery (node, hm_pre) ------------------
// 16 warps, each a 16-row x 64-col tile: wm = wid>>1 (0..7), wn = wid&1.
#define NACC_INIT(ACC, BIAS)                                                 \
    _Pragma("unroll")                                                        \
    for (int j = 0; j < 8; j++) {                                            \
        float b0v = 0.0f, b1v = 0.0f;                                        \
        if (BIAS) {                                                          \
            int c0 = n0 + 8 * j + 2 * q;                                     \
            b0v = __ldg((const float*)(BIAS) + c0);                          \
            b1v = __ldg((const float*)(BIAS) + c0 + 1);                      \
        }                                                                    \
        ACC[j][0] = b0v; ACC[j][1] = b1v;                                    \
        ACC[j][2] = b0v; ACC[j][3] = b1v;                                    \
    }

__device__ __forceinline__ void gemm128v(const float* As, const float* Wg, float* sB,
                                         float acc[8][4], int tid) {
    const int wid = tid >> 5, lane = tid & 31;
    const int wm = wid >> 1, wn = wid & 1;
    const int m0 = wm * 16;
    const int g = lane >> 2, q = lane & 3;

    #pragma unroll 1
    for (int c2 = 0; c2 < 4; c2++) {
        __syncthreads();
        const float4* wsrc = (const float4*)Wg + c2 * 32 * 32;
        #pragma unroll
        for (int i = 0; i < 2; i++) {
            int it = tid + i * 512;
            int r = it >> 5, c = it & 31;
            *(float4*)(sB + r * 132 + c * 4) = wsrc[r * 32 + c];
        }
        __syncthreads();

        const unsigned* Mu = (const unsigned*)As;
        const float4*   B4 = (const float4*)sB;
        #pragma unroll
        for (int ks = 0; ks < 4; ks++) {
            int kr = ks * 8;
            int bb0 = (kr + q) * 33 + g * 4 + wn * 2;
            int bb1 = (kr + q + 4) * 33 + g * 4 + wn * 2;
            float4 u0 = B4[bb0], u1 = B4[bb0 + 1];
            float4 v0 = B4[bb1], v1 = B4[bb1 + 1];
            unsigned bu[8] = {__float_as_uint(u0.x), __float_as_uint(u0.y),
                              __float_as_uint(u0.z), __float_as_uint(u0.w),
                              __float_as_uint(u1.x), __float_as_uint(u1.y),
                              __float_as_uint(u1.z), __float_as_uint(u1.w)};
            unsigned bv[8] = {__float_as_uint(v0.x), __float_as_uint(v0.y),
                              __float_as_uint(v0.z), __float_as_uint(v0.w),
                              __float_as_uint(v1.x), __float_as_uint(v1.y),
                              __float_as_uint(v1.z), __float_as_uint(v1.w)};
            int r0 = (m0 + g) * 132 + c2 * 32 + kr + q;
            unsigned a0 = Mu[r0], a1 = Mu[r0 + 8 * 132];
            unsigned a2 = Mu[r0 + 4], a3 = Mu[r0 + 8 * 132 + 4];
            #pragma unroll
            for (int j = 0; j < 8; j++) mma8(acc[j], a0, a1, a2, a3, bu[j], bv[j]);
        }
    }
    __syncthreads();
}

// ---------------- hm_pre: H_r = hidden@W1_top + b1 ; H_s = hidden@W1_bot ----
#define HP_X 0
#define HP_B (128 * 132)
#define HP_SMEMF (HP_B + 32 * 132)     // 84,480 B

__global__ void __launch_bounds__(512) hm_pre_kernel(
    const float* __restrict__ hidden,
    const float* __restrict__ mb1)
{
    extern __shared__ __align__(16) float sm[];
    float* s_x = sm + HP_X;
    float* s_B = sm + HP_B;

    const int tid  = threadIdx.x;
    const int row0 = blockIdx.x * 128;   // linear row in [0, BB*NN)

    #pragma unroll
    for (int i = 0; i < 8; i++) {
        int it = tid + i * 512;
        int r = it >> 5, c4v = it & 31;
        float4 h = *(const float4*)(hidden + (size_t)(row0 + r) * HH + c4v * 4);
        uint4 x; x.x = rna(h.x); x.y = rna(h.y); x.z = rna(h.z); x.w = rna(h.w);
        *(uint4*)(s_x + r * 132 + c4v * 4) = x;
    }

    const int wid = tid >> 5, lane = tid & 31;
    const int wm = wid >> 1, wn = wid & 1;
    const int m0 = wm * 16, n0 = wn * 64;
    const int g = lane >> 2, q = lane & 3;

    float acc[8][4];

    // H_r = x @ W1_top + b1
    NACC_INIT(acc, mb1)
    gemm128v(s_x, g_w1tp, s_B, acc, tid);
    {
        int r_ = m0 + g;
        #pragma unroll
        for (int j = 0; j < 8; j++) {
            int c0 = n0 + 8 * j + 2 * q;
            float2 p0, p2;
            p0.x = acc[j][0]; p0.y = acc[j][1];
            p2.x = acc[j][2]; p2.y = acc[j][3];
            *(float2*)(g_hr + (size_t)(row0 + r_) * HH + c0) = p0;
            *(float2*)(g_hr + (size_t)(row0 + r_ + 8) * HH + c0) = p2;
        }
    }

    // H_s = x @ W1_bot
    NACC_INIT(acc, (const float*)nullptr)
    gemm128v(s_x, g_w1bp, s_B, acc, tid);
    {
        int r_ = m0 + g;
        #pragma unroll
        for (int j = 0; j < 8; j++) {
            int c0 = n0 + 8 * j + 2 * q;
            float2 p0, p2;
            p0.x = acc[j][0]; p0.y = acc[j][1];
            p2.x = acc[j][2]; p2.y = acc[j][3];
            *(float2*)(g_hs + (size_t)(row0 + r_) * HH + c0) = p0;
            *(float2*)(g_hs + (size_t)(row0 + r_ + 8) * HH + c0) = p2;
        }
    }
}

// ---------------- hm edge kernel (factored + chunk-pipelined layer 2) -------
__global__ void __launch_bounds__(256, 2) hm_kernel(
    const int* __restrict__ send_e, const int* __restrict__ recv_e,
    const float* __restrict__ mb2)
{
    extern __shared__ __align__(16) float sm[];
    int* s_recv = (int*)(sm + EK_IDX);
    int* s_send = s_recv + 128;

    const int tid = threadIdx.x;
    const int b   = blockIdx.y;
    const int e0  = blockIdx.x * 128;
    const uint32_t smem_u32 = (uint32_t)__cvta_generic_to_shared(sm);

    if (tid < 128) s_recv[tid] = recv_e[e0 + tid];
    else           s_send[tid - 128] = send_e[e0 + tid - 128];

    const int warp = tid >> 5, lane = tid & 31;
    const int wm = warp >> 1, wn = warp & 1;
    const int m0 = wm * 32, n0 = wn * 64;
    const int g = lane >> 2, q = lane & 3;
    const int se = tid >> 1, half = (tid & 1) * 16;   // staging: edge, 16-col half

    float acc2[2][8][4];
    ACC_INIT(acc2, mb2)
    __syncthreads();   // idx visible

    const float* hr = g_hr + (size_t)b * NN * HH;
    const float* hs = g_hs + (size_t)b * NN * HH;
    const float* pr_base = hr + (size_t)s_recv[se] * HH + half;
    const float* ps_base = hs + (size_t)s_send[se] * HH + half;

    // ---- stage chunk 0 + B chunk 0 ----
    {
        B_CPASYNC(0, (const float4*)g_w2p)
        #pragma unroll
        for (int v = 0; v < 4; v++) {
            float4 a = *(const float4*)(pr_base + v * 4);
            float4 c = *(const float4*)(ps_base + v * 4);
            uint4 r;
            r.x = rna(tanhf(a.x + c.x));
            r.y = rna(tanhf(a.y + c.y));
            r.z = rna(tanhf(a.z + c.z));
            r.w = rna(tanhf(a.w + c.w));
            *(uint4*)(sm + EK_AB(0) + se * 36 + half + v * 4) = r;
        }
        CP_WAIT0();
    }
    __syncthreads();

    // ---- 4 chunks, pipelined ----
    #pragma unroll 1
    for (int c2 = 0; c2 < 4; c2++) {
        const int cur = c2 & 1, nxt = cur ^ 1;
        const bool has = (c2 + 1) < 4;
        float4 pr4[4], ps4[4];
        if (has) {
            const int k0 = (c2 + 1) * 32;
            #pragma unroll
            for (int v = 0; v < 4; v++) {
                pr4[v] = *(const float4*)(pr_base + k0 + v * 4);
                ps4[v] = *(const float4*)(ps_base + k0 + v * 4);
            }
            B_CPASYNC(nxt, (const float4*)g_w2p + (c2 + 1) * 32 * 32)
        }
        CHUNK_MMA(acc2, EK_AB(cur), 36, 0, EK_B(cur), 4)
        if (has) {
            #pragma unroll
            for (int v = 0; v < 4; v++) {
                uint4 r;
                r.x = rna(tanhf(pr4[v].x + ps4[v].x));
                r.y = rna(tanhf(pr4[v].y + ps4[v].y));
                r.z = rna(tanhf(pr4[v].z + ps4[v].z));
                r.w = rna(tanhf(pr4[v].w + ps4[v].w));
                *(uint4*)(sm + EK_AB(nxt) + se * 36 + half + v * 4) = r;
            }
            CP_WAIT0();
        }
        __syncthreads();
    }

    // ---- epilogue -> mid, scatter ----
    #pragma unroll
    for (int t = 0; t < 2; t++) {
        int r = m0 + t * 16 + g;
        #pragma unroll
        for (int j = 0; j < 8; j++) {
            int c0 = n0 + 8 * j + 2 * q;
            sm[r * 132 + c0]           = tanhf(acc2[t][j][0]);
            sm[r * 132 + c0 + 1]       = tanhf(acc2[t][j][1]);
            sm[(r + 8) * 132 + c0]     = tanhf(acc2[t][j][2]);
            sm[(r + 8) * 132 + c0 + 1] = tanhf(acc2[t][j][3]);
        }
    }
    __syncthreads();

    float* dst = g_hm_sum + (size_t)b * NN * HH;
    const int c4 = tid & 31;
    #pragma unroll 1
    for (int e = tid >> 5; e < 128; e += 8) {
        float4 v = *(const float4*)(sm + e * 132 + c4 * 4);
        red4(dst + (size_t)s_recv[e] * HH + c4 * 4, v);
    }
}

// ---------------- pm edge kernel (pipelined tf32, K=144 with K=16 tail) -----
__global__ void __launch_bounds__(256, 2) pm_kernel(
    const float* __restrict__ edge_attr,
    const int* __restrict__ recv_e,
    const float* __restrict__ pb1, const float* __restrict__ pb2)
{
    extern __shared__ __align__(16) float sm[];
    int* s_recv = (int*)(sm + EK_IDX);

    const int tid = threadIdx.x;
    const int b   = blockIdx.y;
    const int e0  = blockIdx.x * 128;
    const uint32_t smem_u32 = (uint32_t)__cvta_generic_to_shared(sm);

    if (tid < 128) s_recv[tid] = recv_e[e0 + tid];

    const int warp = tid >> 5, lane = tid & 31;
    const int wm = warp >> 1, wn = warp & 1;
    const int m0 = wm * 32, n0 = wn * 64;
    const int g = lane >> 2, q = lane & 3;
    const int se = tid >> 3, sv = tid & 7;

    float acc[2][8][4];
    ACC_INIT(acc, pb1)

    const float* ea = edge_attr + ((size_t)b * EE + e0) * FF;

    {
        #pragma unroll
        for (int i = 0; i < 4; i++) {
            int e = se + i * 32;
            int f = sv * 4;
            float4 fv = *(const float4*)(ea + (size_t)e * FF + f);
            uint4 r; r.x = rna(fv.x); r.y = rna(fv.y); r.z = rna(fv.z); r.w = rna(fv.w);
            *(uint4*)(sm + EK_AB(0) + e * 36 + sv * 4) = r;
        }
        B_CPASYNC(0, (const float4*)g_pw1p)
        CP_WAIT0();
    }
    __syncthreads();

    // ---- 4 full chunks (k 0..127), each prefetching the next (incl. tail) ----
    #pragma unroll 1
    for (int kc = 0; kc < 4; kc++) {
        const int cur = kc & 1, nxt = cur ^ 1;
        float4 pf[4];
        {
            const int k0 = (kc + 1) * 32;
            #pragma unroll
            for (int i = 0; i < 4; i++) {
                int e = se + i * 32;
                int f = k0 + sv * 4;
                if (f < FF) pf[i] = *(const float4*)(ea + (size_t)e * FF + f);
                else { pf[i].x = 0.0f; pf[i].y = 0.0f; pf[i].z = 0.0f; pf[i].w = 0.0f; }
            }
            B_CPASYNC(nxt, (const float4*)g_pw1p + (kc + 1) * 32 * 32)
        }
        CHUNK_MMA(acc, EK_AB(cur), 36, 0, EK_B(cur), 4)
        {
            #pragma unroll
            for (int i = 0; i < 4; i++) {
                int e = se + i * 32;
                uint4 r;
                r.x = rna(pf[i].x); r.y = rna(pf[i].y);
                r.z = rna(pf[i].z); r.w = rna(pf[i].w);
                *(uint4*)(sm + EK_AB(nxt) + e * 36 + sv * 4) = r;
            }
            CP_WAIT0();
        }
        __syncthreads();
    }

    // ---- tail chunk: K=16 only (cols 128..143; 144..159 are zero padding) ----
    CHUNK_MMA(acc, EK_AB(0), 36, 0, EK_B(0), 2)
    __syncthreads();

    B_CPASYNC(0, (const float4*)g_pw2p)
    #pragma unroll
    for (int t = 0; t < 2; t++) {
        int r = m0 + t * 16 + g;
        #pragma unroll
        for (int j = 0; j < 8; j++) {
            int c0 = n0 + 8 * j + 2 * q;
            sm[r * 132 + c0]           = uif(rna(fmaxf(acc[t][j][0], 0.0f)));
            sm[r * 132 + c0 + 1]       = uif(rna(fmaxf(acc[t][j][1], 0.0f)));
            sm[(r + 8) * 132 + c0]     = uif(rna(fmaxf(acc[t][j][2], 0.0f)));
            sm[(r + 8) * 132 + c0 + 1] = uif(rna(fmaxf(acc[t][j][3], 0.0f)));
        }
    }
    float acc2[2][8][4];
    ACC_INIT(acc2, pb2)
    CP_WAIT0();
    __syncthreads();

    #pragma unroll 1
    for (int c2 = 0; c2 < 4; c2++) {
        const int cur = c2 & 1, nxt = cur ^ 1;
        const bool has = (c2 + 1) < 4;
        if (has) B_CPASYNC(nxt, (const float4*)g_pw2p + (c2 + 1) * 32 * 32)
        CHUNK_MMA(acc2, 0, 132, c2 * 32, EK_B(cur), 4)
        if (has) CP_WAIT0();
        __syncthreads();
    }

    #pragma unroll
    for (int t = 0; t < 2; t++) {
        int r = m0 + t * 16 + g;
        #pragma unroll
        for (int j = 0; j < 8; j++) {
            int c0 = n0 + 8 * j + 2 * q;
            sm[r * 132 + c0]           = fmaxf(acc2[t][j][0], 0.0f);
            sm[r * 132 + c0 + 1]       = fmaxf(acc2[t][j][1], 0.0f);
            sm[(r + 8) * 132 + c0]     = fmaxf(acc2[t][j][2], 0.0f);
            sm[(r + 8) * 132 + c0 + 1] = fmaxf(acc2[t][j][3], 0.0f);
        }
    }
    __syncthreads();

    float* dst = g_pm_sum + (size_t)b * NN * HH;
    const int c4 = tid & 31;
    #pragma unroll 1
    for (int e = tid >> 5; e < 128; e += 8) {
        float4 v = *(const float4*)(sm + e * 132 + c4 * 4);
        red4(dst + (size_t)s_recv[e] * HH + c4 * 4, v);
    }
}

// ---------------- node kernel (tf32, 512 threads / 16 warps) ----------------
#define ND_PRES 0
#define ND_HEMB (128 * 132)
#define ND_X    (2 * 128 * 132)
#define ND_B    (3 * 128 * 132)
#define ND_SMEMF (ND_B + 32 * 132)

__global__ void __launch_bounds__(512) node_kernel(
    const float* __restrict__ inputs,
    const float* __restrict__ hidden,
    const float* __restrict__ res_b1, const float* __restrict__ res_b2,
    const float* __restrict__ ir_b,   const float* __restrict__ ii_b,
    const float* __restrict__ in_b,
    const float* __restrict__ out_b1, const float* __restrict__ out_b2,
    const float* __restrict__ out_b3,
    float* __restrict__ out_pred,
    float* __restrict__ out_hidden)
{
    extern __shared__ __align__(16) float sm[];
    float* s_pres = sm + ND_PRES;
    float* s_hemb = sm + ND_HEMB;
    float* s_x    = sm + ND_X;
    float* s_B    = sm + ND_B;

    const int tid  = threadIdx.x;
    const int row0 = blockIdx.x * 128;

    #pragma unroll
    for (int i = 0; i < 8; i++) {
        int it = tid + i * 512;
        int r = it >> 5, c4v = it & 31;
        size_t off = (size_t)(row0 + r) * HH + c4v * 4;
        float invc = 1.0f / fmaxf((float)__ldg(&g_cnt[(row0 + r) & (NN - 1)]), 1.0f);
        float4 hm4 = *(const float4*)(g_hm_sum + off);
        float4 pm4 = *(const float4*)(g_pm_sum + off);
        float4 in4 = *(const float4*)(inputs + off);
        uint4 a;
        a.x = rna(hm4.x * invc); a.y = rna(hm4.y * invc);
        a.z = rna(hm4.z * invc); a.w = rna(hm4.w * invc);
        *(uint4*)(s_hemb + r * 132 + c4v * 4) = a;
        float4 p;
        p.x = pm4.x * invc; p.y = pm4.y * invc; p.z = pm4.z * invc; p.w = pm4.w * invc;
        *(float4*)(s_pres + r * 132 + c4v * 4) = p;
        uint4 x;
        x.x = rna(in4.x); x.y = rna(in4.y); x.z = rna(in4.z); x.w = rna(in4.w);
        *(uint4*)(s_x + r * 132 + c4v * 4) = x;
    }

    const int wid = tid >> 5, lane = tid & 31;
    const int wm = wid >> 1, wn = wid & 1;
    const int m0 = wm * 16, n0 = wn * 64;
    const int g = lane >> 2, q = lane & 3;
    (void)wn;

    float acc[8][4];

    #define NFRAG_LOOP(...)                                              \
        {                                                                \
            int r_ = m0 + g;                                             \
            _Pragma("unroll")                                            \
            for (int j = 0; j < 8; j++) {                                \
                int c0 = n0 + 8 * j + 2 * q;                             \
                int i0 = r_ * 132 + c0;                                  \
                int i2 = (r_ + 8) * 132 + c0;                            \
                (void)i0; (void)i2;                                      \
                __VA_ARGS__                                              \
            }                                                            \
        }

    NACC_INIT(acc, res_b1)
    gemm128v(s_x, g_nw[0], s_B, acc, tid);
    NFRAG_LOOP({
        s_x[i0]     = uif(rna(fmaxf(acc[j][0], 0.0f)));
        s_x[i0 + 1] = uif(rna(fmaxf(acc[j][1], 0.0f)));
        s_x[i2]     = uif(rna(fmaxf(acc[j][2], 0.0f)));
        s_x[i2 + 1] = uif(rna(fmaxf(acc[j][3], 0.0f)));
    })

    NACC_INIT(acc, res_b2)
    gemm128v(s_x, g_nw[1], s_B, acc, tid);
    NFRAG_LOOP({
        s_pres[i0]     = uif(rna(fmaxf(acc[j][0], 0.0f) + s_pres[i0]));
        s_pres[i0 + 1] = uif(rna(fmaxf(acc[j][1], 0.0f) + s_pres[i0 + 1]));
        s_pres[i2]     = uif(rna(fmaxf(acc[j][2], 0.0f) + s_pres[i2]));
        s_pres[i2 + 1] = uif(rna(fmaxf(acc[j][3], 0.0f) + s_pres[i2 + 1]));
    })

    NACC_INIT(acc, (const float*)nullptr)
    gemm128v(s_hemb, g_nw[7], s_B, acc, tid);
    NFRAG_LOOP({
        s_x[i0]     = acc[j][0];
        s_x[i0 + 1] = acc[j][1];
        s_x[i2]     = acc[j][2];
        s_x[i2 + 1] = acc[j][3];
    })

    NACC_INIT(acc, ir_b)
    gemm128v(s_pres, g_nw[2], s_B, acc, tid);
    gemm128v(s_hemb, g_nw[3], s_B, acc, tid);
    NFRAG_LOOP({
        s_x[i0]     = sigmoidf_(acc[j][0]) * s_x[i0];
        s_x[i0 + 1] = sigmoidf_(acc[j][1]) * s_x[i0 + 1];
        s_x[i2]     = sigmoidf_(acc[j][2]) * s_x[i2];
        s_x[i2 + 1] = sigmoidf_(acc[j][3]) * s_x[i2 + 1];
    })

    NACC_INIT(acc, ii_b)
    gemm128v(s_pres, g_nw[4], s_B, acc, tid);
    gemm128v(s_hemb, g_nw[5], s_B, acc, tid);
    NFRAG_LOOP({
        s_hemb[i0]     = sigmoidf_(acc[j][0]);
        s_hemb[i0 + 1] = sigmoidf_(acc[j][1]);
        s_hemb[i2]     = sigmoidf_(acc[j][2]);
        s_hemb[i2 + 1] = sigmoidf_(acc[j][3]);
    })

    NACC_INIT(acc, in_b)
    gemm128v(s_pres, g_nw[6], s_B, acc, tid);
    NFRAG_LOOP({
        float n_0 = tanhf(acc[j][0] + s_x[i0]);
        float n_1 = tanhf(acc[j][1] + s_x[i0 + 1]);
        float n_2 = tanhf(acc[j][2] + s_x[i2]);
        float n_3 = tanhf(acc[j][3] + s_x[i2 + 1]);
        float i_0 = s_hemb[i0];
        float i_1 = s_hemb[i0 + 1];
        float i_2 = s_hemb[i2];
        float i_3 = s_hemb[i2 + 1];
        size_t go0 = (size_t)(row0 + r_) * HH + c0;
        size_t go2 = (size_t)(row0 + r_ + 8) * HH + c0;
        float2 h0 = *(const float2*)(hidden + go0);
        float2 h2 = *(const float2*)(hidden + go2);
        float2 nh0;
        float2 nh2;
        nh0.x = (1.0f - i_0) * n_0 + i_0 * h0.x;
        nh0.y = (1.0f - i_1) * n_1 + i_1 * h0.y;
        nh2.x = (1.0f - i_2) * n_2 + i_2 * h2.x;
        nh2.y = (1.0f - i_3) * n_3 + i_3 * h2.y;
        *(float2*)(out_hidden + go0) = nh0;
        *(float2*)(out_hidden + go2) = nh2;
        s_x[i0]     = uif(rna(nh0.x));
        s_x[i0 + 1] = uif(rna(nh0.y));
        s_x[i2]     = uif(rna(nh2.x));
        s_x[i2 + 1] = uif(rna(nh2.y));
    })

    NACC_INIT(acc, out_b1)
    gemm128v(s_x, g_nw[8], s_B, acc, tid);
    NFRAG_LOOP({
        s_hemb[i0]     = uif(rna(fmaxf(acc[j][0], 0.0f)));
        s_hemb[i0 + 1] = uif(rna(fmaxf(acc[j][1], 0.0f)));
        s_hemb[i2]     = uif(rna(fmaxf(acc[j][2], 0.0f)));
        s_hemb[i2 + 1] = uif(rna(fmaxf(acc[j][3], 0.0f)));
    })

    NACC_INIT(acc, out_b2)
    gemm128v(s_hemb, g_nw[9], s_B, acc, tid);
    NFRAG_LOOP({
        s_x[i0]     = uif(rna(fmaxf(acc[j][0], 0.0f)));
        s_x[i0 + 1] = uif(rna(fmaxf(acc[j][1], 0.0f)));
        s_x[i2]     = uif(rna(fmaxf(acc[j][2], 0.0f)));
        s_x[i2 + 1] = uif(rna(fmaxf(acc[j][3], 0.0f)));
    })

    NACC_INIT(acc, out_b3)
    gemm128v(s_x, g_nw[10], s_B, acc, tid);
    NFRAG_LOOP({
        size_t go0 = (size_t)(row0 + r_) * II + c0;
        size_t go2 = (size_t)(row0 + r_ + 8) * II + c0;
        float2 p0;
        float2 p2;
        p0.x = acc[j][0]; p0.y = acc[j][1];
        p2.x = acc[j][2]; p2.y = acc[j][3];
        *(float2*)(out_pred + go0) = p0;
        *(float2*)(out_pred + go2) = p2;
    })
    #undef NFRAG_LOOP
}

// ---------------- launch ----------------
extern "C" void kernel_launch(void* const* d_in, const int* in_sizes, int n_in,
                              void* d_out, int out_size) {
    const float* inputs    = (const float*)d_in[0];
    const float* edge_attr = (const float*)d_in[1];
    const int*   send_e    = (const int*)  d_in[2];
    const int*   recv_e    = (const int*)  d_in[3];
    const float* hidden    = (const float*)d_in[4];
    const float* msg_w1 = (const float*)d_in[5];
    const float* msg_b1 = (const float*)d_in[6];
    const float* msg_w2 = (const float*)d_in[7];
    const float* msg_b2 = (const float*)d_in[8];
    const float* pm_w1  = (const float*)d_in[9];
    const float* pm_b1  = (const float*)d_in[10];
    const float* pm_w2  = (const float*)d_in[11];
    const float* pm_b2  = (const float*)d_in[12];
    const float* res_w1 = (const float*)d_in[13];
    const float* res_b1 = (const float*)d_in[14];
    const float* res_w2 = (const float*)d_in[15];
    const float* res_b2 = (const float*)d_in[16];
    const float* ir_w   = (const float*)d_in[17];
    const float* ir_b   = (const float*)d_in[18];
    const float* ii_w   = (const float*)d_in[19];
    const float* ii_b   = (const float*)d_in[20];
    const float* in_w   = (const float*)d_in[21];
    const float* in_b   = (const float*)d_in[22];
    const float* hr_w   = (const float*)d_in[23];
    const float* hi_w   = (const float*)d_in[24];
    const float* hh_w   = (const float*)d_in[25];
    const float* out_w1 = (const float*)d_in[26];
    const float* out_b1 = (const float*)d_in[27];
    const float* out_w2 = (const float*)d_in[28];
    const float* out_b2 = (const float*)d_in[29];
    const float* out_w3 = (const float*)d_in[30];
    const float* out_b3 = (const float*)d_in[31];

    float* out_pred   = (float*)d_out;
    float* out_hidden = (float*)d_out + (size_t)BB * NN * II;

    const int HM_SMEM = HM_SMEMF * 4;     // 102,400 B -> 2 CTAs/SM
    const int PM_SMEM = PM_SMEMF * 4;     // 101,888 B -> 2 CTAs/SM
    const int HP_SMEM = HP_SMEMF * 4;     //  84,480 B
    const int ND_SMEM = ND_SMEMF * 4;     // 219,648 B
    cudaFuncSetAttribute(hm_kernel, cudaFuncAttributeMaxDynamicSharedMemorySize, HM_SMEM);
    cudaFuncSetAttribute(pm_kernel, cudaFuncAttributeMaxDynamicSharedMemorySize, PM_SMEM);
    cudaFuncSetAttribute(hm_pre_kernel, cudaFuncAttributeMaxDynamicSharedMemorySize, HP_SMEM);
    cudaFuncSetAttribute(node_kernel, cudaFuncAttributeMaxDynamicSharedMemorySize, ND_SMEM);

    zero_kernel<<<1024, 256>>>();
    count_kernel<<<EE / 256, 256>>>(recv_e);
    prep_kernel<<<128, 256>>>(msg_w1, msg_w2, pm_w1, pm_w2,
                              res_w1, res_w2, ir_w, hr_w, ii_w, hi_w,
                              in_w, hh_w, out_w1, out_w2, out_w3);

    hm_pre_kernel<<<(BB * NN) / 128, 512, HP_SMEM>>>(hidden, msg_b1);
    hm_kernel<<<dim3(EE / 128, BB), 256, HM_SMEM>>>(send_e, recv_e, msg_b2);
    pm_kernel<<<dim3(EE / 128, BB), 256, PM_SMEM>>>(edge_attr, recv_e, pm_b1, pm_b2);

    node_kernel<<<(BB * NN) / 128, 512, ND_SMEM>>>(
        inputs, hidden,
        res_b1, res_b2, ir_b, ii_b, in_b,
        out_b1, out_b2, out_b3,
        out_pred, out_hidden);
}